// round 1
// baseline (speedup 1.0000x reference)
#include <cuda_runtime.h>

#define BB 64
#define NNODE 64
#define HH 128
#define TJ 4
#define TE 32
#define NTHREADS 256

// ---- device scratch (no allocations allowed) ----
__device__ float g_A [BB * NNODE * HH];   // h_j @ We1[0:H] + be1
__device__ float g_Bm[BB * NNODE * HH];   // h_k @ We1[H:2H]
__device__ float g_mi[BB * NNODE * HH];   // aggregated messages

__device__ __forceinline__ float silu(float z) {
    return z / (1.f + __expf(-z));
}

// ============================================================
// Kernel 1: per-node pre-projection of the edge MLP layer 1
// A[n] = h[n] @ We1[0:128] + be1 ; Bm[n] = h[n] @ We1[128:256]
// ============================================================
__global__ __launch_bounds__(256) void prep_kernel(
    const float* __restrict__ h,
    const float* __restrict__ We1,
    const float* __restrict__ be1)
{
    __shared__ float hs[32][HH];
    int base = blockIdx.x * 32;
    for (int i = threadIdx.x; i < 32 * HH; i += 256)
        hs[i >> 7][i & 127] = h[base * HH + i];
    __syncthreads();

    int t = threadIdx.x & 127;
    int g = threadIdx.x >> 7;   // 0..1, 16 nodes each
    float accA[16], accB[16];
    float bias = be1[t];
#pragma unroll
    for (int nn = 0; nn < 16; nn++) { accA[nn] = bias; accB[nn] = 0.f; }

    for (int i = 0; i < HH; i++) {
        float w1 = __ldg(&We1[i * HH + t]);
        float w2 = __ldg(&We1[(HH + i) * HH + t]);
#pragma unroll
        for (int nn = 0; nn < 16; nn++) {
            float hv = hs[g * 16 + nn][i];
            accA[nn] += hv * w1;
            accB[nn] += hv * w2;
        }
    }
#pragma unroll
    for (int nn = 0; nn < 16; nn++) {
        int n = base + g * 16 + nn;
        g_A [n * HH + t] = accA[nn];
        g_Bm[n * HH + t] = accB[nn];
    }
}

// ============================================================
// Kernel 2: edge MLP + message aggregation + coordinate update
// Block = (batch b, tile of TJ=4 receiver nodes j). 256 threads.
// ============================================================
struct EdgeSmem {
    float We2[HH * HH];       // 64 KB
    float Wc1[HH * HH];       // 64 KB
    float Bm [NNODE * HH];    // 32 KB
    float A  [TJ * HH];
    float t  [TE * (HH + 4)]; // padded rows (132 floats)
    float m  [TE * (HH + 4)];
    float mi [TJ * HH];
    float xk [NNODE * 3];
    float cutl[TJ][NNODE];
    float d2l [TJ][NNODE];
    int   klist[TJ][NNODE];
    int   cnt [TJ];
    int   wcnt[8];
    float phi [TE];
    float be2s[HH];
    float bc1s[HH];
    float wc2s[HH];
    float wds [HH];
    float xup [TJ][3];
};

__global__ __launch_bounds__(NTHREADS, 1) void edge_kernel(
    const float* __restrict__ x,
    const float* __restrict__ We1,
    const float* __restrict__ We2,
    const float* __restrict__ be2,
    const float* __restrict__ Wc1,
    const float* __restrict__ bc1,
    const float* __restrict__ Wc2,
    float* __restrict__ xout)
{
    extern __shared__ float smem_raw[];
    EdgeSmem* S = (EdgeSmem*)smem_raw;
    int tid = threadIdx.x;
    int jt  = blockIdx.x;   // 0..15
    int b   = blockIdx.y;   // 0..63

    // ---- cooperative loads ----
    for (int i = tid; i < HH * HH; i += NTHREADS) {
        S->We2[i] = We2[i];
        S->Wc1[i] = Wc1[i];
    }
    for (int i = tid; i < NNODE * HH; i += NTHREADS)
        S->Bm[i] = g_Bm[(b * NNODE) * HH + i];
    for (int i = tid; i < TJ * HH; i += NTHREADS) {
        S->A[i]  = g_A[(b * NNODE + jt * TJ) * HH + i];
        S->mi[i] = 0.f;
    }
    for (int i = tid; i < NNODE * 3; i += NTHREADS)
        S->xk[i] = x[b * NNODE * 3 + i];
    if (tid < HH) {
        S->be2s[tid] = be2[tid];
        S->bc1s[tid] = bc1[tid];
        S->wc2s[tid] = Wc2[tid];
        S->wds [tid] = We1[2 * HH * HH + tid];   // d^2 row of We1
    }
    if (tid < TJ * 3) S->xup[tid / 3][tid % 3] = 0.f;
    __syncthreads();

    // ---- deterministic mask build + compaction (4 j x 64 k == 256 threads) ----
    {
        int jl = tid >> 6, k = tid & 63;
        int j  = jt * TJ + jl;
        float dx = S->xk[j * 3 + 0] - S->xk[k * 3 + 0];
        float dy = S->xk[j * 3 + 1] - S->xk[k * 3 + 1];
        float dz = S->xk[j * 3 + 2] - S->xk[k * 3 + 2];
        float d2 = dx * dx + dy * dy + dz * dz;
        bool act = (k != j) && (d2 < 25.f);
        unsigned ball = __ballot_sync(0xffffffffu, act);
        int wd = tid >> 5, lane = tid & 31;
        if (lane == 0) S->wcnt[wd] = __popc(ball);
        __syncthreads();
        int basepos = (wd & 1) ? S->wcnt[wd - 1] : 0;
        if (act) {
            int pos = basepos + __popc(ball & ((1u << lane) - 1u));
            float d = sqrtf(d2);
            // 1 - 1.5 d^2/25 + 0.5 d^3/125
            float cutv = 1.f - 0.06f * d2 + 0.004f * d2 * d;
            S->klist[jl][pos] = k;
            S->cutl [jl][pos] = cutv;
            S->d2l  [jl][pos] = d2;
        }
        if (tid < TJ) S->cnt[tid] = S->wcnt[2 * tid] + S->wcnt[2 * tid + 1];
    }
    __syncthreads();

    const int tc = tid & 31;   // output-column group (4 cols each)
    const int te = tid >> 5;   // edge group (4 edges each)
    const float4* We2v = (const float4*)S->We2;
    const float4* Wc1v = (const float4*)S->Wc1;
    float4* tv4 = (float4*)S->t;        // row stride 33 float4
    const float4* mv4 = (const float4*)S->m;

    for (int jl = 0; jl < TJ; jl++) {
        int j = jt * TJ + jl;
        int m = S->cnt[jl];
        for (int start = 0; start < m; start += TE) {
            int nE = min(TE, m - start);

            // ---- stage t = silu(A_j + Bm_k + d2*wd) ----
            for (int idx = tid; idx < TE * HH; idx += NTHREADS) {
                int e = idx >> 7, hh = idx & 127;
                float v = 0.f;
                if (e < nE) {
                    int k = S->klist[jl][start + e];
                    float z = S->A[jl * HH + hh] + S->Bm[k * HH + hh]
                            + S->d2l[jl][start + e] * S->wds[hh];
                    v = silu(z);
                }
                S->t[e * (HH + 4) + hh] = v;
            }
            __syncthreads();

            // ---- GEMM1: e2 = silu(t @ We2 + be2); mij = e2*cut ----
            float acc[4][4];
#pragma unroll
            for (int i = 0; i < 4; i++)
#pragma unroll
                for (int jj = 0; jj < 4; jj++) acc[i][jj] = 0.f;

            for (int hh = 0; hh < HH; hh += 4) {
                float4 w0 = We2v[(hh + 0) * 32 + tc];
                float4 w1 = We2v[(hh + 1) * 32 + tc];
                float4 w2 = We2v[(hh + 2) * 32 + tc];
                float4 w3 = We2v[(hh + 3) * 32 + tc];
#pragma unroll
                for (int i = 0; i < 4; i++) {
                    float4 tv = tv4[(te * 4 + i) * 33 + (hh >> 2)];
                    acc[i][0] += tv.x * w0.x + tv.y * w1.x + tv.z * w2.x + tv.w * w3.x;
                    acc[i][1] += tv.x * w0.y + tv.y * w1.y + tv.z * w2.y + tv.w * w3.y;
                    acc[i][2] += tv.x * w0.z + tv.y * w1.z + tv.z * w2.z + tv.w * w3.z;
                    acc[i][3] += tv.x * w0.w + tv.y * w1.w + tv.z * w2.w + tv.w * w3.w;
                }
            }
            {
                float4 bev = ((const float4*)S->be2s)[tc];
                float mi_part[4] = {0.f, 0.f, 0.f, 0.f};
#pragma unroll
                for (int i = 0; i < 4; i++) {
                    int e = te * 4 + i;
                    float cutv = (e < nE) ? S->cutl[jl][start + e] : 0.f;
                    float4 mm;
                    mm.x = silu(acc[i][0] + bev.x) * cutv;
                    mm.y = silu(acc[i][1] + bev.y) * cutv;
                    mm.z = silu(acc[i][2] + bev.z) * cutv;
                    mm.w = silu(acc[i][3] + bev.w) * cutv;
                    ((float4*)S->m)[e * 33 + tc] = mm;
                    mi_part[0] += mm.x; mi_part[1] += mm.y;
                    mi_part[2] += mm.z; mi_part[3] += mm.w;
                }
                atomicAdd(&S->mi[jl * HH + tc * 4 + 0], mi_part[0]);
                atomicAdd(&S->mi[jl * HH + tc * 4 + 1], mi_part[1]);
                atomicAdd(&S->mi[jl * HH + tc * 4 + 2], mi_part[2]);
                atomicAdd(&S->mi[jl * HH + tc * 4 + 3], mi_part[3]);
            }
            __syncthreads();

            // ---- GEMM2: g = silu(mij @ Wc1 + bc1); phi = g @ Wc2 ----
#pragma unroll
            for (int i = 0; i < 4; i++)
#pragma unroll
                for (int jj = 0; jj < 4; jj++) acc[i][jj] = 0.f;

            for (int hh = 0; hh < HH; hh += 4) {
                float4 w0 = Wc1v[(hh + 0) * 32 + tc];
                float4 w1 = Wc1v[(hh + 1) * 32 + tc];
                float4 w2 = Wc1v[(hh + 2) * 32 + tc];
                float4 w3 = Wc1v[(hh + 3) * 32 + tc];
#pragma unroll
                for (int i = 0; i < 4; i++) {
                    float4 tv = mv4[(te * 4 + i) * 33 + (hh >> 2)];
                    acc[i][0] += tv.x * w0.x + tv.y * w1.x + tv.z * w2.x + tv.w * w3.x;
                    acc[i][1] += tv.x * w0.y + tv.y * w1.y + tv.z * w2.y + tv.w * w3.y;
                    acc[i][2] += tv.x * w0.z + tv.y * w1.z + tv.z * w2.z + tv.w * w3.z;
                    acc[i][3] += tv.x * w0.w + tv.y * w1.w + tv.z * w2.w + tv.w * w3.w;
                }
            }
            {
                float4 bcv = ((const float4*)S->bc1s)[tc];
                float4 wcv = ((const float4*)S->wc2s)[tc];
                float phi_part[4];
#pragma unroll
                for (int i = 0; i < 4; i++) {
                    phi_part[i] = silu(acc[i][0] + bcv.x) * wcv.x
                                + silu(acc[i][1] + bcv.y) * wcv.y
                                + silu(acc[i][2] + bcv.z) * wcv.z
                                + silu(acc[i][3] + bcv.w) * wcv.w;
                }
#pragma unroll
                for (int off = 16; off; off >>= 1)
#pragma unroll
                    for (int i = 0; i < 4; i++)
                        phi_part[i] += __shfl_xor_sync(0xffffffffu, phi_part[i], off);
                if (tc == 0) {
#pragma unroll
                    for (int i = 0; i < 4; i++) S->phi[te * 4 + i] = phi_part[i];
                }
            }
            __syncthreads();

            // ---- coordinate accumulation (warp 0) ----
            if (tid < 32) {
                float px = 0.f, py = 0.f, pz = 0.f;
                if (tid < nE) {
                    int k = S->klist[jl][start + tid];
                    float p = S->phi[tid];
                    px = (S->xk[j * 3 + 0] - S->xk[k * 3 + 0]) * p;
                    py = (S->xk[j * 3 + 1] - S->xk[k * 3 + 1]) * p;
                    pz = (S->xk[j * 3 + 2] - S->xk[k * 3 + 2]) * p;
                }
#pragma unroll
                for (int off = 16; off; off >>= 1) {
                    px += __shfl_xor_sync(0xffffffffu, px, off);
                    py += __shfl_xor_sync(0xffffffffu, py, off);
                    pz += __shfl_xor_sync(0xffffffffu, pz, off);
                }
                if (tid == 0) {
                    S->xup[jl][0] += px;
                    S->xup[jl][1] += py;
                    S->xup[jl][2] += pz;
                }
            }
            __syncthreads();
        }
    }

    // ---- epilogue: mi scratch + x_new ----
    for (int i = tid; i < TJ * HH; i += NTHREADS)
        g_mi[(b * NNODE + jt * TJ) * HH + i] = S->mi[i];
    if (tid < TJ * 3) {
        int jl = tid / 3, c = tid % 3;
        int j = jt * TJ + jl;
        float v = S->xk[j * 3 + c] + (1.f / 63.f) * S->xup[jl][c];
        v = fminf(fmaxf(v, -1000.f), 1000.f);
        xout[(b * NNODE + j) * 3 + c] = v;
    }
}

// ============================================================
// Kernel 3: node MLP. Block = 32 nodes, 256 threads.
// h_new = h + silu([h, mi, h0] @ Wn1 + bn1) @ Wn2 + bn2
// ============================================================
struct NodeSmem {
    float nf[32 * 388];   // padded row (384+4)
    float u [32 * (HH + 4)];
};

__global__ __launch_bounds__(256, 1) void node_kernel(
    const float* __restrict__ h,
    const float* __restrict__ h0,
    const float* __restrict__ Wn1,
    const float* __restrict__ bn1,
    const float* __restrict__ Wn2,
    const float* __restrict__ bn2,
    float* __restrict__ hout)
{
    extern __shared__ float smem_raw[];
    NodeSmem* S = (NodeSmem*)smem_raw;
    int tid = threadIdx.x;
    int base = blockIdx.x * 32;

    for (int i = tid; i < 32 * 384; i += 256) {
        int n = i / 384, k = i % 384;
        float v;
        if (k < 128)      v = h   [(base + n) * HH + k];
        else if (k < 256) v = g_mi[(base + n) * HH + k - 128];
        else              v = h0  [(base + n) * HH + k - 256];
        S->nf[n * 388 + k] = v;
    }
    __syncthreads();

    const int tc = tid & 31;
    const int te = tid >> 5;
    const float4* nfv = (const float4*)S->nf;   // row stride 97 float4
    const float4* Wn1v = (const float4*)Wn1;
    const float4* Wn2v = (const float4*)Wn2;

    // ---- layer 1 ----
    float acc[4][4];
#pragma unroll
    for (int i = 0; i < 4; i++)
#pragma unroll
        for (int jj = 0; jj < 4; jj++) acc[i][jj] = 0.f;

    for (int k = 0; k < 384; k += 4) {
        float4 w0 = __ldg(&Wn1v[(k + 0) * 32 + tc]);
        float4 w1 = __ldg(&Wn1v[(k + 1) * 32 + tc]);
        float4 w2 = __ldg(&Wn1v[(k + 2) * 32 + tc]);
        float4 w3 = __ldg(&Wn1v[(k + 3) * 32 + tc]);
#pragma unroll
        for (int i = 0; i < 4; i++) {
            float4 fv = nfv[(te * 4 + i) * 97 + (k >> 2)];
            acc[i][0] += fv.x * w0.x + fv.y * w1.x + fv.z * w2.x + fv.w * w3.x;
            acc[i][1] += fv.x * w0.y + fv.y * w1.y + fv.z * w2.y + fv.w * w3.y;
            acc[i][2] += fv.x * w0.z + fv.y * w1.z + fv.z * w2.z + fv.w * w3.z;
            acc[i][3] += fv.x * w0.w + fv.y * w1.w + fv.z * w2.w + fv.w * w3.w;
        }
    }
    {
        float4 bv = ((const float4*)bn1)[tc];
#pragma unroll
        for (int i = 0; i < 4; i++) {
            float4 uu;
            uu.x = silu(acc[i][0] + bv.x);
            uu.y = silu(acc[i][1] + bv.y);
            uu.z = silu(acc[i][2] + bv.z);
            uu.w = silu(acc[i][3] + bv.w);
            ((float4*)S->u)[(te * 4 + i) * 33 + tc] = uu;
        }
    }
    __syncthreads();

    // ---- layer 2 + residual ----
    const float4* uv = (const float4*)S->u;
#pragma unroll
    for (int i = 0; i < 4; i++)
#pragma unroll
        for (int jj = 0; jj < 4; jj++) acc[i][jj] = 0.f;

    for (int k = 0; k < HH; k += 4) {
        float4 w0 = __ldg(&Wn2v[(k + 0) * 32 + tc]);
        float4 w1 = __ldg(&Wn2v[(k + 1) * 32 + tc]);
        float4 w2 = __ldg(&Wn2v[(k + 2) * 32 + tc]);
        float4 w3 = __ldg(&Wn2v[(k + 3) * 32 + tc]);
#pragma unroll
        for (int i = 0; i < 4; i++) {
            float4 fv = uv[(te * 4 + i) * 33 + (k >> 2)];
            acc[i][0] += fv.x * w0.x + fv.y * w1.x + fv.z * w2.x + fv.w * w3.x;
            acc[i][1] += fv.x * w0.y + fv.y * w1.y + fv.z * w2.y + fv.w * w3.y;
            acc[i][2] += fv.x * w0.z + fv.y * w1.z + fv.z * w2.z + fv.w * w3.z;
            acc[i][3] += fv.x * w0.w + fv.y * w1.w + fv.z * w2.w + fv.w * w3.w;
        }
    }
    {
        float4 bv = ((const float4*)bn2)[tc];
#pragma unroll
        for (int i = 0; i < 4; i++) {
            int n = base + te * 4 + i;
            float4 hv = __ldg(&((const float4*)h)[n * 32 + tc]);
            float4 out;
            out.x = acc[i][0] + bv.x + hv.x;
            out.y = acc[i][1] + bv.y + hv.y;
            out.z = acc[i][2] + bv.z + hv.z;
            out.w = acc[i][3] + bv.w + hv.w;
            ((float4*)hout)[n * 32 + tc] = out;
        }
    }
}

// ============================================================
extern "C" void kernel_launch(void* const* d_in, const int* in_sizes, int n_in,
                              void* d_out, int out_size)
{
    (void)in_sizes; (void)n_in; (void)out_size;
    const float* h   = (const float*)d_in[0];
    const float* x   = (const float*)d_in[1];
    /* d_in[2] = node_mask (all true for this problem's inputs) */
    const float* h0  = (const float*)d_in[3];
    const float* We1 = (const float*)d_in[4];
    const float* be1 = (const float*)d_in[5];
    const float* We2 = (const float*)d_in[6];
    const float* be2 = (const float*)d_in[7];
    const float* Wn1 = (const float*)d_in[8];
    const float* bn1 = (const float*)d_in[9];
    const float* Wn2 = (const float*)d_in[10];
    const float* bn2 = (const float*)d_in[11];
    const float* Wc1 = (const float*)d_in[12];
    const float* bc1 = (const float*)d_in[13];
    const float* Wc2 = (const float*)d_in[14];

    float* out  = (float*)d_out;
    float* hout = out;                       // [B,N,H]
    float* xout = out + BB * NNODE * HH;     // [B,N,3]

    cudaFuncSetAttribute(edge_kernel, cudaFuncAttributeMaxDynamicSharedMemorySize,
                         (int)sizeof(EdgeSmem));
    cudaFuncSetAttribute(node_kernel, cudaFuncAttributeMaxDynamicSharedMemorySize,
                         (int)sizeof(NodeSmem));

    prep_kernel<<<BB * NNODE / 32, 256>>>(h, We1, be1);

    dim3 egrid(NNODE / TJ, BB);
    edge_kernel<<<egrid, NTHREADS, sizeof(EdgeSmem)>>>(
        x, We1, We2, be2, Wc1, bc1, Wc2, xout);

    node_kernel<<<BB * NNODE / 32, 256, sizeof(NodeSmem)>>>(
        h, h0, Wn1, bn1, Wn2, bn2, hout);
}

// round 2
// speedup vs baseline: 1.7671x; 1.7671x over previous
#include <cuda_runtime.h>

#define BB 64
#define NNODE 64
#define HH 128
#define TJ 8          // receiver nodes per block
#define TE 64         // edges per tile
#define NTHREADS 512

// ---- device scratch ----
__device__ float g_A [BB * NNODE * HH];   // h_j @ We1[0:H] + be1
__device__ float g_Bm[BB * NNODE * HH];   // h_k @ We1[H:2H]
__device__ float g_mi[BB * NNODE * HH];   // aggregated messages

__device__ __forceinline__ float silu(float z) {
    return z / (1.f + __expf(-z));
}

// ============================================================
// Kernel 1: per-node pre-projection of edge MLP layer 1
// ============================================================
__global__ __launch_bounds__(256) void prep_kernel(
    const float* __restrict__ h,
    const float* __restrict__ We1,
    const float* __restrict__ be1)
{
    __shared__ float hs[16][HH];
    int base = blockIdx.x * 16;
    for (int i = threadIdx.x; i < 16 * HH; i += 256)
        hs[i >> 7][i & 127] = h[base * HH + i];
    __syncthreads();

    int t = threadIdx.x & 127;
    int g = threadIdx.x >> 7;   // 0..1, 8 nodes each
    float accA[8], accB[8];
    float bias = be1[t];
#pragma unroll
    for (int nn = 0; nn < 8; nn++) { accA[nn] = bias; accB[nn] = 0.f; }

#pragma unroll 4
    for (int i = 0; i < HH; i++) {
        float w1 = __ldg(&We1[i * HH + t]);
        float w2 = __ldg(&We1[(HH + i) * HH + t]);
#pragma unroll
        for (int nn = 0; nn < 8; nn++) {
            float hv = hs[g * 8 + nn][i];
            accA[nn] += hv * w1;
            accB[nn] += hv * w2;
        }
    }
#pragma unroll
    for (int nn = 0; nn < 8; nn++) {
        int n = base + g * 8 + nn;
        g_A [n * HH + t] = accA[nn];
        g_Bm[n * HH + t] = accB[nn];
    }
}

// ============================================================
// Kernel 2: edge MLP + aggregation + coord update
// Block = (8 receiver nodes, one batch). 512 threads.
// ============================================================
struct EdgeSmem {
    float We2[HH * HH];         // 64 KB
    float Wc1[HH * HH];         // 64 KB
    float A  [TJ * HH];         // 4 KB
    float t  [TE * (HH + 4)];   // 33 KB  (row = 33 float4)
    float m  [TE * (HH + 4)];   // 33 KB
    float mi [TJ * HH];         // 4 KB
    float xk [NNODE * 3];
    float cutl[TJ * NNODE + TE];
    float d2l [TJ * NNODE + TE];
    float phi [TE];
    float be2s[HH];
    float bc1s[HH];
    float wc2s[HH];
    float wds [HH];
    int   ekey[TJ * NNODE + TE];  // (jl<<8)|k
    int   wcnt[16];
    int   wpre[16];
    int   cnt;
    float xup [TJ][3];
};

__global__ __launch_bounds__(NTHREADS, 1) void edge_kernel(
    const float* __restrict__ x,
    const float* __restrict__ We1,
    const float* __restrict__ We2,
    const float* __restrict__ be2,
    const float* __restrict__ Wc1,
    const float* __restrict__ bc1,
    const float* __restrict__ Wc2,
    float* __restrict__ xout)
{
    extern __shared__ float smem_raw[];
    EdgeSmem* S = (EdgeSmem*)smem_raw;
    int tid = threadIdx.x;
    int jt  = blockIdx.x;   // 0..7
    int b   = blockIdx.y;   // 0..63

    // ---- cooperative loads ----
    {
        const float4* w2g = (const float4*)We2;
        const float4* wcg = (const float4*)Wc1;
        float4* w2s = (float4*)S->We2;
        float4* wcs = (float4*)S->Wc1;
        for (int i = tid; i < HH * HH / 4; i += NTHREADS) {
            w2s[i] = w2g[i];
            wcs[i] = wcg[i];
        }
    }
    for (int i = tid; i < TJ * HH; i += NTHREADS) {
        S->A[i]  = g_A[(b * NNODE + jt * TJ) * HH + i];
        S->mi[i] = 0.f;
    }
    if (tid < NNODE * 3) S->xk[tid] = x[b * NNODE * 3 + tid];
    if (tid < HH) {
        S->be2s[tid] = be2[tid];
        S->bc1s[tid] = bc1[tid];
        S->wc2s[tid] = Wc2[tid];
        S->wds [tid] = We1[2 * HH * HH + tid];
    }
    if (tid < TJ * 3) S->xup[tid / 3][tid % 3] = 0.f;
    __syncthreads();

    // ---- mask build + block-wide compaction (8 j x 64 k = 512 threads) ----
    {
        int jl = tid >> 6, k = tid & 63;
        int j  = jt * TJ + jl;
        float dx = S->xk[j * 3 + 0] - S->xk[k * 3 + 0];
        float dy = S->xk[j * 3 + 1] - S->xk[k * 3 + 1];
        float dz = S->xk[j * 3 + 2] - S->xk[k * 3 + 2];
        float d2 = dx * dx + dy * dy + dz * dz;
        bool act = (k != j) && (d2 < 25.f);
        unsigned ball = __ballot_sync(0xffffffffu, act);
        int wd = tid >> 5, lane = tid & 31;
        if (lane == 0) S->wcnt[wd] = __popc(ball);
        __syncthreads();
        if (tid < 32) {
            int v = (tid < 16) ? S->wcnt[tid] : 0;
#pragma unroll
            for (int off = 1; off < 16; off <<= 1) {
                int u = __shfl_up_sync(0xffffffffu, v, off);
                if ((tid & 31) >= off) v += u;
            }
            if (tid < 16) S->wpre[tid] = v;     // inclusive scan
            if (tid == 15) S->cnt = v;
        }
        __syncthreads();
        int basepos = (wd == 0) ? 0 : S->wpre[wd - 1];
        if (act) {
            int pos = basepos + __popc(ball & ((1u << lane) - 1u));
            float d = sqrtf(d2);
            S->ekey[pos] = (jl << 8) | k;
            S->cutl[pos] = 1.f - 0.06f * d2 + 0.004f * d2 * d;
            S->d2l [pos] = d2;
        }
        // padding slots: inert (cut=0, jl=0, k=0)
        int cnt = S->cnt;
        if (tid < TE) {
            S->ekey[cnt + tid] = 0;
            S->cutl[cnt + tid] = 0.f;
            S->d2l [cnt + tid] = 0.f;
        }
    }
    __syncthreads();

    const int cnt = S->cnt;
    const int tc = tid & 31;   // 4 output columns each
    const int te = tid >> 5;   // 4 edges each (16 warps x 4 = 64)
    const float4* We2v = (const float4*)S->We2;
    const float4* Wc1v = (const float4*)S->Wc1;
    const float4* tv4c = (const float4*)S->t;
    const float4* mv4  = (const float4*)S->m;
    const float4* gBm4 = (const float4*)(g_Bm + (size_t)b * NNODE * HH);

    for (int start = 0; start < cnt; start += TE) {

        // ---- stage t = silu(A_j + Bm_k + d2*wd) : 64x32 float4 ----
        for (int idx = tid; idx < TE * 32; idx += NTHREADS) {
            int e = idx >> 5, h4 = idx & 31;
            int key = S->ekey[start + e];
            int jl = key >> 8, k = key & 255;
            float d2 = S->d2l[start + e];
            float4 av = ((const float4*)S->A)[jl * 32 + h4];
            float4 bv = __ldg(&gBm4[k * 32 + h4]);
            float4 wv = ((const float4*)S->wds)[h4];
            float4 tv;
            tv.x = silu(av.x + bv.x + d2 * wv.x);
            tv.y = silu(av.y + bv.y + d2 * wv.y);
            tv.z = silu(av.z + bv.z + d2 * wv.z);
            tv.w = silu(av.w + bv.w + d2 * wv.w);
            ((float4*)S->t)[e * 33 + h4] = tv;
        }
        __syncthreads();

        // ---- GEMM1: e2 = silu(t @ We2 + be2); mij = e2*cut ----
        float acc[4][4];
#pragma unroll
        for (int i = 0; i < 4; i++)
#pragma unroll
            for (int jj = 0; jj < 4; jj++) acc[i][jj] = 0.f;

        for (int hh = 0; hh < HH; hh += 4) {
            float4 w0 = We2v[(hh + 0) * 32 + tc];
            float4 w1 = We2v[(hh + 1) * 32 + tc];
            float4 w2 = We2v[(hh + 2) * 32 + tc];
            float4 w3 = We2v[(hh + 3) * 32 + tc];
#pragma unroll
            for (int i = 0; i < 4; i++) {
                float4 tv = tv4c[(te * 4 + i) * 33 + (hh >> 2)];
                acc[i][0] += tv.x * w0.x + tv.y * w1.x + tv.z * w2.x + tv.w * w3.x;
                acc[i][1] += tv.x * w0.y + tv.y * w1.y + tv.z * w2.y + tv.w * w3.y;
                acc[i][2] += tv.x * w0.z + tv.y * w1.z + tv.z * w2.z + tv.w * w3.z;
                acc[i][3] += tv.x * w0.w + tv.y * w1.w + tv.z * w2.w + tv.w * w3.w;
            }
        }
        {
            float4 bev = ((const float4*)S->be2s)[tc];
            int jlv[4];
            float4 mmv[4];
#pragma unroll
            for (int i = 0; i < 4; i++) {
                int e = te * 4 + i;
                jlv[i] = S->ekey[start + e] >> 8;
                float cutv = S->cutl[start + e];
                float4 mm;
                mm.x = silu(acc[i][0] + bev.x) * cutv;
                mm.y = silu(acc[i][1] + bev.y) * cutv;
                mm.z = silu(acc[i][2] + bev.z) * cutv;
                mm.w = silu(acc[i][3] + bev.w) * cutv;
                ((float4*)S->m)[e * 33 + tc] = mm;
                mmv[i] = mm;
            }
            // run-flush mi accumulation (edges sorted by jl)
            int cur = jlv[0];
            float sx = mmv[0].x, sy = mmv[0].y, sz = mmv[0].z, sw = mmv[0].w;
#pragma unroll
            for (int i = 1; i < 4; i++) {
                if (jlv[i] == cur) {
                    sx += mmv[i].x; sy += mmv[i].y; sz += mmv[i].z; sw += mmv[i].w;
                } else {
                    atomicAdd(&S->mi[cur * HH + tc * 4 + 0], sx);
                    atomicAdd(&S->mi[cur * HH + tc * 4 + 1], sy);
                    atomicAdd(&S->mi[cur * HH + tc * 4 + 2], sz);
                    atomicAdd(&S->mi[cur * HH + tc * 4 + 3], sw);
                    cur = jlv[i];
                    sx = mmv[i].x; sy = mmv[i].y; sz = mmv[i].z; sw = mmv[i].w;
                }
            }
            atomicAdd(&S->mi[cur * HH + tc * 4 + 0], sx);
            atomicAdd(&S->mi[cur * HH + tc * 4 + 1], sy);
            atomicAdd(&S->mi[cur * HH + tc * 4 + 2], sz);
            atomicAdd(&S->mi[cur * HH + tc * 4 + 3], sw);
        }
        __syncthreads();

        // ---- GEMM2: g = silu(mij @ Wc1 + bc1); phi = g @ Wc2 ----
#pragma unroll
        for (int i = 0; i < 4; i++)
#pragma unroll
            for (int jj = 0; jj < 4; jj++) acc[i][jj] = 0.f;

        for (int hh = 0; hh < HH; hh += 4) {
            float4 w0 = Wc1v[(hh + 0) * 32 + tc];
            float4 w1 = Wc1v[(hh + 1) * 32 + tc];
            float4 w2 = Wc1v[(hh + 2) * 32 + tc];
            float4 w3 = Wc1v[(hh + 3) * 32 + tc];
#pragma unroll
            for (int i = 0; i < 4; i++) {
                float4 tv = mv4[(te * 4 + i) * 33 + (hh >> 2)];
                acc[i][0] += tv.x * w0.x + tv.y * w1.x + tv.z * w2.x + tv.w * w3.x;
                acc[i][1] += tv.x * w0.y + tv.y * w1.y + tv.z * w2.y + tv.w * w3.y;
                acc[i][2] += tv.x * w0.z + tv.y * w1.z + tv.z * w2.z + tv.w * w3.z;
                acc[i][3] += tv.x * w0.w + tv.y * w1.w + tv.z * w2.w + tv.w * w3.w;
            }
        }
        {
            float4 bcv = ((const float4*)S->bc1s)[tc];
            float4 wcv = ((const float4*)S->wc2s)[tc];
            float phi_part[4];
#pragma unroll
            for (int i = 0; i < 4; i++) {
                phi_part[i] = silu(acc[i][0] + bcv.x) * wcv.x
                            + silu(acc[i][1] + bcv.y) * wcv.y
                            + silu(acc[i][2] + bcv.z) * wcv.z
                            + silu(acc[i][3] + bcv.w) * wcv.w;
            }
#pragma unroll
            for (int off = 16; off; off >>= 1)
#pragma unroll
                for (int i = 0; i < 4; i++)
                    phi_part[i] += __shfl_xor_sync(0xffffffffu, phi_part[i], off);
            if (tc == 0) {
#pragma unroll
                for (int i = 0; i < 4; i++) S->phi[te * 4 + i] = phi_part[i];
            }
        }
        __syncthreads();

        // ---- coordinate accumulation ----
        if (tid < 192) {
            int e = tid & 63, c = tid >> 6;   // c in 0..2
            if (start + e < cnt) {
                int key = S->ekey[start + e];
                int jl = key >> 8, k = key & 255;
                int j = jt * TJ + jl;
                float p = S->phi[e];
                atomicAdd(&S->xup[jl][c],
                          (S->xk[j * 3 + c] - S->xk[k * 3 + c]) * p);
            }
        }
        __syncthreads();
    }

    // ---- epilogue ----
    for (int i = tid; i < TJ * HH; i += NTHREADS)
        g_mi[(b * NNODE + jt * TJ) * HH + i] = S->mi[i];
    if (tid < TJ * 3) {
        int jl = tid / 3, c = tid % 3;
        int j = jt * TJ + jl;
        float v = S->xk[j * 3 + c] + (1.f / 63.f) * S->xup[jl][c];
        v = fminf(fmaxf(v, -1000.f), 1000.f);
        xout[(b * NNODE + j) * 3 + c] = v;
    }
}

// ============================================================
// Kernel 3: node MLP. Block = 16 nodes, 256 threads, grid 256.
// ============================================================
struct NodeSmem {
    float nf[16 * 388];
    float u [16 * (HH + 4)];
};

__global__ __launch_bounds__(256, 1) void node_kernel(
    const float* __restrict__ h,
    const float* __restrict__ h0,
    const float* __restrict__ Wn1,
    const float* __restrict__ bn1,
    const float* __restrict__ Wn2,
    const float* __restrict__ bn2,
    float* __restrict__ hout)
{
    extern __shared__ float smem_raw[];
    NodeSmem* S = (NodeSmem*)smem_raw;
    int tid = threadIdx.x;
    int base = blockIdx.x * 16;

    for (int i = tid; i < 16 * 384; i += 256) {
        int n = i / 384, k = i % 384;
        float v;
        if (k < 128)      v = h   [(base + n) * HH + k];
        else if (k < 256) v = g_mi[(base + n) * HH + k - 128];
        else              v = h0  [(base + n) * HH + k - 256];
        S->nf[n * 388 + k] = v;
    }
    __syncthreads();

    const int tc = tid & 31;
    const int te = tid >> 5;   // 8 groups x 2 nodes
    const float4* nfv = (const float4*)S->nf;   // row stride 97
    const float4* Wn1v = (const float4*)Wn1;
    const float4* Wn2v = (const float4*)Wn2;

    float acc[2][4];
#pragma unroll
    for (int i = 0; i < 2; i++)
#pragma unroll
        for (int jj = 0; jj < 4; jj++) acc[i][jj] = 0.f;

#pragma unroll 2
    for (int k = 0; k < 384; k += 4) {
        float4 w0 = __ldg(&Wn1v[(k + 0) * 32 + tc]);
        float4 w1 = __ldg(&Wn1v[(k + 1) * 32 + tc]);
        float4 w2 = __ldg(&Wn1v[(k + 2) * 32 + tc]);
        float4 w3 = __ldg(&Wn1v[(k + 3) * 32 + tc]);
#pragma unroll
        for (int i = 0; i < 2; i++) {
            float4 fv = nfv[(te * 2 + i) * 97 + (k >> 2)];
            acc[i][0] += fv.x * w0.x + fv.y * w1.x + fv.z * w2.x + fv.w * w3.x;
            acc[i][1] += fv.x * w0.y + fv.y * w1.y + fv.z * w2.y + fv.w * w3.y;
            acc[i][2] += fv.x * w0.z + fv.y * w1.z + fv.z * w2.z + fv.w * w3.z;
            acc[i][3] += fv.x * w0.w + fv.y * w1.w + fv.z * w2.w + fv.w * w3.w;
        }
    }
    {
        float4 bv = ((const float4*)bn1)[tc];
#pragma unroll
        for (int i = 0; i < 2; i++) {
            float4 uu;
            uu.x = silu(acc[i][0] + bv.x);
            uu.y = silu(acc[i][1] + bv.y);
            uu.z = silu(acc[i][2] + bv.z);
            uu.w = silu(acc[i][3] + bv.w);
            ((float4*)S->u)[(te * 2 + i) * 33 + tc] = uu;
        }
    }
    __syncthreads();

    const float4* uv = (const float4*)S->u;
#pragma unroll
    for (int i = 0; i < 2; i++)
#pragma unroll
        for (int jj = 0; jj < 4; jj++) acc[i][jj] = 0.f;

#pragma unroll 2
    for (int k = 0; k < HH; k += 4) {
        float4 w0 = __ldg(&Wn2v[(k + 0) * 32 + tc]);
        float4 w1 = __ldg(&Wn2v[(k + 1) * 32 + tc]);
        float4 w2 = __ldg(&Wn2v[(k + 2) * 32 + tc]);
        float4 w3 = __ldg(&Wn2v[(k + 3) * 32 + tc]);
#pragma unroll
        for (int i = 0; i < 2; i++) {
            float4 fv = uv[(te * 2 + i) * 33 + (k >> 2)];
            acc[i][0] += fv.x * w0.x + fv.y * w1.x + fv.z * w2.x + fv.w * w3.x;
            acc[i][1] += fv.x * w0.y + fv.y * w1.y + fv.z * w2.y + fv.w * w3.y;
            acc[i][2] += fv.x * w0.z + fv.y * w1.z + fv.z * w2.z + fv.w * w3.z;
            acc[i][3] += fv.x * w0.w + fv.y * w1.w + fv.z * w2.w + fv.w * w3.w;
        }
    }
    {
        float4 bv = ((const float4*)bn2)[tc];
#pragma unroll
        for (int i = 0; i < 2; i++) {
            int n = base + te * 2 + i;
            float4 hv = __ldg(&((const float4*)h)[n * 32 + tc]);
            float4 out;
            out.x = acc[i][0] + bv.x + hv.x;
            out.y = acc[i][1] + bv.y + hv.y;
            out.z = acc[i][2] + bv.z + hv.z;
            out.w = acc[i][3] + bv.w + hv.w;
            ((float4*)hout)[n * 32 + tc] = out;
        }
    }
}

// ============================================================
extern "C" void kernel_launch(void* const* d_in, const int* in_sizes, int n_in,
                              void* d_out, int out_size)
{
    (void)in_sizes; (void)n_in; (void)out_size;
    const float* h   = (const float*)d_in[0];
    const float* x   = (const float*)d_in[1];
    const float* h0  = (const float*)d_in[3];
    const float* We1 = (const float*)d_in[4];
    const float* be1 = (const float*)d_in[5];
    const float* We2 = (const float*)d_in[6];
    const float* be2 = (const float*)d_in[7];
    const float* Wn1 = (const float*)d_in[8];
    const float* bn1 = (const float*)d_in[9];
    const float* Wn2 = (const float*)d_in[10];
    const float* bn2 = (const float*)d_in[11];
    const float* Wc1 = (const float*)d_in[12];
    const float* bc1 = (const float*)d_in[13];
    const float* Wc2 = (const float*)d_in[14];

    float* out  = (float*)d_out;
    float* hout = out;                       // [B,N,H]
    float* xout = out + BB * NNODE * HH;     // [B,N,3]

    cudaFuncSetAttribute(edge_kernel, cudaFuncAttributeMaxDynamicSharedMemorySize,
                         (int)sizeof(EdgeSmem));
    cudaFuncSetAttribute(node_kernel, cudaFuncAttributeMaxDynamicSharedMemorySize,
                         (int)sizeof(NodeSmem));

    prep_kernel<<<BB * NNODE / 16, 256>>>(h, We1, be1);

    dim3 egrid(NNODE / TJ, BB);
    edge_kernel<<<egrid, NTHREADS, sizeof(EdgeSmem)>>>(
        x, We1, We2, be2, Wc1, bc1, Wc2, xout);

    node_kernel<<<BB * NNODE / 16, 256, sizeof(NodeSmem)>>>(
        h, h0, Wn1, bn1, Wn2, bn2, hout);
}

// round 3
// speedup vs baseline: 1.7972x; 1.0170x over previous
#include <cuda_runtime.h>

#define BB 64
#define NNODE 64
#define HH 128
#define TJ 16         // receiver nodes per block
#define TE 64         // edges per tile
#define NTHREADS 512

// ---- device scratch ----
__device__ float g_A [BB * NNODE * HH];
__device__ float g_Bm[BB * NNODE * HH];
__device__ float g_mi[BB * NNODE * HH];

__device__ __forceinline__ float silu(float z) {
    return z / (1.f + __expf(-z));
}

// ============================================================
// Kernel 1: prep GEMM. 128 blocks x 32 nodes, 256 threads.
// out cols 0..127 -> A (+be1), 128..255 -> Bm
// ============================================================
__global__ __launch_bounds__(256) void prep_kernel(
    const float* __restrict__ h,
    const float* __restrict__ We1,
    const float* __restrict__ be1)
{
    __shared__ float hs[32 * 132];
    int tid = threadIdx.x;
    int base = blockIdx.x * 32;

    for (int i = tid; i < 32 * HH; i += 256)
        hs[(i >> 7) * 132 + (i & 127)] = h[base * HH + i];
    __syncthreads();

    int tn  = tid >> 5;          // node group: 4 nodes
    int tcc = tid & 31;          // col group: 8 of 256 cols
    int halfsel = tcc >> 4;      // 0 -> A, 1 -> Bm
    int col0 = (tcc & 15) * 8;
    const float4* Wg = (const float4*)(We1 + halfsel * HH * HH);
    const float4* H4 = (const float4*)hs;

    float acc[4][8];
#pragma unroll
    for (int r = 0; r < 4; r++)
#pragma unroll
        for (int c = 0; c < 8; c++) acc[r][c] = 0.f;

    for (int i = 0; i < HH; i += 4) {
        float av[4][4];
#pragma unroll
        for (int r = 0; r < 4; r++) {
            float4 a = H4[(tn * 4 + r) * 33 + (i >> 2)];
            av[r][0] = a.x; av[r][1] = a.y; av[r][2] = a.z; av[r][3] = a.w;
        }
#pragma unroll
        for (int s = 0; s < 4; s++) {
            float4 w0 = __ldg(&Wg[(i + s) * 32 + (col0 >> 2)]);
            float4 w1 = __ldg(&Wg[(i + s) * 32 + (col0 >> 2) + 1]);
#pragma unroll
            for (int r = 0; r < 4; r++) {
                float a = av[r][s];
                acc[r][0] += a * w0.x; acc[r][1] += a * w0.y;
                acc[r][2] += a * w0.z; acc[r][3] += a * w0.w;
                acc[r][4] += a * w1.x; acc[r][5] += a * w1.y;
                acc[r][6] += a * w1.z; acc[r][7] += a * w1.w;
            }
        }
    }

    float* outp = halfsel ? g_Bm : g_A;
    float4 b0 = make_float4(0.f, 0.f, 0.f, 0.f), b1 = b0;
    if (!halfsel) {
        b0 = ((const float4*)be1)[col0 >> 2];
        b1 = ((const float4*)be1)[(col0 >> 2) + 1];
    }
#pragma unroll
    for (int r = 0; r < 4; r++) {
        int n = base + tn * 4 + r;
        float4 o0 = make_float4(acc[r][0] + b0.x, acc[r][1] + b0.y,
                                acc[r][2] + b0.z, acc[r][3] + b0.w);
        float4 o1 = make_float4(acc[r][4] + b1.x, acc[r][5] + b1.y,
                                acc[r][6] + b1.z, acc[r][7] + b1.w);
        ((float4*)outp)[n * 32 + (col0 >> 2)]     = o0;
        ((float4*)outp)[n * 32 + (col0 >> 2) + 1] = o1;
    }
}

// ============================================================
// Kernel 2: edge MLP. Block = (16 j, one batch). 512 threads.
// Weights in smem (swizzled rows), K-split GEMMs 4e x 8c.
// ============================================================
#define NPAIR (TJ * NNODE)          // 1024
#define ELIST (NPAIR + TE)

struct EdgeSmem {
    float We2s[HH * 32 * 4];        // 128 rows x 32 float4 (swizzled)
    float Wc1s[HH * 32 * 4];
    float t [TE * 132];             // staged acts / GEMM2 partial scratch
    float m [TE * 132];             // GEMM1 partial scratch / e2
    float A [TJ * HH];
    float mi[TJ * HH];
    float xk[NNODE * 3];
    float cutl[ELIST];
    float d2l [ELIST];
    int   ekey[ELIST];
    float phi[TE];
    float be2s[HH], bc1s[HH], wc2s[HH], wds[HH];
    int   wcnt[32], wexc[32], cnt;
    float xup[TJ][3];
};

__global__ __launch_bounds__(NTHREADS, 1) void edge_kernel(
    const float* __restrict__ x,
    const float* __restrict__ We1,
    const float* __restrict__ We2,
    const float* __restrict__ be2,
    const float* __restrict__ Wc1,
    const float* __restrict__ bc1,
    const float* __restrict__ Wc2,
    float* __restrict__ xout)
{
    extern __shared__ float smem_raw[];
    EdgeSmem* S = (EdgeSmem*)smem_raw;
    int tid = threadIdx.x;
    int jt  = blockIdx.x;   // 0..3
    int b   = blockIdx.y;   // 0..63

    // ---- weight load with de-interleave swizzle ----
    for (int i = tid; i < HH * 32; i += NTHREADS) {
        int row = i >> 5, c = i & 31;
        int phys = (c >> 1) | ((c & 1) << 4);
        ((float4*)S->We2s)[row * 32 + phys] = ((const float4*)We2)[i];
        ((float4*)S->Wc1s)[row * 32 + phys] = ((const float4*)Wc1)[i];
    }
    for (int i = tid; i < TJ * HH; i += NTHREADS) {
        S->A[i]  = g_A[(b * NNODE + jt * TJ) * HH + i];
        S->mi[i] = 0.f;
    }
    if (tid < NNODE * 3) S->xk[tid] = x[b * NNODE * 3 + tid];
    if (tid < HH) {
        S->be2s[tid] = be2[tid];
        S->bc1s[tid] = bc1[tid];
        S->wc2s[tid] = Wc2[tid];
        S->wds [tid] = We1[2 * HH * HH + tid];
    }
    if (tid < TJ * 3) S->xup[tid / 3][tid % 3] = 0.f;
    __syncthreads();

    // ---- compaction: 1024 pairs, 2 passes ----
    int lane = tid & 31, wd = tid >> 5;
#pragma unroll
    for (int p = 0; p < 2; p++) {
        int pid = p * 512 + tid;
        int jl = pid >> 6, k = pid & 63;
        int j = jt * TJ + jl;
        float dx = S->xk[j * 3 + 0] - S->xk[k * 3 + 0];
        float dy = S->xk[j * 3 + 1] - S->xk[k * 3 + 1];
        float dz = S->xk[j * 3 + 2] - S->xk[k * 3 + 2];
        float d2 = dx * dx + dy * dy + dz * dz;
        bool act = (k != j) && (d2 < 25.f);
        unsigned ball = __ballot_sync(0xffffffffu, act);
        if (lane == 0) S->wcnt[p * 16 + wd] = __popc(ball);
    }
    __syncthreads();
    if (tid == 0) {
        int run = 0;
        for (int i = 0; i < 32; i++) { S->wexc[i] = run; run += S->wcnt[i]; }
        S->cnt = run;
    }
    __syncthreads();
#pragma unroll
    for (int p = 0; p < 2; p++) {
        int pid = p * 512 + tid;
        int jl = pid >> 6, k = pid & 63;
        int j = jt * TJ + jl;
        float dx = S->xk[j * 3 + 0] - S->xk[k * 3 + 0];
        float dy = S->xk[j * 3 + 1] - S->xk[k * 3 + 1];
        float dz = S->xk[j * 3 + 2] - S->xk[k * 3 + 2];
        float d2 = dx * dx + dy * dy + dz * dz;
        bool act = (k != j) && (d2 < 25.f);
        unsigned ball = __ballot_sync(0xffffffffu, act);
        if (act) {
            int pos = S->wexc[p * 16 + wd] + __popc(ball & ((1u << lane) - 1u));
            float d = sqrtf(d2);
            S->ekey[pos] = (jl << 8) | k;
            S->cutl[pos] = 1.f - 0.06f * d2 + 0.004f * d2 * d;
            S->d2l [pos] = d2;
        }
    }
    __syncthreads();
    const int cnt = S->cnt;
    if (tid < TE) {
        S->ekey[cnt + tid] = 0;
        S->cutl[cnt + tid] = 0.f;
        S->d2l [cnt + tid] = 0.f;
    }
    __syncthreads();

    const int half = tid >> 8;      // K-half
    const int t256 = tid & 255;
    const int te = t256 >> 4;       // 4 edges
    const int tc = t256 & 15;       // 8 cols
    const int hbase = half * 64;
    const float4* gBm4 = (const float4*)(g_Bm + (size_t)b * NNODE * HH);
    const float4* T4 = (const float4*)S->t;
    const float4* M4 = (const float4*)S->m;
    const float4* W2 = (const float4*)S->We2s;
    const float4* WC = (const float4*)S->Wc1s;

    int ntiles = (cnt + TE - 1) / TE;
    for (int ti = 0; ti < ntiles; ti++) {
        int start = ti * TE;

        // ---- stage t = silu(A + Bm + d2*wd), all 512 threads ----
        for (int idx = tid; idx < TE * 32; idx += NTHREADS) {
            int e = idx >> 5, h4 = idx & 31;
            int key = S->ekey[start + e];
            int jl = key >> 8, k = key & 255;
            float d2 = S->d2l[start + e];
            float4 av = ((const float4*)S->A)[jl * 32 + h4];
            float4 bv = __ldg(&gBm4[k * 32 + h4]);
            float4 wv = ((const float4*)S->wds)[h4];
            float4 tv;
            tv.x = silu(av.x + bv.x + d2 * wv.x);
            tv.y = silu(av.y + bv.y + d2 * wv.y);
            tv.z = silu(av.z + bv.z + d2 * wv.z);
            tv.w = silu(av.w + bv.w + d2 * wv.w);
            ((float4*)S->t)[e * 33 + h4] = tv;
        }
        __syncthreads();

        // ---- GEMM1: z = t @ We2 (K-split) ----
        float acc[4][8];
#pragma unroll
        for (int i = 0; i < 4; i++)
#pragma unroll
            for (int c = 0; c < 8; c++) acc[i][c] = 0.f;

        for (int hh = 0; hh < 64; hh += 4) {
            int row = hbase + hh;
            float av[4][4];
#pragma unroll
            for (int i = 0; i < 4; i++) {
                float4 a = T4[(te * 4 + i) * 33 + (row >> 2)];
                av[i][0] = a.x; av[i][1] = a.y; av[i][2] = a.z; av[i][3] = a.w;
            }
#pragma unroll
            for (int s = 0; s < 4; s++) {
                float4 w0 = W2[(row + s) * 32 + tc];
                float4 w1 = W2[(row + s) * 32 + 16 + tc];
#pragma unroll
                for (int i = 0; i < 4; i++) {
                    float a = av[i][s];
                    acc[i][0] += a * w0.x; acc[i][1] += a * w0.y;
                    acc[i][2] += a * w0.z; acc[i][3] += a * w0.w;
                    acc[i][4] += a * w1.x; acc[i][5] += a * w1.y;
                    acc[i][6] += a * w1.z; acc[i][7] += a * w1.w;
                }
            }
        }
        if (half == 1) {
#pragma unroll
            for (int i = 0; i < 4; i++) {
                int e = te * 4 + i;
                ((float4*)S->m)[e * 33 + tc * 2] =
                    make_float4(acc[i][0], acc[i][1], acc[i][2], acc[i][3]);
                ((float4*)S->m)[e * 33 + tc * 2 + 1] =
                    make_float4(acc[i][4], acc[i][5], acc[i][6], acc[i][7]);
            }
        }
        __syncthreads();

        // ---- GEMM1 epilogue (half 0): e2 = silu(z + be2); mi += e2*cut ----
        if (half == 0) {
            float4 be0 = ((const float4*)S->be2s)[tc * 2];
            float4 be1v = ((const float4*)S->be2s)[tc * 2 + 1];
            float fsum[8];
            int curjl = S->ekey[start + te * 4] >> 8;
#pragma unroll
            for (int c = 0; c < 8; c++) fsum[c] = 0.f;
#pragma unroll
            for (int i = 0; i < 4; i++) {
                int e = te * 4 + i;
                int jl = S->ekey[start + e] >> 8;
                float cut = S->cutl[start + e];
                float4 p0 = M4[e * 33 + tc * 2];
                float4 p1 = M4[e * 33 + tc * 2 + 1];
                float e2v[8];
                e2v[0] = silu(acc[i][0] + p0.x + be0.x);
                e2v[1] = silu(acc[i][1] + p0.y + be0.y);
                e2v[2] = silu(acc[i][2] + p0.z + be0.z);
                e2v[3] = silu(acc[i][3] + p0.w + be0.w);
                e2v[4] = silu(acc[i][4] + p1.x + be1v.x);
                e2v[5] = silu(acc[i][5] + p1.y + be1v.y);
                e2v[6] = silu(acc[i][6] + p1.z + be1v.z);
                e2v[7] = silu(acc[i][7] + p1.w + be1v.w);
                ((float4*)S->m)[e * 33 + tc * 2] =
                    make_float4(e2v[0], e2v[1], e2v[2], e2v[3]);
                ((float4*)S->m)[e * 33 + tc * 2 + 1] =
                    make_float4(e2v[4], e2v[5], e2v[6], e2v[7]);
                if (jl != curjl) {
#pragma unroll
                    for (int c = 0; c < 8; c++) {
                        atomicAdd(&S->mi[curjl * HH + tc * 8 + c], fsum[c]);
                        fsum[c] = 0.f;
                    }
                    curjl = jl;
                }
#pragma unroll
                for (int c = 0; c < 8; c++) fsum[c] += e2v[c] * cut;
            }
#pragma unroll
            for (int c = 0; c < 8; c++)
                atomicAdd(&S->mi[curjl * HH + tc * 8 + c], fsum[c]);
        }
        __syncthreads();

        // ---- GEMM2: zc = e2 @ Wc1 (K-split) ----
#pragma unroll
        for (int i = 0; i < 4; i++)
#pragma unroll
            for (int c = 0; c < 8; c++) acc[i][c] = 0.f;

        for (int hh = 0; hh < 64; hh += 4) {
            int row = hbase + hh;
            float av[4][4];
#pragma unroll
            for (int i = 0; i < 4; i++) {
                float4 a = M4[(te * 4 + i) * 33 + (row >> 2)];
                av[i][0] = a.x; av[i][1] = a.y; av[i][2] = a.z; av[i][3] = a.w;
            }
#pragma unroll
            for (int s = 0; s < 4; s++) {
                float4 w0 = WC[(row + s) * 32 + tc];
                float4 w1 = WC[(row + s) * 32 + 16 + tc];
#pragma unroll
                for (int i = 0; i < 4; i++) {
                    float a = av[i][s];
                    acc[i][0] += a * w0.x; acc[i][1] += a * w0.y;
                    acc[i][2] += a * w0.z; acc[i][3] += a * w0.w;
                    acc[i][4] += a * w1.x; acc[i][5] += a * w1.y;
                    acc[i][6] += a * w1.z; acc[i][7] += a * w1.w;
                }
            }
        }
        if (half == 1) {
#pragma unroll
            for (int i = 0; i < 4; i++) {
                int e = te * 4 + i;
                ((float4*)S->t)[e * 33 + tc * 2] =
                    make_float4(acc[i][0], acc[i][1], acc[i][2], acc[i][3]);
                ((float4*)S->t)[e * 33 + tc * 2 + 1] =
                    make_float4(acc[i][4], acc[i][5], acc[i][6], acc[i][7]);
            }
        }
        __syncthreads();

        // ---- GEMM2 epilogue (half 0): phi ----
        if (half == 0) {
            float4 bc0 = ((const float4*)S->bc1s)[tc * 2];
            float4 bc1v = ((const float4*)S->bc1s)[tc * 2 + 1];
            float4 wc0 = ((const float4*)S->wc2s)[tc * 2];
            float4 wc1v = ((const float4*)S->wc2s)[tc * 2 + 1];
            float ph[4];
#pragma unroll
            for (int i = 0; i < 4; i++) {
                int e = te * 4 + i;
                float cut = S->cutl[start + e];
                float4 p0 = T4[e * 33 + tc * 2];
                float4 p1 = T4[e * 33 + tc * 2 + 1];
                ph[i] = silu(cut * (acc[i][0] + p0.x) + bc0.x) * wc0.x
                      + silu(cut * (acc[i][1] + p0.y) + bc0.y) * wc0.y
                      + silu(cut * (acc[i][2] + p0.z) + bc0.z) * wc0.z
                      + silu(cut * (acc[i][3] + p0.w) + bc0.w) * wc0.w
                      + silu(cut * (acc[i][4] + p1.x) + bc1v.x) * wc1v.x
                      + silu(cut * (acc[i][5] + p1.y) + bc1v.y) * wc1v.y
                      + silu(cut * (acc[i][6] + p1.z) + bc1v.z) * wc1v.z
                      + silu(cut * (acc[i][7] + p1.w) + bc1v.w) * wc1v.w;
            }
#pragma unroll
            for (int off = 8; off; off >>= 1)
#pragma unroll
                for (int i = 0; i < 4; i++)
                    ph[i] += __shfl_xor_sync(0xffffffffu, ph[i], off);
            if (tc == 0) {
#pragma unroll
                for (int i = 0; i < 4; i++) S->phi[te * 4 + i] = ph[i];
            }
        }
        __syncthreads();

        // ---- coordinate accumulation ----
        if (tid < 192) {
            int e = tid & 63, c = tid >> 6;
            if (start + e < cnt) {
                int key = S->ekey[start + e];
                int jl = key >> 8, k = key & 255;
                int j = jt * TJ + jl;
                atomicAdd(&S->xup[jl][c],
                          (S->xk[j * 3 + c] - S->xk[k * 3 + c]) * S->phi[e]);
            }
        }
        __syncthreads();
    }

    // ---- epilogue ----
    for (int i = tid; i < TJ * HH; i += NTHREADS)
        g_mi[(b * NNODE + jt * TJ) * HH + i] = S->mi[i];
    if (tid < TJ * 3) {
        int jl = tid / 3, c = tid % 3;
        int j = jt * TJ + jl;
        float v = S->xk[j * 3 + c] + (1.f / 63.f) * S->xup[jl][c];
        v = fminf(fmaxf(v, -1000.f), 1000.f);
        xout[(b * NNODE + j) * 3 + c] = v;
    }
}

// ============================================================
// Kernel 3: node MLP (unchanged from R2)
// ============================================================
struct NodeSmem {
    float nf[16 * 388];
    float u [16 * (HH + 4)];
};

__global__ __launch_bounds__(256, 1) void node_kernel(
    const float* __restrict__ h,
    const float* __restrict__ h0,
    const float* __restrict__ Wn1,
    const float* __restrict__ bn1,
    const float* __restrict__ Wn2,
    const float* __restrict__ bn2,
    float* __restrict__ hout)
{
    extern __shared__ float smem_raw[];
    NodeSmem* S = (NodeSmem*)smem_raw;
    int tid = threadIdx.x;
    int base = blockIdx.x * 16;

    for (int i = tid; i < 16 * 384; i += 256) {
        int n = i / 384, k = i % 384;
        float v;
        if (k < 128)      v = h   [(base + n) * HH + k];
        else if (k < 256) v = g_mi[(base + n) * HH + k - 128];
        else              v = h0  [(base + n) * HH + k - 256];
        S->nf[n * 388 + k] = v;
    }
    __syncthreads();

    const int tc = tid & 31;
    const int te = tid >> 5;
    const float4* nfv = (const float4*)S->nf;
    const float4* Wn1v = (const float4*)Wn1;
    const float4* Wn2v = (const float4*)Wn2;

    float acc[2][4];
#pragma unroll
    for (int i = 0; i < 2; i++)
#pragma unroll
        for (int jj = 0; jj < 4; jj++) acc[i][jj] = 0.f;

#pragma unroll 2
    for (int k = 0; k < 384; k += 4) {
        float4 w0 = __ldg(&Wn1v[(k + 0) * 32 + tc]);
        float4 w1 = __ldg(&Wn1v[(k + 1) * 32 + tc]);
        float4 w2 = __ldg(&Wn1v[(k + 2) * 32 + tc]);
        float4 w3 = __ldg(&Wn1v[(k + 3) * 32 + tc]);
#pragma unroll
        for (int i = 0; i < 2; i++) {
            float4 fv = nfv[(te * 2 + i) * 97 + (k >> 2)];
            acc[i][0] += fv.x * w0.x + fv.y * w1.x + fv.z * w2.x + fv.w * w3.x;
            acc[i][1] += fv.x * w0.y + fv.y * w1.y + fv.z * w2.y + fv.w * w3.y;
            acc[i][2] += fv.x * w0.z + fv.y * w1.z + fv.z * w2.z + fv.w * w3.z;
            acc[i][3] += fv.x * w0.w + fv.y * w1.w + fv.z * w2.w + fv.w * w3.w;
        }
    }
    {
        float4 bv = ((const float4*)bn1)[tc];
#pragma unroll
        for (int i = 0; i < 2; i++) {
            float4 uu;
            uu.x = silu(acc[i][0] + bv.x);
            uu.y = silu(acc[i][1] + bv.y);
            uu.z = silu(acc[i][2] + bv.z);
            uu.w = silu(acc[i][3] + bv.w);
            ((float4*)S->u)[(te * 2 + i) * 33 + tc] = uu;
        }
    }
    __syncthreads();

    const float4* uv = (const float4*)S->u;
#pragma unroll
    for (int i = 0; i < 2; i++)
#pragma unroll
        for (int jj = 0; jj < 4; jj++) acc[i][jj] = 0.f;

#pragma unroll 2
    for (int k = 0; k < HH; k += 4) {
        float4 w0 = __ldg(&Wn2v[(k + 0) * 32 + tc]);
        float4 w1 = __ldg(&Wn2v[(k + 1) * 32 + tc]);
        float4 w2 = __ldg(&Wn2v[(k + 2) * 32 + tc]);
        float4 w3 = __ldg(&Wn2v[(k + 3) * 32 + tc]);
#pragma unroll
        for (int i = 0; i < 2; i++) {
            float4 fv = uv[(te * 2 + i) * 33 + (k >> 2)];
            acc[i][0] += fv.x * w0.x + fv.y * w1.x + fv.z * w2.x + fv.w * w3.x;
            acc[i][1] += fv.x * w0.y + fv.y * w1.y + fv.z * w2.y + fv.w * w3.y;
            acc[i][2] += fv.x * w0.z + fv.y * w1.z + fv.z * w2.z + fv.w * w3.z;
            acc[i][3] += fv.x * w0.w + fv.y * w1.w + fv.z * w2.w + fv.w * w3.w;
        }
    }
    {
        float4 bv = ((const float4*)bn2)[tc];
#pragma unroll
        for (int i = 0; i < 2; i++) {
            int n = base + te * 2 + i;
            float4 hv = __ldg(&((const float4*)h)[n * 32 + tc]);
            float4 out;
            out.x = acc[i][0] + bv.x + hv.x;
            out.y = acc[i][1] + bv.y + hv.y;
            out.z = acc[i][2] + bv.z + hv.z;
            out.w = acc[i][3] + bv.w + hv.w;
            ((float4*)hout)[n * 32 + tc] = out;
        }
    }
}

// ============================================================
extern "C" void kernel_launch(void* const* d_in, const int* in_sizes, int n_in,
                              void* d_out, int out_size)
{
    (void)in_sizes; (void)n_in; (void)out_size;
    const float* h   = (const float*)d_in[0];
    const float* x   = (const float*)d_in[1];
    const float* h0  = (const float*)d_in[3];
    const float* We1 = (const float*)d_in[4];
    const float* be1 = (const float*)d_in[5];
    const float* We2 = (const float*)d_in[6];
    const float* be2 = (const float*)d_in[7];
    const float* Wn1 = (const float*)d_in[8];
    const float* bn1 = (const float*)d_in[9];
    const float* Wn2 = (const float*)d_in[10];
    const float* bn2 = (const float*)d_in[11];
    const float* Wc1 = (const float*)d_in[12];
    const float* bc1 = (const float*)d_in[13];
    const float* Wc2 = (const float*)d_in[14];

    float* out  = (float*)d_out;
    float* hout = out;
    float* xout = out + BB * NNODE * HH;

    cudaFuncSetAttribute(edge_kernel, cudaFuncAttributeMaxDynamicSharedMemorySize,
                         (int)sizeof(EdgeSmem));
    cudaFuncSetAttribute(node_kernel, cudaFuncAttributeMaxDynamicSharedMemorySize,
                         (int)sizeof(NodeSmem));

    prep_kernel<<<BB * NNODE / 32, 256>>>(h, We1, be1);

    dim3 egrid(NNODE / TJ, BB);
    edge_kernel<<<egrid, NTHREADS, sizeof(EdgeSmem)>>>(
        x, We1, We2, be2, Wc1, bc1, Wc2, xout);

    node_kernel<<<BB * NNODE / 16, 256, sizeof(NodeSmem)>>>(
        h, h0, Wn1, bn1, Wn2, bn2, hout);
}

// round 8
// speedup vs baseline: 2.4904x; 1.3857x over previous
#include <cuda_runtime.h>
#include <cstdint>

#define BB 64
#define NNODE 64
#define HH 128
#define TJ 32          // receiver nodes per block
#define TE 128         // edges per MMA tile
#define NTHREADS 256
#define ASTRIDE 132    // activation smem row stride (floats)
#define WSTRIDE 136    // weight smem row stride (floats)

// ---- device scratch ----
__device__ float g_A [BB * NNODE * HH];
__device__ float g_Bm[BB * NNODE * HH];
__device__ float g_mi[BB * NNODE * HH];

__device__ __forceinline__ float silu(float z) {
    return z / (1.f + __expf(-z));
}
__device__ __forceinline__ float to_tf32(float x) {
    uint32_t r;
    asm("cvt.rna.tf32.f32 %0, %1;" : "=r"(r) : "f"(x));
    return __uint_as_float(r);
}

__device__ __forceinline__ void mma_tf32(float* c,
    uint32_t a0, uint32_t a1, uint32_t a2, uint32_t a3,
    uint32_t b0, uint32_t b1)
{
    asm volatile(
        "mma.sync.aligned.m16n8k8.row.col.f32.tf32.tf32.f32 "
        "{%0,%1,%2,%3}, {%4,%5,%6,%7}, {%8,%9}, {%0,%1,%2,%3};"
        : "+f"(c[0]), "+f"(c[1]), "+f"(c[2]), "+f"(c[3])
        : "r"(a0), "r"(a1), "r"(a2), "r"(a3), "r"(b0), "r"(b1));
}

// ============================================================
// Kernel 1: prep. grid 512, 256 threads, warp-per-node.
// ============================================================
__global__ __launch_bounds__(256) void prep_kernel(
    const float* __restrict__ h,
    const float* __restrict__ We1,
    const float* __restrict__ be1)
{
    __shared__ float hs[8 * HH];
    int tid = threadIdx.x;
    int base = blockIdx.x * 8;
    for (int i = tid; i < 8 * HH; i += 256) hs[i] = h[base * HH + i];
    __syncthreads();

    int w = tid >> 5, lane = tid & 31;
    int n = base + w;
    bool isA = lane < 16;
    int c8 = (lane & 15) * 8;
    const float4* Wg = (const float4*)(We1 + (isA ? 0 : HH * HH));

    float acc[8];
#pragma unroll
    for (int c = 0; c < 8; c++) acc[c] = 0.f;

#pragma unroll 4
    for (int k = 0; k < HH; k++) {
        float hv = hs[w * HH + k];
        float4 w0 = __ldg(&Wg[k * 32 + (c8 >> 2)]);
        float4 w1 = __ldg(&Wg[k * 32 + (c8 >> 2) + 1]);
        acc[0] += hv * w0.x; acc[1] += hv * w0.y; acc[2] += hv * w0.z; acc[3] += hv * w0.w;
        acc[4] += hv * w1.x; acc[5] += hv * w1.y; acc[6] += hv * w1.z; acc[7] += hv * w1.w;
    }
    if (isA) {
        float4 b0 = ((const float4*)be1)[c8 >> 2];
        float4 b1 = ((const float4*)be1)[(c8 >> 2) + 1];
        acc[0] += b0.x; acc[1] += b0.y; acc[2] += b0.z; acc[3] += b0.w;
        acc[4] += b1.x; acc[5] += b1.y; acc[6] += b1.z; acc[7] += b1.w;
    }
    float* outp = isA ? g_A : g_Bm;
    ((float4*)outp)[n * 32 + (c8 >> 2)]     = make_float4(acc[0], acc[1], acc[2], acc[3]);
    ((float4*)outp)[n * 32 + (c8 >> 2) + 1] = make_float4(acc[4], acc[5], acc[6], acc[7]);
}

// ============================================================
// Kernel 2: mma.sync tf32 edge kernel. Block = (b, 32 j). 256 thr.
// ============================================================
#define ELIST 2176

struct EdgeSmem {
    float As[TE * ASTRIDE];      // activations / mij
    float W1[HH * WSTRIDE];      // We2 [k][n]
    float W2[HH * WSTRIDE];      // Wc1 [k][n]
    float mi[TJ * HH];
    float phi[TE];
    unsigned short ekey[ELIST];  // (jl<<6)|k, sorted
    float xk[NNODE * 3];
    float be2s[HH], bc1s[HH], wc2s[HH], wds[HH];
    int jstart[33];
    int wcnt[64], wexc[64];
    float xup[TJ][3];
    int cnt;
};

__global__ __launch_bounds__(NTHREADS, 1) void edge_kernel(
    const float* __restrict__ x,
    const float* __restrict__ We1,
    const float* __restrict__ We2,
    const float* __restrict__ be2,
    const float* __restrict__ Wc1,
    const float* __restrict__ bc1,
    const float* __restrict__ Wc2,
    float* __restrict__ xout)
{
    extern __shared__ char smem_raw[];
    EdgeSmem* S = (EdgeSmem*)smem_raw;
    int tid = threadIdx.x;
    int wid = tid >> 5, lane = tid & 31;
    int jt = blockIdx.x;    // 0..1
    int b  = blockIdx.y;    // 0..63

    // ---- load weights [k][n] (tf32-rounded) ----
    for (int i = tid; i < HH * HH; i += NTHREADS) {
        int k = i >> 7, n = i & 127;
        S->W1[k * WSTRIDE + n] = to_tf32(We2[i]);
        S->W2[k * WSTRIDE + n] = to_tf32(Wc1[i]);
    }
    for (int i = tid; i < TJ * HH; i += NTHREADS) S->mi[i] = 0.f;
    if (tid < NNODE * 3) S->xk[tid] = x[b * NNODE * 3 + tid];
    if (tid < HH) {
        S->be2s[tid] = be2[tid];
        S->bc1s[tid] = bc1[tid];
        S->wc2s[tid] = Wc2[tid];
        S->wds [tid] = We1[2 * HH * HH + tid];
    }
    if (tid < TJ * 3) S->xup[tid / 3][tid % 3] = 0.f;
    __syncthreads();

    // ---- compaction: 2048 pairs, 8 passes ----
#pragma unroll
    for (int p = 0; p < 8; p++) {
        int pid = p * 256 + tid;
        int jl = pid >> 6, k = pid & 63;
        int j = jt * TJ + jl;
        float dx = S->xk[j * 3 + 0] - S->xk[k * 3 + 0];
        float dy = S->xk[j * 3 + 1] - S->xk[k * 3 + 1];
        float dz = S->xk[j * 3 + 2] - S->xk[k * 3 + 2];
        float d2 = dx * dx + dy * dy + dz * dz;
        bool act = (k != j) && (d2 < 25.f);
        unsigned ball = __ballot_sync(0xffffffffu, act);
        if (lane == 0) S->wcnt[p * 8 + wid] = __popc(ball);
    }
    __syncthreads();
    if (tid == 0) {
        int run = 0;
        for (int i = 0; i < 64; i++) { S->wexc[i] = run; run += S->wcnt[i]; }
        S->cnt = run;
    }
    __syncthreads();
#pragma unroll
    for (int p = 0; p < 8; p++) {
        int pid = p * 256 + tid;
        int jl = pid >> 6, k = pid & 63;
        int j = jt * TJ + jl;
        float dx = S->xk[j * 3 + 0] - S->xk[k * 3 + 0];
        float dy = S->xk[j * 3 + 1] - S->xk[k * 3 + 1];
        float dz = S->xk[j * 3 + 2] - S->xk[k * 3 + 2];
        float d2 = dx * dx + dy * dy + dz * dz;
        bool act = (k != j) && (d2 < 25.f);
        unsigned ball = __ballot_sync(0xffffffffu, act);
        if (act) {
            int pos = S->wexc[p * 8 + wid] + __popc(ball & ((1u << lane) - 1u));
            S->ekey[pos] = (unsigned short)((jl << 6) | k);
        }
    }
    __syncthreads();
    const int cnt = S->cnt;
    if (tid < TE) S->ekey[cnt + tid] = 0;
    if (tid < 33) {
        int target = tid << 6;
        int lo = 0, hi = cnt;
        while (lo < hi) {
            int mid = (lo + hi) >> 1;
            if ((int)S->ekey[mid] < target) lo = mid + 1; else hi = mid;
        }
        S->jstart[tid] = lo;
    }
    __syncthreads();

    const float4* gA4  = (const float4*)g_A  + (size_t)b * NNODE * 32;
    const float4* gBm4 = (const float4*)g_Bm + (size_t)b * NNODE * 32;

    const int g = lane >> 2, q = lane & 3;
    const int m0 = (wid >> 1) * 32;      // 4-way M split
    const int n0 = (wid & 1) * 64;       // 2-way N split
    int ntiles = (cnt + TE - 1) / TE;

    for (int ti = 0; ti < ntiles; ti++) {
        int start = ti * TE;

        // ---- stage A = tf32(silu(A_j + Bm_k + d2*wd)); zero phi ----
        if (tid < TE) S->phi[tid] = 0.f;
        for (int idx = tid; idx < TE * 32; idx += NTHREADS) {
            int e = idx >> 5, h4 = idx & 31;
            int key = S->ekey[start + e];
            int jl = key >> 6, k = key & 63;
            int j = jt * TJ + jl;
            float dx = S->xk[j * 3 + 0] - S->xk[k * 3 + 0];
            float dy = S->xk[j * 3 + 1] - S->xk[k * 3 + 1];
            float dz = S->xk[j * 3 + 2] - S->xk[k * 3 + 2];
            float d2 = dx * dx + dy * dy + dz * dz;
            float4 av = __ldg(&gA4[j * 32 + h4]);
            float4 bv = __ldg(&gBm4[k * 32 + h4]);
            float4 wv = ((const float4*)S->wds)[h4];
            float4 tv;
            tv.x = to_tf32(silu(av.x + bv.x + d2 * wv.x));
            tv.y = to_tf32(silu(av.y + bv.y + d2 * wv.y));
            tv.z = to_tf32(silu(av.z + bv.z + d2 * wv.z));
            tv.w = to_tf32(silu(av.w + bv.w + d2 * wv.w));
            *(float4*)&S->As[e * ASTRIDE + h4 * 4] = tv;
        }
        __syncthreads();

        // ---- GEMM1: z = A @ We2 ----
        float acc[2][8][4];
#pragma unroll
        for (int mt = 0; mt < 2; mt++)
#pragma unroll
            for (int nt = 0; nt < 8; nt++)
#pragma unroll
                for (int c = 0; c < 4; c++) acc[mt][nt][c] = 0.f;

#pragma unroll
        for (int kt = 0; kt < 16; kt++) {
            int k0 = kt * 8;
            uint32_t a[2][4];
#pragma unroll
            for (int mt = 0; mt < 2; mt++) {
                int rb = m0 + mt * 16;
                a[mt][0] = __float_as_uint(S->As[(rb + g)     * ASTRIDE + k0 + q]);
                a[mt][1] = __float_as_uint(S->As[(rb + g + 8) * ASTRIDE + k0 + q]);
                a[mt][2] = __float_as_uint(S->As[(rb + g)     * ASTRIDE + k0 + 4 + q]);
                a[mt][3] = __float_as_uint(S->As[(rb + g + 8) * ASTRIDE + k0 + 4 + q]);
            }
#pragma unroll
            for (int nt = 0; nt < 8; nt++) {
                uint32_t b0 = __float_as_uint(S->W1[(k0 + q)     * WSTRIDE + n0 + nt * 8 + g]);
                uint32_t b1 = __float_as_uint(S->W1[(k0 + 4 + q) * WSTRIDE + n0 + nt * 8 + g]);
                mma_tf32(acc[0][nt], a[0][0], a[0][1], a[0][2], a[0][3], b0, b1);
                mma_tf32(acc[1][nt], a[1][0], a[1][1], a[1][2], a[1][3], b0, b1);
            }
        }
        __syncthreads();   // all GEMM1 reads of As done

        // ---- epilogue 1: mij = tf32(silu(z + be2) * cut) -> As ----
        {
#pragma unroll
            for (int mt = 0; mt < 2; mt++) {
                int r0 = m0 + mt * 16 + g;
                float cutv[2];
#pragma unroll
                for (int hr = 0; hr < 2; hr++) {
                    int row = r0 + hr * 8;
                    int key = S->ekey[start + row];
                    int jl = key >> 6, k = key & 63;
                    int j = jt * TJ + jl;
                    float dx = S->xk[j * 3 + 0] - S->xk[k * 3 + 0];
                    float dy = S->xk[j * 3 + 1] - S->xk[k * 3 + 1];
                    float dz = S->xk[j * 3 + 2] - S->xk[k * 3 + 2];
                    float d2 = dx * dx + dy * dy + dz * dz;
                    float d = sqrtf(d2);
                    cutv[hr] = 1.f - 0.06f * d2 + 0.004f * d2 * d;
                }
#pragma unroll
                for (int nt = 0; nt < 8; nt++) {
                    int col = n0 + nt * 8 + q * 2;
                    float be0 = S->be2s[col], be1v = S->be2s[col + 1];
                    S->As[r0 * ASTRIDE + col]           = to_tf32(silu(acc[mt][nt][0] + be0)  * cutv[0]);
                    S->As[r0 * ASTRIDE + col + 1]       = to_tf32(silu(acc[mt][nt][1] + be1v) * cutv[0]);
                    S->As[(r0 + 8) * ASTRIDE + col]     = to_tf32(silu(acc[mt][nt][2] + be0)  * cutv[1]);
                    S->As[(r0 + 8) * ASTRIDE + col + 1] = to_tf32(silu(acc[mt][nt][3] + be1v) * cutv[1]);
                }
            }
        }
        __syncthreads();   // mij complete

        // ---- mi accumulation (exclusive (jl, colgroup) owners) ----
        {
            int jl = tid >> 3, cg = tid & 7;
            int lo = max(S->jstart[jl], start);
            int hi = min(S->jstart[jl + 1], start + TE);
            if (lo < hi) {
                float4 s0 = make_float4(0, 0, 0, 0), s1 = s0, s2 = s0, s3 = s0;
                for (int e = lo; e < hi; e++) {
                    const float4* rp = (const float4*)&S->As[(e - start) * ASTRIDE + cg * 16];
                    float4 v0 = rp[0], v1 = rp[1], v2 = rp[2], v3 = rp[3];
                    s0.x += v0.x; s0.y += v0.y; s0.z += v0.z; s0.w += v0.w;
                    s1.x += v1.x; s1.y += v1.y; s1.z += v1.z; s1.w += v1.w;
                    s2.x += v2.x; s2.y += v2.y; s2.z += v2.z; s2.w += v2.w;
                    s3.x += v3.x; s3.y += v3.y; s3.z += v3.z; s3.w += v3.w;
                }
                float4* mip = (float4*)&S->mi[jl * HH + cg * 16];
                float4 m0v = mip[0], m1v = mip[1], m2v = mip[2], m3v = mip[3];
                mip[0] = make_float4(m0v.x + s0.x, m0v.y + s0.y, m0v.z + s0.z, m0v.w + s0.w);
                mip[1] = make_float4(m1v.x + s1.x, m1v.y + s1.y, m1v.z + s1.z, m1v.w + s1.w);
                mip[2] = make_float4(m2v.x + s2.x, m2v.y + s2.y, m2v.z + s2.z, m2v.w + s2.w);
                mip[3] = make_float4(m3v.x + s3.x, m3v.y + s3.y, m3v.z + s3.z, m3v.w + s3.w);
            }
        }

        // ---- GEMM2: zc = mij @ Wc1 ----
#pragma unroll
        for (int mt = 0; mt < 2; mt++)
#pragma unroll
            for (int nt = 0; nt < 8; nt++)
#pragma unroll
                for (int c = 0; c < 4; c++) acc[mt][nt][c] = 0.f;

#pragma unroll
        for (int kt = 0; kt < 16; kt++) {
            int k0 = kt * 8;
            uint32_t a[2][4];
#pragma unroll
            for (int mt = 0; mt < 2; mt++) {
                int rb = m0 + mt * 16;
                a[mt][0] = __float_as_uint(S->As[(rb + g)     * ASTRIDE + k0 + q]);
                a[mt][1] = __float_as_uint(S->As[(rb + g + 8) * ASTRIDE + k0 + q]);
                a[mt][2] = __float_as_uint(S->As[(rb + g)     * ASTRIDE + k0 + 4 + q]);
                a[mt][3] = __float_as_uint(S->As[(rb + g + 8) * ASTRIDE + k0 + 4 + q]);
            }
#pragma unroll
            for (int nt = 0; nt < 8; nt++) {
                uint32_t b0 = __float_as_uint(S->W2[(k0 + q)     * WSTRIDE + n0 + nt * 8 + g]);
                uint32_t b1 = __float_as_uint(S->W2[(k0 + 4 + q) * WSTRIDE + n0 + nt * 8 + g]);
                mma_tf32(acc[0][nt], a[0][0], a[0][1], a[0][2], a[0][3], b0, b1);
                mma_tf32(acc[1][nt], a[1][0], a[1][1], a[1][2], a[1][3], b0, b1);
            }
        }

        // ---- epilogue 2: phi[e] = sum_n silu(zc + bc1)*wc2 ----
        {
#pragma unroll
            for (int mt = 0; mt < 2; mt++) {
                float p0 = 0.f, p1 = 0.f;
#pragma unroll
                for (int nt = 0; nt < 8; nt++) {
                    int col = n0 + nt * 8 + q * 2;
                    float bc0 = S->bc1s[col], bc1v = S->bc1s[col + 1];
                    float wc0 = S->wc2s[col], wc1v = S->wc2s[col + 1];
                    p0 += silu(acc[mt][nt][0] + bc0)  * wc0;
                    p0 += silu(acc[mt][nt][1] + bc1v) * wc1v;
                    p1 += silu(acc[mt][nt][2] + bc0)  * wc0;
                    p1 += silu(acc[mt][nt][3] + bc1v) * wc1v;
                }
#pragma unroll
                for (int off = 1; off < 4; off <<= 1) {
                    p0 += __shfl_xor_sync(0xffffffffu, p0, off);
                    p1 += __shfl_xor_sync(0xffffffffu, p1, off);
                }
                if (q == 0) {
                    int r0 = m0 + mt * 16 + g;
                    atomicAdd(&S->phi[r0], p0);
                    atomicAdd(&S->phi[r0 + 8], p1);
                }
            }
        }
        __syncthreads();   // phi complete

        // ---- coordinate accumulation ----
        if (tid < TE && start + tid < cnt) {
            int key = S->ekey[start + tid];
            int jl = key >> 6, k = key & 63;
            int j = jt * TJ + jl;
            float p = S->phi[tid];
            atomicAdd(&S->xup[jl][0], (S->xk[j * 3 + 0] - S->xk[k * 3 + 0]) * p);
            atomicAdd(&S->xup[jl][1], (S->xk[j * 3 + 1] - S->xk[k * 3 + 1]) * p);
            atomicAdd(&S->xup[jl][2], (S->xk[j * 3 + 2] - S->xk[k * 3 + 2]) * p);
        }
        __syncthreads();   // before next-tile staging overwrites As/phi
    }

    // ---- epilogue: write mi, x_new ----
    for (int i = tid; i < TJ * HH; i += NTHREADS)
        g_mi[(b * NNODE + jt * TJ) * HH + i] = S->mi[i];
    if (tid < TJ * 3) {
        int jl = tid / 3, c = tid % 3;
        int j = jt * TJ + jl;
        float v = S->xk[j * 3 + c] + (1.f / 63.f) * S->xup[jl][c];
        v = fminf(fmaxf(v, -1000.f), 1000.f);
        xout[(b * NNODE + j) * 3 + c] = v;
    }
}

// ============================================================
// Kernel 3: node MLP (unchanged).
// ============================================================
struct NodeSmem {
    float nf[16 * 388];
    float u [16 * (HH + 4)];
};

__global__ __launch_bounds__(256, 1) void node_kernel(
    const float* __restrict__ h,
    const float* __restrict__ h0,
    const float* __restrict__ Wn1,
    const float* __restrict__ bn1,
    const float* __restrict__ Wn2,
    const float* __restrict__ bn2,
    float* __restrict__ hout)
{
    extern __shared__ char smem_raw[];
    NodeSmem* S = (NodeSmem*)smem_raw;
    int tid = threadIdx.x;
    int base = blockIdx.x * 16;

    for (int i = tid; i < 16 * 384; i += 256) {
        int n = i / 384, k = i % 384;
        float v;
        if (k < 128)      v = h   [(base + n) * HH + k];
        else if (k < 256) v = g_mi[(base + n) * HH + k - 128];
        else              v = h0  [(base + n) * HH + k - 256];
        S->nf[n * 388 + k] = v;
    }
    __syncthreads();

    const int tc = tid & 31;
    const int te = tid >> 5;
    const float4* nfv = (const float4*)S->nf;
    const float4* Wn1v = (const float4*)Wn1;
    const float4* Wn2v = (const float4*)Wn2;

    float acc[2][4];
#pragma unroll
    for (int i = 0; i < 2; i++)
#pragma unroll
        for (int jj = 0; jj < 4; jj++) acc[i][jj] = 0.f;

#pragma unroll 2
    for (int k = 0; k < 384; k += 4) {
        float4 w0 = __ldg(&Wn1v[(k + 0) * 32 + tc]);
        float4 w1 = __ldg(&Wn1v[(k + 1) * 32 + tc]);
        float4 w2 = __ldg(&Wn1v[(k + 2) * 32 + tc]);
        float4 w3 = __ldg(&Wn1v[(k + 3) * 32 + tc]);
#pragma unroll
        for (int i = 0; i < 2; i++) {
            float4 fv = nfv[(te * 2 + i) * 97 + (k >> 2)];
            acc[i][0] += fv.x * w0.x + fv.y * w1.x + fv.z * w2.x + fv.w * w3.x;
            acc[i][1] += fv.x * w0.y + fv.y * w1.y + fv.z * w2.y + fv.w * w3.y;
            acc[i][2] += fv.x * w0.z + fv.y * w1.z + fv.z * w2.z + fv.w * w3.z;
            acc[i][3] += fv.x * w0.w + fv.y * w1.w + fv.z * w2.w + fv.w * w3.w;
        }
    }
    {
        float4 bv = ((const float4*)bn1)[tc];
#pragma unroll
        for (int i = 0; i < 2; i++) {
            float4 uu;
            uu.x = silu(acc[i][0] + bv.x);
            uu.y = silu(acc[i][1] + bv.y);
            uu.z = silu(acc[i][2] + bv.z);
            uu.w = silu(acc[i][3] + bv.w);
            ((float4*)S->u)[(te * 2 + i) * 33 + tc] = uu;
        }
    }
    __syncthreads();

    const float4* uv = (const float4*)S->u;
#pragma unroll
    for (int i = 0; i < 2; i++)
#pragma unroll
        for (int jj = 0; jj < 4; jj++) acc[i][jj] = 0.f;

#pragma unroll 2
    for (int k = 0; k < HH; k += 4) {
        float4 w0 = __ldg(&Wn2v[(k + 0) * 32 + tc]);
        float4 w1 = __ldg(&Wn2v[(k + 1) * 32 + tc]);
        float4 w2 = __ldg(&Wn2v[(k + 2) * 32 + tc]);
        float4 w3 = __ldg(&Wn2v[(k + 3) * 32 + tc]);
#pragma unroll
        for (int i = 0; i < 2; i++) {
            float4 fv = uv[(te * 2 + i) * 33 + (k >> 2)];
            acc[i][0] += fv.x * w0.x + fv.y * w1.x + fv.z * w2.x + fv.w * w3.x;
            acc[i][1] += fv.x * w0.y + fv.y * w1.y + fv.z * w2.y + fv.w * w3.y;
            acc[i][2] += fv.x * w0.z + fv.y * w1.z + fv.z * w2.z + fv.w * w3.z;
            acc[i][3] += fv.x * w0.w + fv.y * w1.w + fv.z * w2.w + fv.w * w3.w;
        }
    }
    {
        float4 bv = ((const float4*)bn2)[tc];
#pragma unroll
        for (int i = 0; i < 2; i++) {
            int n = base + te * 2 + i;
            float4 hv = __ldg(&((const float4*)h)[n * 32 + tc]);
            float4 out;
            out.x = acc[i][0] + bv.x + hv.x;
            out.y = acc[i][1] + bv.y + hv.y;
            out.z = acc[i][2] + bv.z + hv.z;
            out.w = acc[i][3] + bv.w + hv.w;
            ((float4*)hout)[n * 32 + tc] = out;
        }
    }
}

// ============================================================
extern "C" void kernel_launch(void* const* d_in, const int* in_sizes, int n_in,
                              void* d_out, int out_size)
{
    (void)in_sizes; (void)n_in; (void)out_size;
    const float* h   = (const float*)d_in[0];
    const float* x   = (const float*)d_in[1];
    const float* h0  = (const float*)d_in[3];
    const float* We1 = (const float*)d_in[4];
    const float* be1 = (const float*)d_in[5];
    const float* We2 = (const float*)d_in[6];
    const float* be2 = (const float*)d_in[7];
    const float* Wn1 = (const float*)d_in[8];
    const float* bn1 = (const float*)d_in[9];
    const float* Wn2 = (const float*)d_in[10];
    const float* bn2 = (const float*)d_in[11];
    const float* Wc1 = (const float*)d_in[12];
    const float* bc1 = (const float*)d_in[13];
    const float* Wc2 = (const float*)d_in[14];

    float* out  = (float*)d_out;
    float* hout = out;
    float* xout = out + BB * NNODE * HH;

    cudaFuncSetAttribute(edge_kernel, cudaFuncAttributeMaxDynamicSharedMemorySize,
                         (int)sizeof(EdgeSmem));
    cudaFuncSetAttribute(node_kernel, cudaFuncAttributeMaxDynamicSharedMemorySize,
                         (int)sizeof(NodeSmem));

    prep_kernel<<<BB * NNODE / 8, 256>>>(h, We1, be1);

    dim3 egrid(NNODE / TJ, BB);
    edge_kernel<<<egrid, NTHREADS, sizeof(EdgeSmem)>>>(
        x, We1, We2, be2, Wc1, bc1, Wc2, xout);

    node_kernel<<<BB * NNODE / 16, 256, sizeof(NodeSmem)>>>(
        h, h0, Wn1, bn1, Wn2, bn2, hout);
}

// round 10
// speedup vs baseline: 3.6342x; 1.4593x over previous
#include <cuda_runtime.h>
#include <cstdint>

#define BB 64
#define NNODE 64
#define HH 128
#define TJ 32          // receiver nodes per block
#define TE 128         // edges per MMA tile
#define NTHREADS 512
#define ASTRIDE 132    // activation smem row stride (floats)
#define WSTRIDE 136    // weight smem row stride (floats)

// ---- device scratch ----
__device__ float g_A [BB * NNODE * HH];
__device__ float g_Bm[BB * NNODE * HH];
__device__ float g_mi[BB * NNODE * HH];

__device__ __forceinline__ float silu(float z) {
    return __fdividef(z, 1.f + __expf(-z));
}
__device__ __forceinline__ float to_tf32(float x) {
    uint32_t r;
    asm("cvt.rna.tf32.f32 %0, %1;" : "=r"(r) : "f"(x));
    return __uint_as_float(r);
}

__device__ __forceinline__ void mma_tf32(float* c,
    uint32_t a0, uint32_t a1, uint32_t a2, uint32_t a3,
    uint32_t b0, uint32_t b1)
{
    asm volatile(
        "mma.sync.aligned.m16n8k8.row.col.f32.tf32.tf32.f32 "
        "{%0,%1,%2,%3}, {%4,%5,%6,%7}, {%8,%9}, {%0,%1,%2,%3};"
        : "+f"(c[0]), "+f"(c[1]), "+f"(c[2]), "+f"(c[3])
        : "r"(a0), "r"(a1), "r"(a2), "r"(a3), "r"(b0), "r"(b1));
}

// ============================================================
// Kernel 1: prep blocked GEMM. 128 blocks x 32 nodes, 256 thr.
// Output cols 0..127 -> A (+be1), 128..255 -> Bm.
// Weights staged through smem in 16-k slabs (reuse across nodes).
// ============================================================
__global__ __launch_bounds__(256) void prep_kernel(
    const float* __restrict__ h,
    const float* __restrict__ We1,
    const float* __restrict__ be1)
{
    __shared__ float hs[32 * 132];
    __shared__ float Ws[16 * 256];
    int tid = threadIdx.x;
    int base = blockIdx.x * 32;

    for (int i = tid; i < 32 * HH; i += 256)
        hs[(i >> 7) * 132 + (i & 127)] = h[base * HH + i];

    const int tn = tid >> 5;        // node group: 4 nodes
    const int tc = tid & 31;        // col group: 8 cols
    const int col0 = tc * 8;

    float acc[4][8];
#pragma unroll
    for (int r = 0; r < 4; r++)
#pragma unroll
        for (int c = 0; c < 8; c++) acc[r][c] = 0.f;

    for (int ks = 0; ks < HH; ks += 16) {
        __syncthreads();
        // stage weight slab [16 k][256 cols]
        for (int i = tid; i < 16 * 256; i += 256) {
            int kk = i >> 8, t = i & 255;
            int wrow = ks + kk + ((t >= 128) ? 128 : 0);
            Ws[kk * 256 + t] = We1[wrow * HH + (t & 127)];
        }
        __syncthreads();
#pragma unroll
        for (int kk = 0; kk < 16; kk++) {
            float4 w0 = *(const float4*)&Ws[kk * 256 + col0];
            float4 w1 = *(const float4*)&Ws[kk * 256 + col0 + 4];
#pragma unroll
            for (int r = 0; r < 4; r++) {
                float hv = hs[(tn * 4 + r) * 132 + ks + kk];
                acc[r][0] += hv * w0.x; acc[r][1] += hv * w0.y;
                acc[r][2] += hv * w0.z; acc[r][3] += hv * w0.w;
                acc[r][4] += hv * w1.x; acc[r][5] += hv * w1.y;
                acc[r][6] += hv * w1.z; acc[r][7] += hv * w1.w;
            }
        }
    }

    bool isBm = (col0 >= 128);
    int cw = col0 & 127;
    float* outp = isBm ? g_Bm : g_A;
    float4 b0 = make_float4(0.f, 0.f, 0.f, 0.f), b1 = b0;
    if (!isBm) {
        b0 = ((const float4*)be1)[cw >> 2];
        b1 = ((const float4*)be1)[(cw >> 2) + 1];
    }
#pragma unroll
    for (int r = 0; r < 4; r++) {
        int n = base + tn * 4 + r;
        ((float4*)outp)[n * 32 + (cw >> 2)] =
            make_float4(acc[r][0] + b0.x, acc[r][1] + b0.y,
                        acc[r][2] + b0.z, acc[r][3] + b0.w);
        ((float4*)outp)[n * 32 + (cw >> 2) + 1] =
            make_float4(acc[r][4] + b1.x, acc[r][5] + b1.y,
                        acc[r][6] + b1.z, acc[r][7] + b1.w);
    }
}

// ============================================================
// Kernel 2: mma.sync tf32 edge kernel. Block = (b, 32 j). 512 thr.
// ============================================================
#define ELIST 2176

struct EdgeSmem {
    float As[TE * ASTRIDE];      // activations / mij
    float W1[HH * WSTRIDE];      // We2 [k][n]
    float W2[HH * WSTRIDE];      // Wc1 [k][n]
    float mi[TJ * HH];
    float phi[TE];
    unsigned short ekey[ELIST];  // (jl<<6)|k, sorted
    float xk[NNODE * 3];
    float be2s[HH], bc1s[HH], wc2s[HH], wds[HH];
    int jstart[33];
    union {
        struct { int wcnt[64]; int wexc[64]; } c;
        float d2t[TE];           // per-tile edge d^2 (after compaction)
    } u;
    float xup[TJ][3];
    int cnt;
};

__global__ __launch_bounds__(NTHREADS, 1) void edge_kernel(
    const float* __restrict__ x,
    const float* __restrict__ We1,
    const float* __restrict__ We2,
    const float* __restrict__ be2,
    const float* __restrict__ Wc1,
    const float* __restrict__ bc1,
    const float* __restrict__ Wc2,
    float* __restrict__ xout)
{
    extern __shared__ char smem_raw[];
    EdgeSmem* S = (EdgeSmem*)smem_raw;
    int tid = threadIdx.x;
    int wid = tid >> 5, lane = tid & 31;
    int jt = blockIdx.x;    // 0..1
    int b  = blockIdx.y;    // 0..63

    // ---- load weights [k][n] (tf32-rounded) ----
    for (int i = tid; i < HH * HH; i += NTHREADS) {
        int k = i >> 7, n = i & 127;
        S->W1[k * WSTRIDE + n] = to_tf32(We2[i]);
        S->W2[k * WSTRIDE + n] = to_tf32(Wc1[i]);
    }
    for (int i = tid; i < TJ * HH; i += NTHREADS) S->mi[i] = 0.f;
    if (tid < NNODE * 3) S->xk[tid] = x[b * NNODE * 3 + tid];
    if (tid < HH) {
        S->be2s[tid] = be2[tid];
        S->bc1s[tid] = bc1[tid];
        S->wc2s[tid] = Wc2[tid];
        S->wds [tid] = We1[2 * HH * HH + tid];
    }
    if (tid < TJ * 3) S->xup[tid / 3][tid % 3] = 0.f;
    __syncthreads();

    // ---- compaction: 2048 pairs, 4 passes of 512 ----
#pragma unroll
    for (int p = 0; p < 4; p++) {
        int pid = p * 512 + tid;
        int jl = pid >> 6, k = pid & 63;
        int j = jt * TJ + jl;
        float dx = S->xk[j * 3 + 0] - S->xk[k * 3 + 0];
        float dy = S->xk[j * 3 + 1] - S->xk[k * 3 + 1];
        float dz = S->xk[j * 3 + 2] - S->xk[k * 3 + 2];
        float d2 = dx * dx + dy * dy + dz * dz;
        bool act = (k != j) && (d2 < 25.f);
        unsigned ball = __ballot_sync(0xffffffffu, act);
        if (lane == 0) S->u.c.wcnt[p * 16 + wid] = __popc(ball);
    }
    __syncthreads();
    if (tid == 0) {
        int run = 0;
        for (int i = 0; i < 64; i++) { S->u.c.wexc[i] = run; run += S->u.c.wcnt[i]; }
        S->cnt = run;
    }
    __syncthreads();
#pragma unroll
    for (int p = 0; p < 4; p++) {
        int pid = p * 512 + tid;
        int jl = pid >> 6, k = pid & 63;
        int j = jt * TJ + jl;
        float dx = S->xk[j * 3 + 0] - S->xk[k * 3 + 0];
        float dy = S->xk[j * 3 + 1] - S->xk[k * 3 + 1];
        float dz = S->xk[j * 3 + 2] - S->xk[k * 3 + 2];
        float d2 = dx * dx + dy * dy + dz * dz;
        bool act = (k != j) && (d2 < 25.f);
        unsigned ball = __ballot_sync(0xffffffffu, act);
        if (act) {
            int pos = S->u.c.wexc[p * 16 + wid] + __popc(ball & ((1u << lane) - 1u));
            S->ekey[pos] = (unsigned short)((jl << 6) | k);
        }
    }
    __syncthreads();
    const int cnt = S->cnt;
    if (tid < TE) S->ekey[cnt + tid] = 0;
    if (tid < 33) {
        int target = tid << 6;
        int lo = 0, hi = cnt;
        while (lo < hi) {
            int mid = (lo + hi) >> 1;
            if ((int)S->ekey[mid] < target) lo = mid + 1; else hi = mid;
        }
        S->jstart[tid] = lo;
    }
    __syncthreads();

    const float4* gA4  = (const float4*)g_A  + (size_t)b * NNODE * 32;
    const float4* gBm4 = (const float4*)g_Bm + (size_t)b * NNODE * 32;

    const int g = lane >> 2, q = lane & 3;
    const int m0 = (wid >> 1) * 16;      // 8-way M split (16 rows per warp)
    const int n0 = (wid & 1) * 64;       // 2-way N split
    int ntiles = (cnt + TE - 1) / TE;

    for (int ti = 0; ti < ntiles; ti++) {
        int start = ti * TE;

        // ---- per-tile precompute: phi = 0, d2t[e] ----
        if (tid < TE) {
            S->phi[tid] = 0.f;
            int key = S->ekey[start + tid];
            int jl = key >> 6, k = key & 63;
            int j = jt * TJ + jl;
            float dx = S->xk[j * 3 + 0] - S->xk[k * 3 + 0];
            float dy = S->xk[j * 3 + 1] - S->xk[k * 3 + 1];
            float dz = S->xk[j * 3 + 2] - S->xk[k * 3 + 2];
            S->u.d2t[tid] = dx * dx + dy * dy + dz * dz;
        }
        __syncthreads();

        // ---- stage A = tf32(silu(A_j + Bm_k + d2*wd)) ----
        for (int idx = tid; idx < TE * 32; idx += NTHREADS) {
            int e = idx >> 5, h4 = idx & 31;
            int key = S->ekey[start + e];
            int jl = key >> 6, k = key & 63;
            int j = jt * TJ + jl;
            float d2 = S->u.d2t[e];
            float4 av = __ldg(&gA4[j * 32 + h4]);
            float4 bv = __ldg(&gBm4[k * 32 + h4]);
            float4 wv = ((const float4*)S->wds)[h4];
            float4 tv;
            tv.x = to_tf32(silu(av.x + bv.x + d2 * wv.x));
            tv.y = to_tf32(silu(av.y + bv.y + d2 * wv.y));
            tv.z = to_tf32(silu(av.z + bv.z + d2 * wv.z));
            tv.w = to_tf32(silu(av.w + bv.w + d2 * wv.w));
            *(float4*)&S->As[e * ASTRIDE + h4 * 4] = tv;
        }
        __syncthreads();

        // ---- GEMM1: z = A @ We2 ----
        float acc[8][4];
#pragma unroll
        for (int nt = 0; nt < 8; nt++)
#pragma unroll
            for (int c = 0; c < 4; c++) acc[nt][c] = 0.f;

#pragma unroll
        for (int kt = 0; kt < 16; kt++) {
            int k0 = kt * 8;
            uint32_t a0 = __float_as_uint(S->As[(m0 + g)     * ASTRIDE + k0 + q]);
            uint32_t a1 = __float_as_uint(S->As[(m0 + g + 8) * ASTRIDE + k0 + q]);
            uint32_t a2 = __float_as_uint(S->As[(m0 + g)     * ASTRIDE + k0 + 4 + q]);
            uint32_t a3 = __float_as_uint(S->As[(m0 + g + 8) * ASTRIDE + k0 + 4 + q]);
#pragma unroll
            for (int nt = 0; nt < 8; nt++) {
                uint32_t b0 = __float_as_uint(S->W1[(k0 + q)     * WSTRIDE + n0 + nt * 8 + g]);
                uint32_t b1 = __float_as_uint(S->W1[(k0 + 4 + q) * WSTRIDE + n0 + nt * 8 + g]);
                mma_tf32(acc[nt], a0, a1, a2, a3, b0, b1);
            }
        }
        __syncthreads();   // all GEMM1 reads of As done

        // ---- epilogue 1: mij = tf32(silu(z + be2) * cut) -> As ----
        {
            int r0 = m0 + g;
            float d2a = S->u.d2t[r0];
            float d2b = S->u.d2t[r0 + 8];
            float cut0 = 1.f - 0.06f * d2a + 0.004f * d2a * sqrtf(d2a);
            float cut1 = 1.f - 0.06f * d2b + 0.004f * d2b * sqrtf(d2b);
#pragma unroll
            for (int nt = 0; nt < 8; nt++) {
                int col = n0 + nt * 8 + q * 2;
                float be0 = S->be2s[col], be1v = S->be2s[col + 1];
                float2 top, bot;
                top.x = to_tf32(silu(acc[nt][0] + be0)  * cut0);
                top.y = to_tf32(silu(acc[nt][1] + be1v) * cut0);
                bot.x = to_tf32(silu(acc[nt][2] + be0)  * cut1);
                bot.y = to_tf32(silu(acc[nt][3] + be1v) * cut1);
                *(float2*)&S->As[r0 * ASTRIDE + col] = top;
                *(float2*)&S->As[(r0 + 8) * ASTRIDE + col] = bot;
            }
        }
        __syncthreads();   // mij complete

        // ---- mi accumulation (exclusive (jl, colgroup) owners) ----
        {
            int jl = tid >> 4, cg = tid & 15;   // 32 jl x 16 col-groups of 8
            int lo = max(S->jstart[jl], start);
            int hi = min(S->jstart[jl + 1], start + TE);
            if (lo < hi) {
                float4 s0 = make_float4(0, 0, 0, 0), s1 = s0;
                for (int e = lo; e < hi; e++) {
                    const float4* rp = (const float4*)&S->As[(e - start) * ASTRIDE + cg * 8];
                    float4 v0 = rp[0], v1 = rp[1];
                    s0.x += v0.x; s0.y += v0.y; s0.z += v0.z; s0.w += v0.w;
                    s1.x += v1.x; s1.y += v1.y; s1.z += v1.z; s1.w += v1.w;
                }
                float4* mip = (float4*)&S->mi[jl * HH + cg * 8];
                float4 m0v = mip[0], m1v = mip[1];
                mip[0] = make_float4(m0v.x + s0.x, m0v.y + s0.y, m0v.z + s0.z, m0v.w + s0.w);
                mip[1] = make_float4(m1v.x + s1.x, m1v.y + s1.y, m1v.z + s1.z, m1v.w + s1.w);
            }
        }

        // ---- GEMM2: zc = mij @ Wc1 ----
#pragma unroll
        for (int nt = 0; nt < 8; nt++)
#pragma unroll
            for (int c = 0; c < 4; c++) acc[nt][c] = 0.f;

#pragma unroll
        for (int kt = 0; kt < 16; kt++) {
            int k0 = kt * 8;
            uint32_t a0 = __float_as_uint(S->As[(m0 + g)     * ASTRIDE + k0 + q]);
            uint32_t a1 = __float_as_uint(S->As[(m0 + g + 8) * ASTRIDE + k0 + q]);
            uint32_t a2 = __float_as_uint(S->As[(m0 + g)     * ASTRIDE + k0 + 4 + q]);
            uint32_t a3 = __float_as_uint(S->As[(m0 + g + 8) * ASTRIDE + k0 + 4 + q]);
#pragma unroll
            for (int nt = 0; nt < 8; nt++) {
                uint32_t b0 = __float_as_uint(S->W2[(k0 + q)     * WSTRIDE + n0 + nt * 8 + g]);
                uint32_t b1 = __float_as_uint(S->W2[(k0 + 4 + q) * WSTRIDE + n0 + nt * 8 + g]);
                mma_tf32(acc[nt], a0, a1, a2, a3, b0, b1);
            }
        }

        // ---- epilogue 2: phi[e] = sum_n silu(zc + bc1)*wc2 ----
        {
            float p0 = 0.f, p1 = 0.f;
#pragma unroll
            for (int nt = 0; nt < 8; nt++) {
                int col = n0 + nt * 8 + q * 2;
                float bc0 = S->bc1s[col], bc1v = S->bc1s[col + 1];
                float wc0 = S->wc2s[col], wc1v = S->wc2s[col + 1];
                p0 += silu(acc[nt][0] + bc0)  * wc0;
                p0 += silu(acc[nt][1] + bc1v) * wc1v;
                p1 += silu(acc[nt][2] + bc0)  * wc0;
                p1 += silu(acc[nt][3] + bc1v) * wc1v;
            }
#pragma unroll
            for (int off = 1; off < 4; off <<= 1) {
                p0 += __shfl_xor_sync(0xffffffffu, p0, off);
                p1 += __shfl_xor_sync(0xffffffffu, p1, off);
            }
            if (q == 0) {
                int r0 = m0 + g;
                atomicAdd(&S->phi[r0], p0);
                atomicAdd(&S->phi[r0 + 8], p1);
            }
        }
        __syncthreads();   // phi complete

        // ---- coordinate accumulation ----
        if (tid < TE && start + tid < cnt) {
            int key = S->ekey[start + tid];
            int jl = key >> 6, k = key & 63;
            int j = jt * TJ + jl;
            float p = S->phi[tid];
            atomicAdd(&S->xup[jl][0], (S->xk[j * 3 + 0] - S->xk[k * 3 + 0]) * p);
            atomicAdd(&S->xup[jl][1], (S->xk[j * 3 + 1] - S->xk[k * 3 + 1]) * p);
            atomicAdd(&S->xup[jl][2], (S->xk[j * 3 + 2] - S->xk[k * 3 + 2]) * p);
        }
        __syncthreads();   // before next-tile overwrites As/phi/d2t
    }

    // ---- epilogue: write mi, x_new ----
    for (int i = tid; i < TJ * HH; i += NTHREADS)
        g_mi[(b * NNODE + jt * TJ) * HH + i] = S->mi[i];
    if (tid < TJ * 3) {
        int jl = tid / 3, c = tid % 3;
        int j = jt * TJ + jl;
        float v = S->xk[j * 3 + c] + (1.f / 63.f) * S->xup[jl][c];
        v = fminf(fmaxf(v, -1000.f), 1000.f);
        xout[(b * NNODE + j) * 3 + c] = v;
    }
}

// ============================================================
// Kernel 3: node MLP (fast-silu).
// ============================================================
struct NodeSmem {
    float nf[16 * 388];
    float u [16 * (HH + 4)];
};

__global__ __launch_bounds__(256, 1) void node_kernel(
    const float* __restrict__ h,
    const float* __restrict__ h0,
    const float* __restrict__ Wn1,
    const float* __restrict__ bn1,
    const float* __restrict__ Wn2,
    const float* __restrict__ bn2,
    float* __restrict__ hout)
{
    extern __shared__ char smem_raw[];
    NodeSmem* S = (NodeSmem*)smem_raw;
    int tid = threadIdx.x;
    int base = blockIdx.x * 16;

    for (int i = tid; i < 16 * 384; i += 256) {
        int n = i / 384, k = i % 384;
        float v;
        if (k < 128)      v = h   [(base + n) * HH + k];
        else if (k < 256) v = g_mi[(base + n) * HH + k - 128];
        else              v = h0  [(base + n) * HH + k - 256];
        S->nf[n * 388 + k] = v;
    }
    __syncthreads();

    const int tc = tid & 31;
    const int te = tid >> 5;
    const float4* nfv = (const float4*)S->nf;
    const float4* Wn1v = (const float4*)Wn1;
    const float4* Wn2v = (const float4*)Wn2;

    float acc[2][4];
#pragma unroll
    for (int i = 0; i < 2; i++)
#pragma unroll
        for (int jj = 0; jj < 4; jj++) acc[i][jj] = 0.f;

#pragma unroll 2
    for (int k = 0; k < 384; k += 4) {
        float4 w0 = __ldg(&Wn1v[(k + 0) * 32 + tc]);
        float4 w1 = __ldg(&Wn1v[(k + 1) * 32 + tc]);
        float4 w2 = __ldg(&Wn1v[(k + 2) * 32 + tc]);
        float4 w3 = __ldg(&Wn1v[(k + 3) * 32 + tc]);
#pragma unroll
        for (int i = 0; i < 2; i++) {
            float4 fv = nfv[(te * 2 + i) * 97 + (k >> 2)];
            acc[i][0] += fv.x * w0.x + fv.y * w1.x + fv.z * w2.x + fv.w * w3.x;
            acc[i][1] += fv.x * w0.y + fv.y * w1.y + fv.z * w2.y + fv.w * w3.y;
            acc[i][2] += fv.x * w0.z + fv.y * w1.z + fv.z * w2.z + fv.w * w3.z;
            acc[i][3] += fv.x * w0.w + fv.y * w1.w + fv.z * w2.w + fv.w * w3.w;
        }
    }
    {
        float4 bv = ((const float4*)bn1)[tc];
#pragma unroll
        for (int i = 0; i < 2; i++) {
            float4 uu;
            uu.x = silu(acc[i][0] + bv.x);
            uu.y = silu(acc[i][1] + bv.y);
            uu.z = silu(acc[i][2] + bv.z);
            uu.w = silu(acc[i][3] + bv.w);
            ((float4*)S->u)[(te * 2 + i) * 33 + tc] = uu;
        }
    }
    __syncthreads();

    const float4* uv = (const float4*)S->u;
#pragma unroll
    for (int i = 0; i < 2; i++)
#pragma unroll
        for (int jj = 0; jj < 4; jj++) acc[i][jj] = 0.f;

#pragma unroll 2
    for (int k = 0; k < HH; k += 4) {
        float4 w0 = __ldg(&Wn2v[(k + 0) * 32 + tc]);
        float4 w1 = __ldg(&Wn2v[(k + 1) * 32 + tc]);
        float4 w2 = __ldg(&Wn2v[(k + 2) * 32 + tc]);
        float4 w3 = __ldg(&Wn2v[(k + 3) * 32 + tc]);
#pragma unroll
        for (int i = 0; i < 2; i++) {
            float4 fv = uv[(te * 2 + i) * 33 + (k >> 2)];
            acc[i][0] += fv.x * w0.x + fv.y * w1.x + fv.z * w2.x + fv.w * w3.x;
            acc[i][1] += fv.x * w0.y + fv.y * w1.y + fv.z * w2.y + fv.w * w3.y;
            acc[i][2] += fv.x * w0.z + fv.y * w1.z + fv.z * w2.z + fv.w * w3.z;
            acc[i][3] += fv.x * w0.w + fv.y * w1.w + fv.z * w2.w + fv.w * w3.w;
        }
    }
    {
        float4 bv = ((const float4*)bn2)[tc];
#pragma unroll
        for (int i = 0; i < 2; i++) {
            int n = base + te * 2 + i;
            float4 hv = __ldg(&((const float4*)h)[n * 32 + tc]);
            float4 out;
            out.x = acc[i][0] + bv.x + hv.x;
            out.y = acc[i][1] + bv.y + hv.y;
            out.z = acc[i][2] + bv.z + hv.z;
            out.w = acc[i][3] + bv.w + hv.w;
            ((float4*)hout)[n * 32 + tc] = out;
        }
    }
}

// ============================================================
extern "C" void kernel_launch(void* const* d_in, const int* in_sizes, int n_in,
                              void* d_out, int out_size)
{
    (void)in_sizes; (void)n_in; (void)out_size;
    const float* h   = (const float*)d_in[0];
    const float* x   = (const float*)d_in[1];
    const float* h0  = (const float*)d_in[3];
    const float* We1 = (const float*)d_in[4];
    const float* be1 = (const float*)d_in[5];
    const float* We2 = (const float*)d_in[6];
    const float* be2 = (const float*)d_in[7];
    const float* Wn1 = (const float*)d_in[8];
    const float* bn1 = (const float*)d_in[9];
    const float* Wn2 = (const float*)d_in[10];
    const float* bn2 = (const float*)d_in[11];
    const float* Wc1 = (const float*)d_in[12];
    const float* bc1 = (const float*)d_in[13];
    const float* Wc2 = (const float*)d_in[14];

    float* out  = (float*)d_out;
    float* hout = out;
    float* xout = out + BB * NNODE * HH;

    cudaFuncSetAttribute(edge_kernel, cudaFuncAttributeMaxDynamicSharedMemorySize,
                         (int)sizeof(EdgeSmem));
    cudaFuncSetAttribute(node_kernel, cudaFuncAttributeMaxDynamicSharedMemorySize,
                         (int)sizeof(NodeSmem));

    prep_kernel<<<BB * NNODE / 32, 256>>>(h, We1, be1);

    dim3 egrid(NNODE / TJ, BB);
    edge_kernel<<<egrid, NTHREADS, sizeof(EdgeSmem)>>>(
        x, We1, We2, be2, Wc1, bc1, Wc2, xout);

    node_kernel<<<BB * NNODE / 16, 256, sizeof(NodeSmem)>>>(
        h, h0, Wn1, bn1, Wn2, bn2, hout);
}

// round 11
// speedup vs baseline: 3.7639x; 1.0357x over previous
#include <cuda_runtime.h>
#include <cstdint>

#define BB 64
#define NNODE 64
#define HH 128
#define TJ 32          // receiver nodes per block
#define TE 128         // edges per MMA tile
#define NTHREADS 512
#define ASTRIDE 132    // activation smem row stride (floats)
#define WSTRIDE 136    // weight smem row stride (floats)

// ---- device scratch ----
__device__ float g_A [BB * NNODE * HH];
__device__ float g_Bm[BB * NNODE * HH];
__device__ float g_mi[BB * NNODE * HH];

__device__ __forceinline__ float silu(float z) {
    // silu(z) = z * sigmoid(z) = 0.5*z*(1 + tanh(z/2)); 1 MUFU instead of 2
    float t;
    asm("tanh.approx.f32 %0, %1;" : "=f"(t) : "f"(z * 0.5f));
    return 0.5f * z * (1.f + t);
}
__device__ __forceinline__ float to_tf32(float x) {
    uint32_t r;
    asm("cvt.rna.tf32.f32 %0, %1;" : "=r"(r) : "f"(x));
    return __uint_as_float(r);
}

__device__ __forceinline__ void mma_tf32(float* c,
    uint32_t a0, uint32_t a1, uint32_t a2, uint32_t a3,
    uint32_t b0, uint32_t b1)
{
    asm volatile(
        "mma.sync.aligned.m16n8k8.row.col.f32.tf32.tf32.f32 "
        "{%0,%1,%2,%3}, {%4,%5,%6,%7}, {%8,%9}, {%0,%1,%2,%3};"
        : "+f"(c[0]), "+f"(c[1]), "+f"(c[2]), "+f"(c[3])
        : "r"(a0), "r"(a1), "r"(a2), "r"(a3), "r"(b0), "r"(b1));
}

// ============================================================
// Kernel 1: prep blocked GEMM. 128 blocks x 32 nodes, 512 thr.
// 16 warps x (2 nodes, 8 cols of 256). Weights staged in 16-k slabs.
// ============================================================
__global__ __launch_bounds__(512) void prep_kernel(
    const float* __restrict__ h,
    const float* __restrict__ We1,
    const float* __restrict__ be1)
{
    __shared__ float hs[32 * 132];
    __shared__ float Ws[16 * 256];
    int tid = threadIdx.x;
    int base = blockIdx.x * 32;

    for (int i = tid; i < 32 * HH; i += 512)
        hs[(i >> 7) * 132 + (i & 127)] = h[base * HH + i];

    const int tn = tid >> 5;        // warp: 2 nodes
    const int lane = tid & 31;
    const int col0 = lane * 8;      // 8 of 256 output cols

    float acc[2][8];
#pragma unroll
    for (int r = 0; r < 2; r++)
#pragma unroll
        for (int c = 0; c < 8; c++) acc[r][c] = 0.f;

    for (int ks = 0; ks < HH; ks += 16) {
        __syncthreads();
        for (int i = tid; i < 16 * 256; i += 512) {
            int kk = i >> 8, t = i & 255;
            int wrow = ks + kk + ((t >= 128) ? 128 : 0);
            Ws[kk * 256 + t] = We1[wrow * HH + (t & 127)];
        }
        __syncthreads();
#pragma unroll
        for (int kk = 0; kk < 16; kk++) {
            float4 w0 = *(const float4*)&Ws[kk * 256 + col0];
            float4 w1 = *(const float4*)&Ws[kk * 256 + col0 + 4];
#pragma unroll
            for (int r = 0; r < 2; r++) {
                float hv = hs[(tn * 2 + r) * 132 + ks + kk];
                acc[r][0] += hv * w0.x; acc[r][1] += hv * w0.y;
                acc[r][2] += hv * w0.z; acc[r][3] += hv * w0.w;
                acc[r][4] += hv * w1.x; acc[r][5] += hv * w1.y;
                acc[r][6] += hv * w1.z; acc[r][7] += hv * w1.w;
            }
        }
    }

    bool isBm = (col0 >= 128);
    int cw = col0 & 127;
    float* outp = isBm ? g_Bm : g_A;
    float4 b0 = make_float4(0.f, 0.f, 0.f, 0.f), b1 = b0;
    if (!isBm) {
        b0 = ((const float4*)be1)[cw >> 2];
        b1 = ((const float4*)be1)[(cw >> 2) + 1];
    }
#pragma unroll
    for (int r = 0; r < 2; r++) {
        int n = base + tn * 2 + r;
        ((float4*)outp)[n * 32 + (cw >> 2)] =
            make_float4(acc[r][0] + b0.x, acc[r][1] + b0.y,
                        acc[r][2] + b0.z, acc[r][3] + b0.w);
        ((float4*)outp)[n * 32 + (cw >> 2) + 1] =
            make_float4(acc[r][4] + b1.x, acc[r][5] + b1.y,
                        acc[r][6] + b1.z, acc[r][7] + b1.w);
    }
}

// ============================================================
// Kernel 2: mma.sync tf32 edge kernel. Block = (b, 32 j). 512 thr.
// (identical to R10 passing version except fast silu)
// ============================================================
#define ELIST 2176

struct EdgeSmem {
    float As[TE * ASTRIDE];      // activations / mij
    float W1[HH * WSTRIDE];      // We2 [k][n]
    float W2[HH * WSTRIDE];      // Wc1 [k][n]
    float mi[TJ * HH];
    float phi[TE];
    unsigned short ekey[ELIST];  // (jl<<6)|k, sorted
    float xk[NNODE * 3];
    float be2s[HH], bc1s[HH], wc2s[HH], wds[HH];
    int jstart[33];
    union {
        struct { int wcnt[64]; int wexc[64]; } c;
        float d2t[TE];           // per-tile edge d^2 (after compaction)
    } u;
    float xup[TJ][3];
    int cnt;
};

__global__ __launch_bounds__(NTHREADS, 1) void edge_kernel(
    const float* __restrict__ x,
    const float* __restrict__ We1,
    const float* __restrict__ We2,
    const float* __restrict__ be2,
    const float* __restrict__ Wc1,
    const float* __restrict__ bc1,
    const float* __restrict__ Wc2,
    float* __restrict__ xout)
{
    extern __shared__ char smem_raw[];
    EdgeSmem* S = (EdgeSmem*)smem_raw;
    int tid = threadIdx.x;
    int wid = tid >> 5, lane = tid & 31;
    int jt = blockIdx.x;    // 0..1
    int b  = blockIdx.y;    // 0..63

    for (int i = tid; i < HH * HH; i += NTHREADS) {
        int k = i >> 7, n = i & 127;
        S->W1[k * WSTRIDE + n] = to_tf32(We2[i]);
        S->W2[k * WSTRIDE + n] = to_tf32(Wc1[i]);
    }
    for (int i = tid; i < TJ * HH; i += NTHREADS) S->mi[i] = 0.f;
    if (tid < NNODE * 3) S->xk[tid] = x[b * NNODE * 3 + tid];
    if (tid < HH) {
        S->be2s[tid] = be2[tid];
        S->bc1s[tid] = bc1[tid];
        S->wc2s[tid] = Wc2[tid];
        S->wds [tid] = We1[2 * HH * HH + tid];
    }
    if (tid < TJ * 3) S->xup[tid / 3][tid % 3] = 0.f;
    __syncthreads();

    // ---- compaction ----
#pragma unroll
    for (int p = 0; p < 4; p++) {
        int pid = p * 512 + tid;
        int jl = pid >> 6, k = pid & 63;
        int j = jt * TJ + jl;
        float dx = S->xk[j * 3 + 0] - S->xk[k * 3 + 0];
        float dy = S->xk[j * 3 + 1] - S->xk[k * 3 + 1];
        float dz = S->xk[j * 3 + 2] - S->xk[k * 3 + 2];
        float d2 = dx * dx + dy * dy + dz * dz;
        bool act = (k != j) && (d2 < 25.f);
        unsigned ball = __ballot_sync(0xffffffffu, act);
        if (lane == 0) S->u.c.wcnt[p * 16 + wid] = __popc(ball);
    }
    __syncthreads();
    if (tid == 0) {
        int run = 0;
        for (int i = 0; i < 64; i++) { S->u.c.wexc[i] = run; run += S->u.c.wcnt[i]; }
        S->cnt = run;
    }
    __syncthreads();
#pragma unroll
    for (int p = 0; p < 4; p++) {
        int pid = p * 512 + tid;
        int jl = pid >> 6, k = pid & 63;
        int j = jt * TJ + jl;
        float dx = S->xk[j * 3 + 0] - S->xk[k * 3 + 0];
        float dy = S->xk[j * 3 + 1] - S->xk[k * 3 + 1];
        float dz = S->xk[j * 3 + 2] - S->xk[k * 3 + 2];
        float d2 = dx * dx + dy * dy + dz * dz;
        bool act = (k != j) && (d2 < 25.f);
        unsigned ball = __ballot_sync(0xffffffffu, act);
        if (act) {
            int pos = S->u.c.wexc[p * 16 + wid] + __popc(ball & ((1u << lane) - 1u));
            S->ekey[pos] = (unsigned short)((jl << 6) | k);
        }
    }
    __syncthreads();
    const int cnt = S->cnt;
    if (tid < TE) S->ekey[cnt + tid] = 0;
    if (tid < 33) {
        int target = tid << 6;
        int lo = 0, hi = cnt;
        while (lo < hi) {
            int mid = (lo + hi) >> 1;
            if ((int)S->ekey[mid] < target) lo = mid + 1; else hi = mid;
        }
        S->jstart[tid] = lo;
    }
    __syncthreads();

    const float4* gA4  = (const float4*)g_A  + (size_t)b * NNODE * 32;
    const float4* gBm4 = (const float4*)g_Bm + (size_t)b * NNODE * 32;

    const int g = lane >> 2, q = lane & 3;
    const int m0 = (wid >> 1) * 16;
    const int n0 = (wid & 1) * 64;
    int ntiles = (cnt + TE - 1) / TE;

    for (int ti = 0; ti < ntiles; ti++) {
        int start = ti * TE;

        if (tid < TE) {
            S->phi[tid] = 0.f;
            int key = S->ekey[start + tid];
            int jl = key >> 6, k = key & 63;
            int j = jt * TJ + jl;
            float dx = S->xk[j * 3 + 0] - S->xk[k * 3 + 0];
            float dy = S->xk[j * 3 + 1] - S->xk[k * 3 + 1];
            float dz = S->xk[j * 3 + 2] - S->xk[k * 3 + 2];
            S->u.d2t[tid] = dx * dx + dy * dy + dz * dz;
        }
        __syncthreads();

        for (int idx = tid; idx < TE * 32; idx += NTHREADS) {
            int e = idx >> 5, h4 = idx & 31;
            int key = S->ekey[start + e];
            int jl = key >> 6, k = key & 63;
            int j = jt * TJ + jl;
            float d2 = S->u.d2t[e];
            float4 av = __ldg(&gA4[j * 32 + h4]);
            float4 bv = __ldg(&gBm4[k * 32 + h4]);
            float4 wv = ((const float4*)S->wds)[h4];
            float4 tv;
            tv.x = to_tf32(silu(av.x + bv.x + d2 * wv.x));
            tv.y = to_tf32(silu(av.y + bv.y + d2 * wv.y));
            tv.z = to_tf32(silu(av.z + bv.z + d2 * wv.z));
            tv.w = to_tf32(silu(av.w + bv.w + d2 * wv.w));
            *(float4*)&S->As[e * ASTRIDE + h4 * 4] = tv;
        }
        __syncthreads();

        // ---- GEMM1 ----
        float acc[8][4];
#pragma unroll
        for (int nt = 0; nt < 8; nt++)
#pragma unroll
            for (int c = 0; c < 4; c++) acc[nt][c] = 0.f;

#pragma unroll
        for (int kt = 0; kt < 16; kt++) {
            int k0 = kt * 8;
            uint32_t a0 = __float_as_uint(S->As[(m0 + g)     * ASTRIDE + k0 + q]);
            uint32_t a1 = __float_as_uint(S->As[(m0 + g + 8) * ASTRIDE + k0 + q]);
            uint32_t a2 = __float_as_uint(S->As[(m0 + g)     * ASTRIDE + k0 + 4 + q]);
            uint32_t a3 = __float_as_uint(S->As[(m0 + g + 8) * ASTRIDE + k0 + 4 + q]);
#pragma unroll
            for (int nt = 0; nt < 8; nt++) {
                uint32_t b0 = __float_as_uint(S->W1[(k0 + q)     * WSTRIDE + n0 + nt * 8 + g]);
                uint32_t b1 = __float_as_uint(S->W1[(k0 + 4 + q) * WSTRIDE + n0 + nt * 8 + g]);
                mma_tf32(acc[nt], a0, a1, a2, a3, b0, b1);
            }
        }
        __syncthreads();

        // ---- epilogue 1 ----
        {
            int r0 = m0 + g;
            float d2a = S->u.d2t[r0];
            float d2b = S->u.d2t[r0 + 8];
            float cut0 = 1.f - 0.06f * d2a + 0.004f * d2a * sqrtf(d2a);
            float cut1 = 1.f - 0.06f * d2b + 0.004f * d2b * sqrtf(d2b);
#pragma unroll
            for (int nt = 0; nt < 8; nt++) {
                int col = n0 + nt * 8 + q * 2;
                float be0 = S->be2s[col], be1v = S->be2s[col + 1];
                float2 top, bot;
                top.x = to_tf32(silu(acc[nt][0] + be0)  * cut0);
                top.y = to_tf32(silu(acc[nt][1] + be1v) * cut0);
                bot.x = to_tf32(silu(acc[nt][2] + be0)  * cut1);
                bot.y = to_tf32(silu(acc[nt][3] + be1v) * cut1);
                *(float2*)&S->As[r0 * ASTRIDE + col] = top;
                *(float2*)&S->As[(r0 + 8) * ASTRIDE + col] = bot;
            }
        }
        __syncthreads();

        // ---- mi accumulation ----
        {
            int jl = tid >> 4, cg = tid & 15;
            int lo = max(S->jstart[jl], start);
            int hi = min(S->jstart[jl + 1], start + TE);
            if (lo < hi) {
                float4 s0 = make_float4(0, 0, 0, 0), s1 = s0;
                for (int e = lo; e < hi; e++) {
                    const float4* rp = (const float4*)&S->As[(e - start) * ASTRIDE + cg * 8];
                    float4 v0 = rp[0], v1 = rp[1];
                    s0.x += v0.x; s0.y += v0.y; s0.z += v0.z; s0.w += v0.w;
                    s1.x += v1.x; s1.y += v1.y; s1.z += v1.z; s1.w += v1.w;
                }
                float4* mip = (float4*)&S->mi[jl * HH + cg * 8];
                float4 m0v = mip[0], m1v = mip[1];
                mip[0] = make_float4(m0v.x + s0.x, m0v.y + s0.y, m0v.z + s0.z, m0v.w + s0.w);
                mip[1] = make_float4(m1v.x + s1.x, m1v.y + s1.y, m1v.z + s1.z, m1v.w + s1.w);
            }
        }

        // ---- GEMM2 ----
#pragma unroll
        for (int nt = 0; nt < 8; nt++)
#pragma unroll
            for (int c = 0; c < 4; c++) acc[nt][c] = 0.f;

#pragma unroll
        for (int kt = 0; kt < 16; kt++) {
            int k0 = kt * 8;
            uint32_t a0 = __float_as_uint(S->As[(m0 + g)     * ASTRIDE + k0 + q]);
            uint32_t a1 = __float_as_uint(S->As[(m0 + g + 8) * ASTRIDE + k0 + q]);
            uint32_t a2 = __float_as_uint(S->As[(m0 + g)     * ASTRIDE + k0 + 4 + q]);
            uint32_t a3 = __float_as_uint(S->As[(m0 + g + 8) * ASTRIDE + k0 + 4 + q]);
#pragma unroll
            for (int nt = 0; nt < 8; nt++) {
                uint32_t b0 = __float_as_uint(S->W2[(k0 + q)     * WSTRIDE + n0 + nt * 8 + g]);
                uint32_t b1 = __float_as_uint(S->W2[(k0 + 4 + q) * WSTRIDE + n0 + nt * 8 + g]);
                mma_tf32(acc[nt], a0, a1, a2, a3, b0, b1);
            }
        }

        // ---- epilogue 2 ----
        {
            float p0 = 0.f, p1 = 0.f;
#pragma unroll
            for (int nt = 0; nt < 8; nt++) {
                int col = n0 + nt * 8 + q * 2;
                float bc0 = S->bc1s[col], bc1v = S->bc1s[col + 1];
                float wc0 = S->wc2s[col], wc1v = S->wc2s[col + 1];
                p0 += silu(acc[nt][0] + bc0)  * wc0;
                p0 += silu(acc[nt][1] + bc1v) * wc1v;
                p1 += silu(acc[nt][2] + bc0)  * wc0;
                p1 += silu(acc[nt][3] + bc1v) * wc1v;
            }
#pragma unroll
            for (int off = 1; off < 4; off <<= 1) {
                p0 += __shfl_xor_sync(0xffffffffu, p0, off);
                p1 += __shfl_xor_sync(0xffffffffu, p1, off);
            }
            if (q == 0) {
                int r0 = m0 + g;
                atomicAdd(&S->phi[r0], p0);
                atomicAdd(&S->phi[r0 + 8], p1);
            }
        }
        __syncthreads();

        if (tid < TE && start + tid < cnt) {
            int key = S->ekey[start + tid];
            int jl = key >> 6, k = key & 63;
            int j = jt * TJ + jl;
            float p = S->phi[tid];
            atomicAdd(&S->xup[jl][0], (S->xk[j * 3 + 0] - S->xk[k * 3 + 0]) * p);
            atomicAdd(&S->xup[jl][1], (S->xk[j * 3 + 1] - S->xk[k * 3 + 1]) * p);
            atomicAdd(&S->xup[jl][2], (S->xk[j * 3 + 2] - S->xk[k * 3 + 2]) * p);
        }
        __syncthreads();
    }

    for (int i = tid; i < TJ * HH; i += NTHREADS)
        g_mi[(b * NNODE + jt * TJ) * HH + i] = S->mi[i];
    if (tid < TJ * 3) {
        int jl = tid / 3, c = tid % 3;
        int j = jt * TJ + jl;
        float v = S->xk[j * 3 + c] + (1.f / 63.f) * S->xup[jl][c];
        v = fminf(fmaxf(v, -1000.f), 1000.f);
        xout[(b * NNODE + j) * 3 + c] = v;
    }
}

// ============================================================
// Kernel 3: node MLP via tf32 mma. 128 blocks x 32 nodes, 256 thr.
// 8 warps = 2m x 4n (M=16, N=32 per warp). Wn1 staged in 3 k-slabs.
// ============================================================
#define NSTR 388
#define USTR 132
#define NWSTR 136

struct NodeSmem {
    float nf[32 * NSTR];     // [node][384] tf32 (49664 B)
    float wb[128 * NWSTR];   // weight slab [k][n] tf32 (69632 B)
    float u [32 * USTR];     // layer-1 act tf32 (16896 B)
    float bn1s[HH], bn2s[HH];
};

__global__ __launch_bounds__(256, 1) void node_kernel(
    const float* __restrict__ h,
    const float* __restrict__ h0,
    const float* __restrict__ Wn1,
    const float* __restrict__ bn1,
    const float* __restrict__ Wn2,
    const float* __restrict__ bn2,
    float* __restrict__ hout)
{
    extern __shared__ char smem_raw[];
    NodeSmem* S = (NodeSmem*)smem_raw;
    int tid = threadIdx.x;
    int wid = tid >> 5, lane = tid & 31;
    int base = blockIdx.x * 32;

    // stage nf = [h, mi, h0] tf32
    for (int i = tid; i < 32 * 384; i += 256) {
        int n = i / 384, k = i % 384;
        float v;
        if (k < 128)      v = h   [(base + n) * HH + k];
        else if (k < 256) v = g_mi[(base + n) * HH + k - 128];
        else              v = h0  [(base + n) * HH + k - 256];
        S->nf[n * NSTR + k] = to_tf32(v);
    }
    if (tid < HH) {
        S->bn1s[tid] = bn1[tid];
        S->bn2s[tid] = bn2[tid];
    }

    const int g = lane >> 2, q = lane & 3;
    const int m0 = (wid >> 2) * 16;      // 2 m-groups
    const int n0 = (wid & 3) * 32;       // 4 n-groups

    // ---- layer 1: u = silu(nf @ Wn1 + bn1), K=384 in 3 slabs ----
    float acc[4][4];
#pragma unroll
    for (int nt = 0; nt < 4; nt++)
#pragma unroll
        for (int c = 0; c < 4; c++) acc[nt][c] = 0.f;

    for (int ks = 0; ks < 384; ks += 128) {
        __syncthreads();
        for (int i = tid; i < 128 * HH; i += 256) {
            int kk = i >> 7, n = i & 127;
            S->wb[kk * NWSTR + n] = to_tf32(Wn1[(ks + kk) * HH + n]);
        }
        __syncthreads();
#pragma unroll
        for (int kt = 0; kt < 16; kt++) {
            int k0 = kt * 8;
            uint32_t a0 = __float_as_uint(S->nf[(m0 + g)     * NSTR + ks + k0 + q]);
            uint32_t a1 = __float_as_uint(S->nf[(m0 + g + 8) * NSTR + ks + k0 + q]);
            uint32_t a2 = __float_as_uint(S->nf[(m0 + g)     * NSTR + ks + k0 + 4 + q]);
            uint32_t a3 = __float_as_uint(S->nf[(m0 + g + 8) * NSTR + ks + k0 + 4 + q]);
#pragma unroll
            for (int nt = 0; nt < 4; nt++) {
                uint32_t b0 = __float_as_uint(S->wb[(k0 + q)     * NWSTR + n0 + nt * 8 + g]);
                uint32_t b1 = __float_as_uint(S->wb[(k0 + 4 + q) * NWSTR + n0 + nt * 8 + g]);
                mma_tf32(acc[nt], a0, a1, a2, a3, b0, b1);
            }
        }
    }
    // epilogue 1
    {
        int r0 = m0 + g;
#pragma unroll
        for (int nt = 0; nt < 4; nt++) {
            int col = n0 + nt * 8 + q * 2;
            float b0 = S->bn1s[col], b1 = S->bn1s[col + 1];
            float2 top, bot;
            top.x = to_tf32(silu(acc[nt][0] + b0));
            top.y = to_tf32(silu(acc[nt][1] + b1));
            bot.x = to_tf32(silu(acc[nt][2] + b0));
            bot.y = to_tf32(silu(acc[nt][3] + b1));
            *(float2*)&S->u[r0 * USTR + col] = top;
            *(float2*)&S->u[(r0 + 8) * USTR + col] = bot;
        }
    }
    __syncthreads();

    // stage Wn2 into wb
    for (int i = tid; i < HH * HH; i += 256) {
        int kk = i >> 7, n = i & 127;
        S->wb[kk * NWSTR + n] = to_tf32(Wn2[kk * HH + n]);
    }
    __syncthreads();

    // ---- layer 2 ----
#pragma unroll
    for (int nt = 0; nt < 4; nt++)
#pragma unroll
        for (int c = 0; c < 4; c++) acc[nt][c] = 0.f;

#pragma unroll
    for (int kt = 0; kt < 16; kt++) {
        int k0 = kt * 8;
        uint32_t a0 = __float_as_uint(S->u[(m0 + g)     * USTR + k0 + q]);
        uint32_t a1 = __float_as_uint(S->u[(m0 + g + 8) * USTR + k0 + q]);
        uint32_t a2 = __float_as_uint(S->u[(m0 + g)     * USTR + k0 + 4 + q]);
        uint32_t a3 = __float_as_uint(S->u[(m0 + g + 8) * USTR + k0 + 4 + q]);
#pragma unroll
        for (int nt = 0; nt < 4; nt++) {
            uint32_t b0 = __float_as_uint(S->wb[(k0 + q)     * NWSTR + n0 + nt * 8 + g]);
            uint32_t b1 = __float_as_uint(S->wb[(k0 + 4 + q) * NWSTR + n0 + nt * 8 + g]);
            mma_tf32(acc[nt], a0, a1, a2, a3, b0, b1);
        }
    }

    // epilogue 2: h_new = h + out + bn2 (h re-read fp32 for exact residual)
    {
        int r0 = m0 + g;
#pragma unroll
        for (int nt = 0; nt < 4; nt++) {
            int col = n0 + nt * 8 + q * 2;
            float b0 = S->bn2s[col], b1 = S->bn2s[col + 1];
            float2 h_t = *(const float2*)&h[(base + r0) * HH + col];
            float2 h_b = *(const float2*)&h[(base + r0 + 8) * HH + col];
            float2 top, bot;
            top.x = acc[nt][0] + b0 + h_t.x;
            top.y = acc[nt][1] + b1 + h_t.y;
            bot.x = acc[nt][2] + b0 + h_b.x;
            bot.y = acc[nt][3] + b1 + h_b.y;
            *(float2*)&hout[(base + r0) * HH + col] = top;
            *(float2*)&hout[(base + r0 + 8) * HH + col] = bot;
        }
    }
}

// ============================================================
extern "C" void kernel_launch(void* const* d_in, const int* in_sizes, int n_in,
                              void* d_out, int out_size)
{
    (void)in_sizes; (void)n_in; (void)out_size;
    const float* h   = (const float*)d_in[0];
    const float* x   = (const float*)d_in[1];
    const float* h0  = (const float*)d_in[3];
    const float* We1 = (const float*)d_in[4];
    const float* be1 = (const float*)d_in[5];
    const float* We2 = (const float*)d_in[6];
    const float* be2 = (const float*)d_in[7];
    const float* Wn1 = (const float*)d_in[8];
    const float* bn1 = (const float*)d_in[9];
    const float* Wn2 = (const float*)d_in[10];
    const float* bn2 = (const float*)d_in[11];
    const float* Wc1 = (const float*)d_in[12];
    const float* bc1 = (const float*)d_in[13];
    const float* Wc2 = (const float*)d_in[14];

    float* out  = (float*)d_out;
    float* hout = out;
    float* xout = out + BB * NNODE * HH;

    cudaFuncSetAttribute(edge_kernel, cudaFuncAttributeMaxDynamicSharedMemorySize,
                         (int)sizeof(EdgeSmem));
    cudaFuncSetAttribute(node_kernel, cudaFuncAttributeMaxDynamicSharedMemorySize,
                         (int)sizeof(NodeSmem));

    prep_kernel<<<BB * NNODE / 32, 512>>>(h, We1, be1);

    dim3 egrid(NNODE / TJ, BB);
    edge_kernel<<<egrid, NTHREADS, sizeof(EdgeSmem)>>>(
        x, We1, We2, be2, Wc1, bc1, Wc2, xout);

    node_kernel<<<BB * NNODE / 32, 256, sizeof(NodeSmem)>>>(
        h, h0, Wn1, bn1, Wn2, bn2, hout);
}

// round 12
// speedup vs baseline: 4.1014x; 1.0897x over previous
#include <cuda_runtime.h>
#include <cstdint>

#define BB 64
#define NNODE 64
#define HH 128
#define TJ 32          // receiver nodes per block
#define TE 128         // edges per MMA tile
#define NTHREADS 512
#define ASTRIDE 132    // activation smem row stride (floats)
#define WSTRIDE 136    // weight smem row stride (floats)

// ---- device scratch ----
__device__ float g_A [BB * NNODE * HH];
__device__ float g_Bm[BB * NNODE * HH];
__device__ float g_mi[BB * NNODE * HH];

__device__ __forceinline__ float silu(float z) {
    // silu(z) = 0.5*z*(1 + tanh(z/2)); 1 MUFU instead of 2
    float t;
    asm("tanh.approx.f32 %0, %1;" : "=f"(t) : "f"(z * 0.5f));
    return 0.5f * z * (1.f + t);
}
__device__ __forceinline__ float to_tf32(float x) {
    uint32_t r;
    asm("cvt.rna.tf32.f32 %0, %1;" : "=r"(r) : "f"(x));
    return __uint_as_float(r);
}

__device__ __forceinline__ void mma_tf32(float* c,
    uint32_t a0, uint32_t a1, uint32_t a2, uint32_t a3,
    uint32_t b0, uint32_t b1)
{
    asm volatile(
        "mma.sync.aligned.m16n8k8.row.col.f32.tf32.tf32.f32 "
        "{%0,%1,%2,%3}, {%4,%5,%6,%7}, {%8,%9}, {%0,%1,%2,%3};"
        : "+f"(c[0]), "+f"(c[1]), "+f"(c[2]), "+f"(c[3])
        : "r"(a0), "r"(a1), "r"(a2), "r"(a3), "r"(b0), "r"(b1));
}

// ============================================================
// Kernel 1: prep GEMM, software-pipelined double-buffered slabs.
// grid (128 node-groups, 2 col-halves), 256 threads, fp32 exact.
// half 0: A[n] = h[n]@We1[0:128] + be1 ; half 1: Bm[n] = h[n]@We1[128:256]
// ============================================================
__global__ __launch_bounds__(256) void prep_kernel(
    const float* __restrict__ h,
    const float* __restrict__ We1,
    const float* __restrict__ be1)
{
    __shared__ float hs[32 * 132];
    __shared__ float Ws[2][16 * 128];
    int tid = threadIdx.x;
    int base = blockIdx.x * 32;
    int half = blockIdx.y;
    const float* Wbase = We1 + (size_t)half * HH * HH;

    for (int i = tid; i < 32 * HH; i += 256)
        hs[(i >> 7) * 132 + (i & 127)] = h[base * HH + i];
    for (int i = tid; i < 16 * 128; i += 256)
        Ws[0][i] = __ldg(&Wbase[i]);
    __syncthreads();

    const int tn = tid >> 5;        // 8 warps x 4 nodes
    const int lane = tid & 31;
    const int col0 = lane * 4;

    float acc[4][4];
#pragma unroll
    for (int r = 0; r < 4; r++)
#pragma unroll
        for (int c = 0; c < 4; c++) acc[r][c] = 0.f;

    for (int s = 0; s < 8; s++) {
        float r[8];
        if (s < 7) {
            const float* src = Wbase + (s + 1) * 16 * 128;
#pragma unroll
            for (int u = 0; u < 8; u++) r[u] = __ldg(&src[u * 256 + tid]);
        }
        const float* W = Ws[s & 1];
        int ks = s * 16;
#pragma unroll
        for (int kk = 0; kk < 16; kk++) {
            float4 w = *(const float4*)&W[kk * 128 + col0];
#pragma unroll
            for (int rr = 0; rr < 4; rr++) {
                float hv = hs[(tn * 4 + rr) * 132 + ks + kk];
                acc[rr][0] += hv * w.x; acc[rr][1] += hv * w.y;
                acc[rr][2] += hv * w.z; acc[rr][3] += hv * w.w;
            }
        }
        if (s < 7) {
            float* Wn = Ws[(s + 1) & 1];
#pragma unroll
            for (int u = 0; u < 8; u++) Wn[u * 256 + tid] = r[u];
        }
        __syncthreads();
    }

    float* outp = half ? g_Bm : g_A;
    float4 bv = make_float4(0.f, 0.f, 0.f, 0.f);
    if (!half) bv = ((const float4*)be1)[col0 >> 2];
#pragma unroll
    for (int rr = 0; rr < 4; rr++) {
        int n = base + tn * 4 + rr;
        ((float4*)outp)[n * 32 + (col0 >> 2)] =
            make_float4(acc[rr][0] + bv.x, acc[rr][1] + bv.y,
                        acc[rr][2] + bv.z, acc[rr][3] + bv.w);
    }
}

// ============================================================
// Kernel 2: mma.sync tf32 edge kernel. Block = (b, 32 j). 512 thr.
// (identical to R11 passing version)
// ============================================================
#define ELIST 2176

struct EdgeSmem {
    float As[TE * ASTRIDE];      // activations / mij
    float W1[HH * WSTRIDE];      // We2 [k][n]
    float W2[HH * WSTRIDE];      // Wc1 [k][n]
    float mi[TJ * HH];
    float phi[TE];
    unsigned short ekey[ELIST];  // (jl<<6)|k, sorted
    float xk[NNODE * 3];
    float be2s[HH], bc1s[HH], wc2s[HH], wds[HH];
    int jstart[33];
    union {
        struct { int wcnt[64]; int wexc[64]; } c;
        float d2t[TE];
    } u;
    float xup[TJ][3];
    int cnt;
};

__global__ __launch_bounds__(NTHREADS, 1) void edge_kernel(
    const float* __restrict__ x,
    const float* __restrict__ We1,
    const float* __restrict__ We2,
    const float* __restrict__ be2,
    const float* __restrict__ Wc1,
    const float* __restrict__ bc1,
    const float* __restrict__ Wc2,
    float* __restrict__ xout)
{
    extern __shared__ char smem_raw[];
    EdgeSmem* S = (EdgeSmem*)smem_raw;
    int tid = threadIdx.x;
    int wid = tid >> 5, lane = tid & 31;
    int jt = blockIdx.x;
    int b  = blockIdx.y;

    for (int i = tid; i < HH * HH; i += NTHREADS) {
        int k = i >> 7, n = i & 127;
        S->W1[k * WSTRIDE + n] = to_tf32(We2[i]);
        S->W2[k * WSTRIDE + n] = to_tf32(Wc1[i]);
    }
    for (int i = tid; i < TJ * HH; i += NTHREADS) S->mi[i] = 0.f;
    if (tid < NNODE * 3) S->xk[tid] = x[b * NNODE * 3 + tid];
    if (tid < HH) {
        S->be2s[tid] = be2[tid];
        S->bc1s[tid] = bc1[tid];
        S->wc2s[tid] = Wc2[tid];
        S->wds [tid] = We1[2 * HH * HH + tid];
    }
    if (tid < TJ * 3) S->xup[tid / 3][tid % 3] = 0.f;
    __syncthreads();

#pragma unroll
    for (int p = 0; p < 4; p++) {
        int pid = p * 512 + tid;
        int jl = pid >> 6, k = pid & 63;
        int j = jt * TJ + jl;
        float dx = S->xk[j * 3 + 0] - S->xk[k * 3 + 0];
        float dy = S->xk[j * 3 + 1] - S->xk[k * 3 + 1];
        float dz = S->xk[j * 3 + 2] - S->xk[k * 3 + 2];
        float d2 = dx * dx + dy * dy + dz * dz;
        bool act = (k != j) && (d2 < 25.f);
        unsigned ball = __ballot_sync(0xffffffffu, act);
        if (lane == 0) S->u.c.wcnt[p * 16 + wid] = __popc(ball);
    }
    __syncthreads();
    if (tid == 0) {
        int run = 0;
        for (int i = 0; i < 64; i++) { S->u.c.wexc[i] = run; run += S->u.c.wcnt[i]; }
        S->cnt = run;
    }
    __syncthreads();
#pragma unroll
    for (int p = 0; p < 4; p++) {
        int pid = p * 512 + tid;
        int jl = pid >> 6, k = pid & 63;
        int j = jt * TJ + jl;
        float dx = S->xk[j * 3 + 0] - S->xk[k * 3 + 0];
        float dy = S->xk[j * 3 + 1] - S->xk[k * 3 + 1];
        float dz = S->xk[j * 3 + 2] - S->xk[k * 3 + 2];
        float d2 = dx * dx + dy * dy + dz * dz;
        bool act = (k != j) && (d2 < 25.f);
        unsigned ball = __ballot_sync(0xffffffffu, act);
        if (act) {
            int pos = S->u.c.wexc[p * 16 + wid] + __popc(ball & ((1u << lane) - 1u));
            S->ekey[pos] = (unsigned short)((jl << 6) | k);
        }
    }
    __syncthreads();
    const int cnt = S->cnt;
    if (tid < TE) S->ekey[cnt + tid] = 0;
    if (tid < 33) {
        int target = tid << 6;
        int lo = 0, hi = cnt;
        while (lo < hi) {
            int mid = (lo + hi) >> 1;
            if ((int)S->ekey[mid] < target) lo = mid + 1; else hi = mid;
        }
        S->jstart[tid] = lo;
    }
    __syncthreads();

    const float4* gA4  = (const float4*)g_A  + (size_t)b * NNODE * 32;
    const float4* gBm4 = (const float4*)g_Bm + (size_t)b * NNODE * 32;

    const int g = lane >> 2, q = lane & 3;
    const int m0 = (wid >> 1) * 16;
    const int n0 = (wid & 1) * 64;
    int ntiles = (cnt + TE - 1) / TE;

    for (int ti = 0; ti < ntiles; ti++) {
        int start = ti * TE;

        if (tid < TE) {
            S->phi[tid] = 0.f;
            int key = S->ekey[start + tid];
            int jl = key >> 6, k = key & 63;
            int j = jt * TJ + jl;
            float dx = S->xk[j * 3 + 0] - S->xk[k * 3 + 0];
            float dy = S->xk[j * 3 + 1] - S->xk[k * 3 + 1];
            float dz = S->xk[j * 3 + 2] - S->xk[k * 3 + 2];
            S->u.d2t[tid] = dx * dx + dy * dy + dz * dz;
        }
        __syncthreads();

        for (int idx = tid; idx < TE * 32; idx += NTHREADS) {
            int e = idx >> 5, h4 = idx & 31;
            int key = S->ekey[start + e];
            int jl = key >> 6, k = key & 63;
            int j = jt * TJ + jl;
            float d2 = S->u.d2t[e];
            float4 av = __ldg(&gA4[j * 32 + h4]);
            float4 bv = __ldg(&gBm4[k * 32 + h4]);
            float4 wv = ((const float4*)S->wds)[h4];
            float4 tv;
            tv.x = to_tf32(silu(av.x + bv.x + d2 * wv.x));
            tv.y = to_tf32(silu(av.y + bv.y + d2 * wv.y));
            tv.z = to_tf32(silu(av.z + bv.z + d2 * wv.z));
            tv.w = to_tf32(silu(av.w + bv.w + d2 * wv.w));
            *(float4*)&S->As[e * ASTRIDE + h4 * 4] = tv;
        }
        __syncthreads();

        float acc[8][4];
#pragma unroll
        for (int nt = 0; nt < 8; nt++)
#pragma unroll
            for (int c = 0; c < 4; c++) acc[nt][c] = 0.f;

#pragma unroll
        for (int kt = 0; kt < 16; kt++) {
            int k0 = kt * 8;
            uint32_t a0 = __float_as_uint(S->As[(m0 + g)     * ASTRIDE + k0 + q]);
            uint32_t a1 = __float_as_uint(S->As[(m0 + g + 8) * ASTRIDE + k0 + q]);
            uint32_t a2 = __float_as_uint(S->As[(m0 + g)     * ASTRIDE + k0 + 4 + q]);
            uint32_t a3 = __float_as_uint(S->As[(m0 + g + 8) * ASTRIDE + k0 + 4 + q]);
#pragma unroll
            for (int nt = 0; nt < 8; nt++) {
                uint32_t b0 = __float_as_uint(S->W1[(k0 + q)     * WSTRIDE + n0 + nt * 8 + g]);
                uint32_t b1 = __float_as_uint(S->W1[(k0 + 4 + q) * WSTRIDE + n0 + nt * 8 + g]);
                mma_tf32(acc[nt], a0, a1, a2, a3, b0, b1);
            }
        }
        __syncthreads();

        {
            int r0 = m0 + g;
            float d2a = S->u.d2t[r0];
            float d2b = S->u.d2t[r0 + 8];
            float cut0 = 1.f - 0.06f * d2a + 0.004f * d2a * sqrtf(d2a);
            float cut1 = 1.f - 0.06f * d2b + 0.004f * d2b * sqrtf(d2b);
#pragma unroll
            for (int nt = 0; nt < 8; nt++) {
                int col = n0 + nt * 8 + q * 2;
                float be0 = S->be2s[col], be1v = S->be2s[col + 1];
                float2 top, bot;
                top.x = to_tf32(silu(acc[nt][0] + be0)  * cut0);
                top.y = to_tf32(silu(acc[nt][1] + be1v) * cut0);
                bot.x = to_tf32(silu(acc[nt][2] + be0)  * cut1);
                bot.y = to_tf32(silu(acc[nt][3] + be1v) * cut1);
                *(float2*)&S->As[r0 * ASTRIDE + col] = top;
                *(float2*)&S->As[(r0 + 8) * ASTRIDE + col] = bot;
            }
        }
        __syncthreads();

        {
            int jl = tid >> 4, cg = tid & 15;
            int lo = max(S->jstart[jl], start);
            int hi = min(S->jstart[jl + 1], start + TE);
            if (lo < hi) {
                float4 s0 = make_float4(0, 0, 0, 0), s1 = s0;
                for (int e = lo; e < hi; e++) {
                    const float4* rp = (const float4*)&S->As[(e - start) * ASTRIDE + cg * 8];
                    float4 v0 = rp[0], v1 = rp[1];
                    s0.x += v0.x; s0.y += v0.y; s0.z += v0.z; s0.w += v0.w;
                    s1.x += v1.x; s1.y += v1.y; s1.z += v1.z; s1.w += v1.w;
                }
                float4* mip = (float4*)&S->mi[jl * HH + cg * 8];
                float4 m0v = mip[0], m1v = mip[1];
                mip[0] = make_float4(m0v.x + s0.x, m0v.y + s0.y, m0v.z + s0.z, m0v.w + s0.w);
                mip[1] = make_float4(m1v.x + s1.x, m1v.y + s1.y, m1v.z + s1.z, m1v.w + s1.w);
            }
        }

#pragma unroll
        for (int nt = 0; nt < 8; nt++)
#pragma unroll
            for (int c = 0; c < 4; c++) acc[nt][c] = 0.f;

#pragma unroll
        for (int kt = 0; kt < 16; kt++) {
            int k0 = kt * 8;
            uint32_t a0 = __float_as_uint(S->As[(m0 + g)     * ASTRIDE + k0 + q]);
            uint32_t a1 = __float_as_uint(S->As[(m0 + g + 8) * ASTRIDE + k0 + q]);
            uint32_t a2 = __float_as_uint(S->As[(m0 + g)     * ASTRIDE + k0 + 4 + q]);
            uint32_t a3 = __float_as_uint(S->As[(m0 + g + 8) * ASTRIDE + k0 + 4 + q]);
#pragma unroll
            for (int nt = 0; nt < 8; nt++) {
                uint32_t b0 = __float_as_uint(S->W2[(k0 + q)     * WSTRIDE + n0 + nt * 8 + g]);
                uint32_t b1 = __float_as_uint(S->W2[(k0 + 4 + q) * WSTRIDE + n0 + nt * 8 + g]);
                mma_tf32(acc[nt], a0, a1, a2, a3, b0, b1);
            }
        }

        {
            float p0 = 0.f, p1 = 0.f;
#pragma unroll
            for (int nt = 0; nt < 8; nt++) {
                int col = n0 + nt * 8 + q * 2;
                float bc0 = S->bc1s[col], bc1v = S->bc1s[col + 1];
                float wc0 = S->wc2s[col], wc1v = S->wc2s[col + 1];
                p0 += silu(acc[nt][0] + bc0)  * wc0;
                p0 += silu(acc[nt][1] + bc1v) * wc1v;
                p1 += silu(acc[nt][2] + bc0)  * wc0;
                p1 += silu(acc[nt][3] + bc1v) * wc1v;
            }
#pragma unroll
            for (int off = 1; off < 4; off <<= 1) {
                p0 += __shfl_xor_sync(0xffffffffu, p0, off);
                p1 += __shfl_xor_sync(0xffffffffu, p1, off);
            }
            if (q == 0) {
                int r0 = m0 + g;
                atomicAdd(&S->phi[r0], p0);
                atomicAdd(&S->phi[r0 + 8], p1);
            }
        }
        __syncthreads();

        if (tid < TE && start + tid < cnt) {
            int key = S->ekey[start + tid];
            int jl = key >> 6, k = key & 63;
            int j = jt * TJ + jl;
            float p = S->phi[tid];
            atomicAdd(&S->xup[jl][0], (S->xk[j * 3 + 0] - S->xk[k * 3 + 0]) * p);
            atomicAdd(&S->xup[jl][1], (S->xk[j * 3 + 1] - S->xk[k * 3 + 1]) * p);
            atomicAdd(&S->xup[jl][2], (S->xk[j * 3 + 2] - S->xk[k * 3 + 2]) * p);
        }
        __syncthreads();
    }

    for (int i = tid; i < TJ * HH; i += NTHREADS)
        g_mi[(b * NNODE + jt * TJ) * HH + i] = S->mi[i];
    if (tid < TJ * 3) {
        int jl = tid / 3, c = tid % 3;
        int j = jt * TJ + jl;
        float v = S->xk[j * 3 + c] + (1.f / 63.f) * S->xup[jl][c];
        v = fminf(fmaxf(v, -1000.f), 1000.f);
        xout[(b * NNODE + j) * 3 + c] = v;
    }
}

// ============================================================
// Kernel 3: node MLP via tf32 mma (identical to R11 passing).
// ============================================================
#define NSTR 388
#define USTR 132
#define NWSTR 136

struct NodeSmem {
    float nf[32 * NSTR];
    float wb[128 * NWSTR];
    float u [32 * USTR];
    float bn1s[HH], bn2s[HH];
};

__global__ __launch_bounds__(256, 1) void node_kernel(
    const float* __restrict__ h,
    const float* __restrict__ h0,
    const float* __restrict__ Wn1,
    const float* __restrict__ bn1,
    const float* __restrict__ Wn2,
    const float* __restrict__ bn2,
    float* __restrict__ hout)
{
    extern __shared__ char smem_raw[];
    NodeSmem* S = (NodeSmem*)smem_raw;
    int tid = threadIdx.x;
    int wid = tid >> 5, lane = tid & 31;
    int base = blockIdx.x * 32;

    for (int i = tid; i < 32 * 384; i += 256) {
        int n = i / 384, k = i % 384;
        float v;
        if (k < 128)      v = h   [(base + n) * HH + k];
        else if (k < 256) v = g_mi[(base + n) * HH + k - 128];
        else              v = h0  [(base + n) * HH + k - 256];
        S->nf[n * NSTR + k] = to_tf32(v);
    }
    if (tid < HH) {
        S->bn1s[tid] = bn1[tid];
        S->bn2s[tid] = bn2[tid];
    }

    const int g = lane >> 2, q = lane & 3;
    const int m0 = (wid >> 2) * 16;
    const int n0 = (wid & 3) * 32;

    float acc[4][4];
#pragma unroll
    for (int nt = 0; nt < 4; nt++)
#pragma unroll
        for (int c = 0; c < 4; c++) acc[nt][c] = 0.f;

    for (int ks = 0; ks < 384; ks += 128) {
        __syncthreads();
        for (int i = tid; i < 128 * HH; i += 256) {
            int kk = i >> 7, n = i & 127;
            S->wb[kk * NWSTR + n] = to_tf32(Wn1[(ks + kk) * HH + n]);
        }
        __syncthreads();
#pragma unroll
        for (int kt = 0; kt < 16; kt++) {
            int k0 = kt * 8;
            uint32_t a0 = __float_as_uint(S->nf[(m0 + g)     * NSTR + ks + k0 + q]);
            uint32_t a1 = __float_as_uint(S->nf[(m0 + g + 8) * NSTR + ks + k0 + q]);
            uint32_t a2 = __float_as_uint(S->nf[(m0 + g)     * NSTR + ks + k0 + 4 + q]);
            uint32_t a3 = __float_as_uint(S->nf[(m0 + g + 8) * NSTR + ks + k0 + 4 + q]);
#pragma unroll
            for (int nt = 0; nt < 4; nt++) {
                uint32_t b0 = __float_as_uint(S->wb[(k0 + q)     * NWSTR + n0 + nt * 8 + g]);
                uint32_t b1 = __float_as_uint(S->wb[(k0 + 4 + q) * NWSTR + n0 + nt * 8 + g]);
                mma_tf32(acc[nt], a0, a1, a2, a3, b0, b1);
            }
        }
    }
    {
        int r0 = m0 + g;
#pragma unroll
        for (int nt = 0; nt < 4; nt++) {
            int col = n0 + nt * 8 + q * 2;
            float b0 = S->bn1s[col], b1 = S->bn1s[col + 1];
            float2 top, bot;
            top.x = to_tf32(silu(acc[nt][0] + b0));
            top.y = to_tf32(silu(acc[nt][1] + b1));
            bot.x = to_tf32(silu(acc[nt][2] + b0));
            bot.y = to_tf32(silu(acc[nt][3] + b1));
            *(float2*)&S->u[r0 * USTR + col] = top;
            *(float2*)&S->u[(r0 + 8) * USTR + col] = bot;
        }
    }
    __syncthreads();

    for (int i = tid; i < HH * HH; i += 256) {
        int kk = i >> 7, n = i & 127;
        S->wb[kk * NWSTR + n] = to_tf32(Wn2[kk * HH + n]);
    }
    __syncthreads();

#pragma unroll
    for (int nt = 0; nt < 4; nt++)
#pragma unroll
        for (int c = 0; c < 4; c++) acc[nt][c] = 0.f;

#pragma unroll
    for (int kt = 0; kt < 16; kt++) {
        int k0 = kt * 8;
        uint32_t a0 = __float_as_uint(S->u[(m0 + g)     * USTR + k0 + q]);
        uint32_t a1 = __float_as_uint(S->u[(m0 + g + 8) * USTR + k0 + q]);
        uint32_t a2 = __float_as_uint(S->u[(m0 + g)     * USTR + k0 + 4 + q]);
        uint32_t a3 = __float_as_uint(S->u[(m0 + g + 8) * USTR + k0 + 4 + q]);
#pragma unroll
        for (int nt = 0; nt < 4; nt++) {
            uint32_t b0 = __float_as_uint(S->wb[(k0 + q)     * NWSTR + n0 + nt * 8 + g]);
            uint32_t b1 = __float_as_uint(S->wb[(k0 + 4 + q) * NWSTR + n0 + nt * 8 + g]);
            mma_tf32(acc[nt], a0, a1, a2, a3, b0, b1);
        }
    }

    {
        int r0 = m0 + g;
#pragma unroll
        for (int nt = 0; nt < 4; nt++) {
            int col = n0 + nt * 8 + q * 2;
            float b0 = S->bn2s[col], b1 = S->bn2s[col + 1];
            float2 h_t = *(const float2*)&h[(base + r0) * HH + col];
            float2 h_b = *(const float2*)&h[(base + r0 + 8) * HH + col];
            float2 top, bot;
            top.x = acc[nt][0] + b0 + h_t.x;
            top.y = acc[nt][1] + b1 + h_t.y;
            bot.x = acc[nt][2] + b0 + h_b.x;
            bot.y = acc[nt][3] + b1 + h_b.y;
            *(float2*)&hout[(base + r0) * HH + col] = top;
            *(float2*)&hout[(base + r0 + 8) * HH + col] = bot;
        }
    }
}

// ============================================================
extern "C" void kernel_launch(void* const* d_in, const int* in_sizes, int n_in,
                              void* d_out, int out_size)
{
    (void)in_sizes; (void)n_in; (void)out_size;
    const float* h   = (const float*)d_in[0];
    const float* x   = (const float*)d_in[1];
    const float* h0  = (const float*)d_in[3];
    const float* We1 = (const float*)d_in[4];
    const float* be1 = (const float*)d_in[5];
    const float* We2 = (const float*)d_in[6];
    const float* be2 = (const float*)d_in[7];
    const float* Wn1 = (const float*)d_in[8];
    const float* bn1 = (const float*)d_in[9];
    const float* Wn2 = (const float*)d_in[10];
    const float* bn2 = (const float*)d_in[11];
    const float* Wc1 = (const float*)d_in[12];
    const float* bc1 = (const float*)d_in[13];
    const float* Wc2 = (const float*)d_in[14];

    float* out  = (float*)d_out;
    float* hout = out;
    float* xout = out + BB * NNODE * HH;

    cudaFuncSetAttribute(edge_kernel, cudaFuncAttributeMaxDynamicSharedMemorySize,
                         (int)sizeof(EdgeSmem));
    cudaFuncSetAttribute(node_kernel, cudaFuncAttributeMaxDynamicSharedMemorySize,
                         (int)sizeof(NodeSmem));

    dim3 pgrid(BB * NNODE / 32, 2);
    prep_kernel<<<pgrid, 256>>>(h, We1, be1);

    dim3 egrid(NNODE / TJ, BB);
    edge_kernel<<<egrid, NTHREADS, sizeof(EdgeSmem)>>>(
        x, We1, We2, be2, Wc1, bc1, Wc2, xout);

    node_kernel<<<BB * NNODE / 32, 256, sizeof(NodeSmem)>>>(
        h, h0, Wn1, bn1, Wn2, bn2, hout);
}

// round 13
// speedup vs baseline: 4.1283x; 1.0066x over previous
#include <cuda_runtime.h>
#include <cstdint>

#define BB 64
#define NNODE 64
#define HH 128
#define TJ 32          // receiver nodes per block
#define TE 128         // edges per MMA tile
#define NTHREADS 512
#define ASTRIDE 132    // activation smem row stride (floats)
#define WSTRIDE 136    // weight smem row stride (floats)

// ---- device scratch ----
__device__ float g_A [BB * NNODE * HH];
__device__ float g_Bm[BB * NNODE * HH];
__device__ float g_mi[BB * NNODE * HH];

__device__ __forceinline__ float silu(float z) {
    float t;
    asm("tanh.approx.f32 %0, %1;" : "=f"(t) : "f"(z * 0.5f));
    return 0.5f * z * (1.f + t);
}
__device__ __forceinline__ float to_tf32(float x) {
    uint32_t r;
    asm("cvt.rna.tf32.f32 %0, %1;" : "=r"(r) : "f"(x));
    return __uint_as_float(r);
}
__device__ __forceinline__ void split_tf32(float v, uint32_t& hi, uint32_t& lo) {
    float h = to_tf32(v);
    float l = to_tf32(v - h);
    hi = __float_as_uint(h);
    lo = __float_as_uint(l);
}

__device__ __forceinline__ void mma_tf32(float* c,
    uint32_t a0, uint32_t a1, uint32_t a2, uint32_t a3,
    uint32_t b0, uint32_t b1)
{
    asm volatile(
        "mma.sync.aligned.m16n8k8.row.col.f32.tf32.tf32.f32 "
        "{%0,%1,%2,%3}, {%4,%5,%6,%7}, {%8,%9}, {%0,%1,%2,%3};"
        : "+f"(c[0]), "+f"(c[1]), "+f"(c[2]), "+f"(c[3])
        : "r"(a0), "r"(a1), "r"(a2), "r"(a3), "r"(b0), "r"(b1));
}

// ============================================================
// Kernel 1: prep via split-tf32 MMA (fp32-class accuracy).
// grid (32 node-groups of 128, 2 halves), 256 threads, 8 warps.
// Warp tile: 64 rows x 32 cols (mt=4, nt=4).
// ============================================================
struct PrepSmem {
    float hs[128 * 132];   // h rows fp32
    float W [128 * 136];   // We1 half [k][n] fp32
    float bias[HH];
};

__global__ __launch_bounds__(256) void prep_kernel(
    const float* __restrict__ h,
    const float* __restrict__ We1,
    const float* __restrict__ be1)
{
    extern __shared__ char psmem_raw[];
    PrepSmem* S = (PrepSmem*)psmem_raw;
    int tid = threadIdx.x;
    int wid = tid >> 5, lane = tid & 31;
    int base = blockIdx.x * 128;
    int half = blockIdx.y;
    const float* Wsrc = We1 + (size_t)half * HH * HH;

    for (int i = tid; i < 128 * HH; i += 256) {
        S->hs[(i >> 7) * 132 + (i & 127)] = h[base * HH + i];
        S->W [(i >> 7) * 136 + (i & 127)] = Wsrc[i];
    }
    if (tid < HH) S->bias[tid] = half ? 0.f : be1[tid];
    __syncthreads();

    const int g = lane >> 2, q = lane & 3;
    const int m0 = (wid >> 2) * 64;      // 2 m-groups of 64 rows
    const int n0 = (wid & 3) * 32;       // 4 n-groups of 32 cols

    float acc[4][4][4];
#pragma unroll
    for (int mt = 0; mt < 4; mt++)
#pragma unroll
        for (int nt = 0; nt < 4; nt++)
#pragma unroll
            for (int c = 0; c < 4; c++) acc[mt][nt][c] = 0.f;

#pragma unroll 4
    for (int kt = 0; kt < 16; kt++) {
        int k0 = kt * 8;
        uint32_t ahi[4][4], alo[4][4];
#pragma unroll
        for (int mt = 0; mt < 4; mt++) {
            int rb = m0 + mt * 16;
            split_tf32(S->hs[(rb + g)     * 132 + k0 + q],     ahi[mt][0], alo[mt][0]);
            split_tf32(S->hs[(rb + g + 8) * 132 + k0 + q],     ahi[mt][1], alo[mt][1]);
            split_tf32(S->hs[(rb + g)     * 132 + k0 + 4 + q], ahi[mt][2], alo[mt][2]);
            split_tf32(S->hs[(rb + g + 8) * 132 + k0 + 4 + q], ahi[mt][3], alo[mt][3]);
        }
#pragma unroll
        for (int nt = 0; nt < 4; nt++) {
            uint32_t bh0, bl0, bh1, bl1;
            split_tf32(S->W[(k0 + q)     * 136 + n0 + nt * 8 + g], bh0, bl0);
            split_tf32(S->W[(k0 + 4 + q) * 136 + n0 + nt * 8 + g], bh1, bl1);
#pragma unroll
            for (int mt = 0; mt < 4; mt++) {
                mma_tf32(acc[mt][nt], ahi[mt][0], ahi[mt][1], ahi[mt][2], ahi[mt][3], bh0, bh1);
                mma_tf32(acc[mt][nt], ahi[mt][0], ahi[mt][1], ahi[mt][2], ahi[mt][3], bl0, bl1);
                mma_tf32(acc[mt][nt], alo[mt][0], alo[mt][1], alo[mt][2], alo[mt][3], bh0, bh1);
            }
        }
    }

    float* outp = half ? g_Bm : g_A;
#pragma unroll
    for (int mt = 0; mt < 4; mt++) {
        int r0 = m0 + mt * 16 + g;
#pragma unroll
        for (int nt = 0; nt < 4; nt++) {
            int col = n0 + nt * 8 + q * 2;
            float b0 = S->bias[col], b1 = S->bias[col + 1];
            float2 top, bot;
            top.x = acc[mt][nt][0] + b0; top.y = acc[mt][nt][1] + b1;
            bot.x = acc[mt][nt][2] + b0; bot.y = acc[mt][nt][3] + b1;
            *(float2*)&outp[(size_t)(base + r0) * HH + col] = top;
            *(float2*)&outp[(size_t)(base + r0 + 8) * HH + col] = bot;
        }
    }
}

// ============================================================
// Kernel 2: mma.sync tf32 edge kernel. Block = (b, 32 j). 512 thr.
// Warp tile retiled to 32 rows x 32 cols (mt=2, nt=4).
// ============================================================
#define ELIST 2176

struct EdgeSmem {
    float As[TE * ASTRIDE];
    float W1[HH * WSTRIDE];
    float W2[HH * WSTRIDE];
    float mi[TJ * HH];
    float phi[TE];
    unsigned short ekey[ELIST];
    float xk[NNODE * 3];
    float be2s[HH], bc1s[HH], wc2s[HH], wds[HH];
    int jstart[33];
    union {
        struct { int wcnt[64]; int wexc[64]; } c;
        float d2t[TE];
    } u;
    float xup[TJ][3];
    int cnt;
};

__global__ __launch_bounds__(NTHREADS, 1) void edge_kernel(
    const float* __restrict__ x,
    const float* __restrict__ We1,
    const float* __restrict__ We2,
    const float* __restrict__ be2,
    const float* __restrict__ Wc1,
    const float* __restrict__ bc1,
    const float* __restrict__ Wc2,
    float* __restrict__ xout)
{
    extern __shared__ char smem_raw[];
    EdgeSmem* S = (EdgeSmem*)smem_raw;
    int tid = threadIdx.x;
    int wid = tid >> 5, lane = tid & 31;
    int jt = blockIdx.x;
    int b  = blockIdx.y;

    for (int i = tid; i < HH * HH; i += NTHREADS) {
        int k = i >> 7, n = i & 127;
        S->W1[k * WSTRIDE + n] = to_tf32(We2[i]);
        S->W2[k * WSTRIDE + n] = to_tf32(Wc1[i]);
    }
    for (int i = tid; i < TJ * HH; i += NTHREADS) S->mi[i] = 0.f;
    if (tid < NNODE * 3) S->xk[tid] = x[b * NNODE * 3 + tid];
    if (tid < HH) {
        S->be2s[tid] = be2[tid];
        S->bc1s[tid] = bc1[tid];
        S->wc2s[tid] = Wc2[tid];
        S->wds [tid] = We1[2 * HH * HH + tid];
    }
    if (tid < TJ * 3) S->xup[tid / 3][tid % 3] = 0.f;
    __syncthreads();

#pragma unroll
    for (int p = 0; p < 4; p++) {
        int pid = p * 512 + tid;
        int jl = pid >> 6, k = pid & 63;
        int j = jt * TJ + jl;
        float dx = S->xk[j * 3 + 0] - S->xk[k * 3 + 0];
        float dy = S->xk[j * 3 + 1] - S->xk[k * 3 + 1];
        float dz = S->xk[j * 3 + 2] - S->xk[k * 3 + 2];
        float d2 = dx * dx + dy * dy + dz * dz;
        bool act = (k != j) && (d2 < 25.f);
        unsigned ball = __ballot_sync(0xffffffffu, act);
        if (lane == 0) S->u.c.wcnt[p * 16 + wid] = __popc(ball);
    }
    __syncthreads();
    if (tid == 0) {
        int run = 0;
        for (int i = 0; i < 64; i++) { S->u.c.wexc[i] = run; run += S->u.c.wcnt[i]; }
        S->cnt = run;
    }
    __syncthreads();
#pragma unroll
    for (int p = 0; p < 4; p++) {
        int pid = p * 512 + tid;
        int jl = pid >> 6, k = pid & 63;
        int j = jt * TJ + jl;
        float dx = S->xk[j * 3 + 0] - S->xk[k * 3 + 0];
        float dy = S->xk[j * 3 + 1] - S->xk[k * 3 + 1];
        float dz = S->xk[j * 3 + 2] - S->xk[k * 3 + 2];
        float d2 = dx * dx + dy * dy + dz * dz;
        bool act = (k != j) && (d2 < 25.f);
        unsigned ball = __ballot_sync(0xffffffffu, act);
        if (act) {
            int pos = S->u.c.wexc[p * 16 + wid] + __popc(ball & ((1u << lane) - 1u));
            S->ekey[pos] = (unsigned short)((jl << 6) | k);
        }
    }
    __syncthreads();
    const int cnt = S->cnt;
    if (tid < TE) S->ekey[cnt + tid] = 0;
    if (tid < 33) {
        int target = tid << 6;
        int lo = 0, hi = cnt;
        while (lo < hi) {
            int mid = (lo + hi) >> 1;
            if ((int)S->ekey[mid] < target) lo = mid + 1; else hi = mid;
        }
        S->jstart[tid] = lo;
    }
    __syncthreads();

    const float4* gA4  = (const float4*)g_A  + (size_t)b * NNODE * 32;
    const float4* gBm4 = (const float4*)g_Bm + (size_t)b * NNODE * 32;

    const int g = lane >> 2, q = lane & 3;
    const int m0 = (wid >> 2) * 32;      // 4 m-groups of 32 rows
    const int n0 = (wid & 3) * 32;       // 4 n-groups of 32 cols
    int ntiles = (cnt + TE - 1) / TE;

    for (int ti = 0; ti < ntiles; ti++) {
        int start = ti * TE;

        if (tid < TE) {
            S->phi[tid] = 0.f;
            int key = S->ekey[start + tid];
            int jl = key >> 6, k = key & 63;
            int j = jt * TJ + jl;
            float dx = S->xk[j * 3 + 0] - S->xk[k * 3 + 0];
            float dy = S->xk[j * 3 + 1] - S->xk[k * 3 + 1];
            float dz = S->xk[j * 3 + 2] - S->xk[k * 3 + 2];
            S->u.d2t[tid] = dx * dx + dy * dy + dz * dz;
        }
        __syncthreads();

        for (int idx = tid; idx < TE * 32; idx += NTHREADS) {
            int e = idx >> 5, h4 = idx & 31;
            int key = S->ekey[start + e];
            int jl = key >> 6, k = key & 63;
            int j = jt * TJ + jl;
            float d2 = S->u.d2t[e];
            float4 av = __ldg(&gA4[j * 32 + h4]);
            float4 bv = __ldg(&gBm4[k * 32 + h4]);
            float4 wv = ((const float4*)S->wds)[h4];
            float4 tv;
            tv.x = to_tf32(silu(av.x + bv.x + d2 * wv.x));
            tv.y = to_tf32(silu(av.y + bv.y + d2 * wv.y));
            tv.z = to_tf32(silu(av.z + bv.z + d2 * wv.z));
            tv.w = to_tf32(silu(av.w + bv.w + d2 * wv.w));
            *(float4*)&S->As[e * ASTRIDE + h4 * 4] = tv;
        }
        __syncthreads();

        // ---- GEMM1: z = A @ We2 ----
        float acc[2][4][4];
#pragma unroll
        for (int mt = 0; mt < 2; mt++)
#pragma unroll
            for (int nt = 0; nt < 4; nt++)
#pragma unroll
                for (int c = 0; c < 4; c++) acc[mt][nt][c] = 0.f;

#pragma unroll
        for (int kt = 0; kt < 16; kt++) {
            int k0 = kt * 8;
            uint32_t a[2][4];
#pragma unroll
            for (int mt = 0; mt < 2; mt++) {
                int rb = m0 + mt * 16;
                a[mt][0] = __float_as_uint(S->As[(rb + g)     * ASTRIDE + k0 + q]);
                a[mt][1] = __float_as_uint(S->As[(rb + g + 8) * ASTRIDE + k0 + q]);
                a[mt][2] = __float_as_uint(S->As[(rb + g)     * ASTRIDE + k0 + 4 + q]);
                a[mt][3] = __float_as_uint(S->As[(rb + g + 8) * ASTRIDE + k0 + 4 + q]);
            }
#pragma unroll
            for (int nt = 0; nt < 4; nt++) {
                uint32_t b0 = __float_as_uint(S->W1[(k0 + q)     * WSTRIDE + n0 + nt * 8 + g]);
                uint32_t b1 = __float_as_uint(S->W1[(k0 + 4 + q) * WSTRIDE + n0 + nt * 8 + g]);
                mma_tf32(acc[0][nt], a[0][0], a[0][1], a[0][2], a[0][3], b0, b1);
                mma_tf32(acc[1][nt], a[1][0], a[1][1], a[1][2], a[1][3], b0, b1);
            }
        }
        __syncthreads();

        // ---- epilogue 1 ----
#pragma unroll
        for (int mt = 0; mt < 2; mt++) {
            int r0 = m0 + mt * 16 + g;
            float d2a = S->u.d2t[r0];
            float d2b = S->u.d2t[r0 + 8];
            float cut0 = 1.f - 0.06f * d2a + 0.004f * d2a * sqrtf(d2a);
            float cut1 = 1.f - 0.06f * d2b + 0.004f * d2b * sqrtf(d2b);
#pragma unroll
            for (int nt = 0; nt < 4; nt++) {
                int col = n0 + nt * 8 + q * 2;
                float be0 = S->be2s[col], be1v = S->be2s[col + 1];
                float2 top, bot;
                top.x = to_tf32(silu(acc[mt][nt][0] + be0)  * cut0);
                top.y = to_tf32(silu(acc[mt][nt][1] + be1v) * cut0);
                bot.x = to_tf32(silu(acc[mt][nt][2] + be0)  * cut1);
                bot.y = to_tf32(silu(acc[mt][nt][3] + be1v) * cut1);
                *(float2*)&S->As[r0 * ASTRIDE + col] = top;
                *(float2*)&S->As[(r0 + 8) * ASTRIDE + col] = bot;
            }
        }
        __syncthreads();

        // ---- mi accumulation ----
        {
            int jl = tid >> 4, cg = tid & 15;
            int lo = max(S->jstart[jl], start);
            int hi = min(S->jstart[jl + 1], start + TE);
            if (lo < hi) {
                float4 s0 = make_float4(0, 0, 0, 0), s1 = s0;
                for (int e = lo; e < hi; e++) {
                    const float4* rp = (const float4*)&S->As[(e - start) * ASTRIDE + cg * 8];
                    float4 v0 = rp[0], v1 = rp[1];
                    s0.x += v0.x; s0.y += v0.y; s0.z += v0.z; s0.w += v0.w;
                    s1.x += v1.x; s1.y += v1.y; s1.z += v1.z; s1.w += v1.w;
                }
                float4* mip = (float4*)&S->mi[jl * HH + cg * 8];
                float4 m0v = mip[0], m1v = mip[1];
                mip[0] = make_float4(m0v.x + s0.x, m0v.y + s0.y, m0v.z + s0.z, m0v.w + s0.w);
                mip[1] = make_float4(m1v.x + s1.x, m1v.y + s1.y, m1v.z + s1.z, m1v.w + s1.w);
            }
        }

        // ---- GEMM2: zc = mij @ Wc1 ----
#pragma unroll
        for (int mt = 0; mt < 2; mt++)
#pragma unroll
            for (int nt = 0; nt < 4; nt++)
#pragma unroll
                for (int c = 0; c < 4; c++) acc[mt][nt][c] = 0.f;

#pragma unroll
        for (int kt = 0; kt < 16; kt++) {
            int k0 = kt * 8;
            uint32_t a[2][4];
#pragma unroll
            for (int mt = 0; mt < 2; mt++) {
                int rb = m0 + mt * 16;
                a[mt][0] = __float_as_uint(S->As[(rb + g)     * ASTRIDE + k0 + q]);
                a[mt][1] = __float_as_uint(S->As[(rb + g + 8) * ASTRIDE + k0 + q]);
                a[mt][2] = __float_as_uint(S->As[(rb + g)     * ASTRIDE + k0 + 4 + q]);
                a[mt][3] = __float_as_uint(S->As[(rb + g + 8) * ASTRIDE + k0 + 4 + q]);
            }
#pragma unroll
            for (int nt = 0; nt < 4; nt++) {
                uint32_t b0 = __float_as_uint(S->W2[(k0 + q)     * WSTRIDE + n0 + nt * 8 + g]);
                uint32_t b1 = __float_as_uint(S->W2[(k0 + 4 + q) * WSTRIDE + n0 + nt * 8 + g]);
                mma_tf32(acc[0][nt], a[0][0], a[0][1], a[0][2], a[0][3], b0, b1);
                mma_tf32(acc[1][nt], a[1][0], a[1][1], a[1][2], a[1][3], b0, b1);
            }
        }

        // ---- epilogue 2: phi ----
#pragma unroll
        for (int mt = 0; mt < 2; mt++) {
            float p0 = 0.f, p1 = 0.f;
#pragma unroll
            for (int nt = 0; nt < 4; nt++) {
                int col = n0 + nt * 8 + q * 2;
                float bc0 = S->bc1s[col], bc1v = S->bc1s[col + 1];
                float wc0 = S->wc2s[col], wc1v = S->wc2s[col + 1];
                p0 += silu(acc[mt][nt][0] + bc0)  * wc0;
                p0 += silu(acc[mt][nt][1] + bc1v) * wc1v;
                p1 += silu(acc[mt][nt][2] + bc0)  * wc0;
                p1 += silu(acc[mt][nt][3] + bc1v) * wc1v;
            }
#pragma unroll
            for (int off = 1; off < 4; off <<= 1) {
                p0 += __shfl_xor_sync(0xffffffffu, p0, off);
                p1 += __shfl_xor_sync(0xffffffffu, p1, off);
            }
            if (q == 0) {
                int r0 = m0 + mt * 16 + g;
                atomicAdd(&S->phi[r0], p0);
                atomicAdd(&S->phi[r0 + 8], p1);
            }
        }
        __syncthreads();

        if (tid < TE && start + tid < cnt) {
            int key = S->ekey[start + tid];
            int jl = key >> 6, k = key & 63;
            int j = jt * TJ + jl;
            float p = S->phi[tid];
            atomicAdd(&S->xup[jl][0], (S->xk[j * 3 + 0] - S->xk[k * 3 + 0]) * p);
            atomicAdd(&S->xup[jl][1], (S->xk[j * 3 + 1] - S->xk[k * 3 + 1]) * p);
            atomicAdd(&S->xup[jl][2], (S->xk[j * 3 + 2] - S->xk[k * 3 + 2]) * p);
        }
        __syncthreads();
    }

    for (int i = tid; i < TJ * HH; i += NTHREADS)
        g_mi[(b * NNODE + jt * TJ) * HH + i] = S->mi[i];
    if (tid < TJ * 3) {
        int jl = tid / 3, c = tid % 3;
        int j = jt * TJ + jl;
        float v = S->xk[j * 3 + c] + (1.f / 63.f) * S->xup[jl][c];
        v = fminf(fmaxf(v, -1000.f), 1000.f);
        xout[(b * NNODE + j) * 3 + c] = v;
    }
}

// ============================================================
// Kernel 3: node MLP via tf32 mma (identical to R12 passing).
// ============================================================
#define NSTR 388
#define USTR 132
#define NWSTR 136

struct NodeSmem {
    float nf[32 * NSTR];
    float wb[128 * NWSTR];
    float u [32 * USTR];
    float bn1s[HH], bn2s[HH];
};

__global__ __launch_bounds__(256, 1) void node_kernel(
    const float* __restrict__ h,
    const float* __restrict__ h0,
    const float* __restrict__ Wn1,
    const float* __restrict__ bn1,
    const float* __restrict__ Wn2,
    const float* __restrict__ bn2,
    float* __restrict__ hout)
{
    extern __shared__ char smem_raw[];
    NodeSmem* S = (NodeSmem*)smem_raw;
    int tid = threadIdx.x;
    int wid = tid >> 5, lane = tid & 31;
    int base = blockIdx.x * 32;

    for (int i = tid; i < 32 * 384; i += 256) {
        int n = i / 384, k = i % 384;
        float v;
        if (k < 128)      v = h   [(base + n) * HH + k];
        else if (k < 256) v = g_mi[(base + n) * HH + k - 128];
        else              v = h0  [(base + n) * HH + k - 256];
        S->nf[n * NSTR + k] = to_tf32(v);
    }
    if (tid < HH) {
        S->bn1s[tid] = bn1[tid];
        S->bn2s[tid] = bn2[tid];
    }

    const int g = lane >> 2, q = lane & 3;
    const int m0 = (wid >> 2) * 16;
    const int n0 = (wid & 3) * 32;

    float acc[4][4];
#pragma unroll
    for (int nt = 0; nt < 4; nt++)
#pragma unroll
        for (int c = 0; c < 4; c++) acc[nt][c] = 0.f;

    for (int ks = 0; ks < 384; ks += 128) {
        __syncthreads();
        for (int i = tid; i < 128 * HH; i += 256) {
            int kk = i >> 7, n = i & 127;
            S->wb[kk * NWSTR + n] = to_tf32(Wn1[(ks + kk) * HH + n]);
        }
        __syncthreads();
#pragma unroll
        for (int kt = 0; kt < 16; kt++) {
            int k0 = kt * 8;
            uint32_t a0 = __float_as_uint(S->nf[(m0 + g)     * NSTR + ks + k0 + q]);
            uint32_t a1 = __float_as_uint(S->nf[(m0 + g + 8) * NSTR + ks + k0 + q]);
            uint32_t a2 = __float_as_uint(S->nf[(m0 + g)     * NSTR + ks + k0 + 4 + q]);
            uint32_t a3 = __float_as_uint(S->nf[(m0 + g + 8) * NSTR + ks + k0 + 4 + q]);
#pragma unroll
            for (int nt = 0; nt < 4; nt++) {
                uint32_t b0 = __float_as_uint(S->wb[(k0 + q)     * NWSTR + n0 + nt * 8 + g]);
                uint32_t b1 = __float_as_uint(S->wb[(k0 + 4 + q) * NWSTR + n0 + nt * 8 + g]);
                mma_tf32(acc[nt], a0, a1, a2, a3, b0, b1);
            }
        }
    }
    {
        int r0 = m0 + g;
#pragma unroll
        for (int nt = 0; nt < 4; nt++) {
            int col = n0 + nt * 8 + q * 2;
            float b0 = S->bn1s[col], b1 = S->bn1s[col + 1];
            float2 top, bot;
            top.x = to_tf32(silu(acc[nt][0] + b0));
            top.y = to_tf32(silu(acc[nt][1] + b1));
            bot.x = to_tf32(silu(acc[nt][2] + b0));
            bot.y = to_tf32(silu(acc[nt][3] + b1));
            *(float2*)&S->u[r0 * USTR + col] = top;
            *(float2*)&S->u[(r0 + 8) * USTR + col] = bot;
        }
    }
    __syncthreads();

    for (int i = tid; i < HH * HH; i += 256) {
        int kk = i >> 7, n = i & 127;
        S->wb[kk * NWSTR + n] = to_tf32(Wn2[kk * HH + n]);
    }
    __syncthreads();

#pragma unroll
    for (int nt = 0; nt < 4; nt++)
#pragma unroll
        for (int c = 0; c < 4; c++) acc[nt][c] = 0.f;

#pragma unroll
    for (int kt = 0; kt < 16; kt++) {
        int k0 = kt * 8;
        uint32_t a0 = __float_as_uint(S->u[(m0 + g)     * USTR + k0 + q]);
        uint32_t a1 = __float_as_uint(S->u[(m0 + g + 8) * USTR + k0 + q]);
        uint32_t a2 = __float_as_uint(S->u[(m0 + g)     * USTR + k0 + 4 + q]);
        uint32_t a3 = __float_as_uint(S->u[(m0 + g + 8) * USTR + k0 + 4 + q]);
#pragma unroll
        for (int nt = 0; nt < 4; nt++) {
            uint32_t b0 = __float_as_uint(S->wb[(k0 + q)     * NWSTR + n0 + nt * 8 + g]);
            uint32_t b1 = __float_as_uint(S->wb[(k0 + 4 + q) * NWSTR + n0 + nt * 8 + g]);
            mma_tf32(acc[nt], a0, a1, a2, a3, b0, b1);
        }
    }

    {
        int r0 = m0 + g;
#pragma unroll
        for (int nt = 0; nt < 4; nt++) {
            int col = n0 + nt * 8 + q * 2;
            float b0 = S->bn2s[col], b1 = S->bn2s[col + 1];
            float2 h_t = *(const float2*)&h[(base + r0) * HH + col];
            float2 h_b = *(const float2*)&h[(base + r0 + 8) * HH + col];
            float2 top, bot;
            top.x = acc[nt][0] + b0 + h_t.x;
            top.y = acc[nt][1] + b1 + h_t.y;
            bot.x = acc[nt][2] + b0 + h_b.x;
            bot.y = acc[nt][3] + b1 + h_b.y;
            *(float2*)&hout[(base + r0) * HH + col] = top;
            *(float2*)&hout[(base + r0 + 8) * HH + col] = bot;
        }
    }
}

// ============================================================
extern "C" void kernel_launch(void* const* d_in, const int* in_sizes, int n_in,
                              void* d_out, int out_size)
{
    (void)in_sizes; (void)n_in; (void)out_size;
    const float* h   = (const float*)d_in[0];
    const float* x   = (const float*)d_in[1];
    const float* h0  = (const float*)d_in[3];
    const float* We1 = (const float*)d_in[4];
    const float* be1 = (const float*)d_in[5];
    const float* We2 = (const float*)d_in[6];
    const float* be2 = (const float*)d_in[7];
    const float* Wn1 = (const float*)d_in[8];
    const float* bn1 = (const float*)d_in[9];
    const float* Wn2 = (const float*)d_in[10];
    const float* bn2 = (const float*)d_in[11];
    const float* Wc1 = (const float*)d_in[12];
    const float* bc1 = (const float*)d_in[13];
    const float* Wc2 = (const float*)d_in[14];

    float* out  = (float*)d_out;
    float* hout = out;
    float* xout = out + BB * NNODE * HH;

    cudaFuncSetAttribute(prep_kernel, cudaFuncAttributeMaxDynamicSharedMemorySize,
                         (int)sizeof(PrepSmem));
    cudaFuncSetAttribute(edge_kernel, cudaFuncAttributeMaxDynamicSharedMemorySize,
                         (int)sizeof(EdgeSmem));
    cudaFuncSetAttribute(node_kernel, cudaFuncAttributeMaxDynamicSharedMemorySize,
                         (int)sizeof(NodeSmem));

    dim3 pgrid(BB * NNODE / 128, 2);
    prep_kernel<<<pgrid, 256, sizeof(PrepSmem)>>>(h, We1, be1);

    dim3 egrid(NNODE / TJ, BB);
    edge_kernel<<<egrid, NTHREADS, sizeof(EdgeSmem)>>>(
        x, We1, We2, be2, Wc1, bc1, Wc2, xout);

    node_kernel<<<BB * NNODE / 32, 256, sizeof(NodeSmem)>>>(
        h, h0, Wn1, bn1, Wn2, bn2, hout);
}

// round 14
// speedup vs baseline: 4.3821x; 1.0615x over previous
#include <cuda_runtime.h>
#include <cuda_fp16.h>
#include <cstdint>

#define BB 64
#define NNODE 64
#define HH 128
#define TJ 32
#define TE 128
#define NTHREADS 512
#define AH 136         // half stride per As row
#define AH2 68         // half2 (uint32) stride per As row

// ---- device scratch ----
__device__ float g_A [BB * NNODE * HH];
__device__ float g_Bm[BB * NNODE * HH];
__device__ float g_mi[BB * NNODE * HH];

__device__ __forceinline__ float silu(float z) {
    float t;
    asm("tanh.approx.f32 %0, %1;" : "=f"(t) : "f"(z * 0.5f));
    return 0.5f * z * (1.f + t);
}
__device__ __forceinline__ float to_tf32(float x) {
    uint32_t r;
    asm("cvt.rna.tf32.f32 %0, %1;" : "=r"(r) : "f"(x));
    return __uint_as_float(r);
}
__device__ __forceinline__ void split_tf32(float v, uint32_t& hi, uint32_t& lo) {
    float h = to_tf32(v);
    float l = to_tf32(v - h);
    hi = __float_as_uint(h);
    lo = __float_as_uint(l);
}
__device__ __forceinline__ uint32_t pack_h2(float a, float b) {
    __half2 p = __floats2half2_rn(a, b);
    return *(uint32_t*)&p;
}

__device__ __forceinline__ void mma_tf32(float* c,
    uint32_t a0, uint32_t a1, uint32_t a2, uint32_t a3,
    uint32_t b0, uint32_t b1)
{
    asm volatile(
        "mma.sync.aligned.m16n8k8.row.col.f32.tf32.tf32.f32 "
        "{%0,%1,%2,%3}, {%4,%5,%6,%7}, {%8,%9}, {%0,%1,%2,%3};"
        : "+f"(c[0]), "+f"(c[1]), "+f"(c[2]), "+f"(c[3])
        : "r"(a0), "r"(a1), "r"(a2), "r"(a3), "r"(b0), "r"(b1));
}
__device__ __forceinline__ void mma_f16(float* c,
    uint32_t a0, uint32_t a1, uint32_t a2, uint32_t a3,
    uint32_t b0, uint32_t b1)
{
    asm volatile(
        "mma.sync.aligned.m16n8k16.row.col.f32.f16.f16.f32 "
        "{%0,%1,%2,%3}, {%4,%5,%6,%7}, {%8,%9}, {%0,%1,%2,%3};"
        : "+f"(c[0]), "+f"(c[1]), "+f"(c[2]), "+f"(c[3])
        : "r"(a0), "r"(a1), "r"(a2), "r"(a3), "r"(b0), "r"(b1));
}

// ============================================================
// Kernel 1: prep via split-tf32 MMA. grid (64 groups, 2 halves),
// 256 threads, 8 warps = 2m x 4n (32x32 warp tile). 104 KB smem.
// ============================================================
struct PrepSmem {
    float hs[64 * 132];
    float W [128 * 136];
    float bias[HH];
};

__global__ __launch_bounds__(256) void prep_kernel(
    const float* __restrict__ h,
    const float* __restrict__ We1,
    const float* __restrict__ be1)
{
    extern __shared__ char psmem_raw[];
    PrepSmem* S = (PrepSmem*)psmem_raw;
    int tid = threadIdx.x;
    int wid = tid >> 5, lane = tid & 31;
    int base = blockIdx.x * 64;
    int half = blockIdx.y;
    const float* Wsrc = We1 + (size_t)half * HH * HH;

    for (int i = tid; i < 64 * HH; i += 256)
        S->hs[(i >> 7) * 132 + (i & 127)] = h[base * HH + i];
    for (int i = tid; i < 128 * HH; i += 256)
        S->W[(i >> 7) * 136 + (i & 127)] = Wsrc[i];
    if (tid < HH) S->bias[tid] = half ? 0.f : be1[tid];
    __syncthreads();

    const int g = lane >> 2, q = lane & 3;
    const int m0 = (wid >> 2) * 32;
    const int n0 = (wid & 3) * 32;

    float acc[2][4][4];
#pragma unroll
    for (int mt = 0; mt < 2; mt++)
#pragma unroll
        for (int nt = 0; nt < 4; nt++)
#pragma unroll
            for (int c = 0; c < 4; c++) acc[mt][nt][c] = 0.f;

#pragma unroll 4
    for (int kt = 0; kt < 16; kt++) {
        int k0 = kt * 8;
        uint32_t ahi[2][4], alo[2][4];
#pragma unroll
        for (int mt = 0; mt < 2; mt++) {
            int rb = m0 + mt * 16;
            split_tf32(S->hs[(rb + g)     * 132 + k0 + q],     ahi[mt][0], alo[mt][0]);
            split_tf32(S->hs[(rb + g + 8) * 132 + k0 + q],     ahi[mt][1], alo[mt][1]);
            split_tf32(S->hs[(rb + g)     * 132 + k0 + 4 + q], ahi[mt][2], alo[mt][2]);
            split_tf32(S->hs[(rb + g + 8) * 132 + k0 + 4 + q], ahi[mt][3], alo[mt][3]);
        }
#pragma unroll
        for (int nt = 0; nt < 4; nt++) {
            uint32_t bh0, bl0, bh1, bl1;
            split_tf32(S->W[(k0 + q)     * 136 + n0 + nt * 8 + g], bh0, bl0);
            split_tf32(S->W[(k0 + 4 + q) * 136 + n0 + nt * 8 + g], bh1, bl1);
#pragma unroll
            for (int mt = 0; mt < 2; mt++) {
                mma_tf32(acc[mt][nt], ahi[mt][0], ahi[mt][1], ahi[mt][2], ahi[mt][3], bh0, bh1);
                mma_tf32(acc[mt][nt], ahi[mt][0], ahi[mt][1], ahi[mt][2], ahi[mt][3], bl0, bl1);
                mma_tf32(acc[mt][nt], alo[mt][0], alo[mt][1], alo[mt][2], alo[mt][3], bh0, bh1);
            }
        }
    }

    float* outp = half ? g_Bm : g_A;
#pragma unroll
    for (int mt = 0; mt < 2; mt++) {
        int r0 = m0 + mt * 16 + g;
#pragma unroll
        for (int nt = 0; nt < 4; nt++) {
            int col = n0 + nt * 8 + q * 2;
            float b0 = S->bias[col], b1 = S->bias[col + 1];
            float2 top, bot;
            top.x = acc[mt][nt][0] + b0; top.y = acc[mt][nt][1] + b1;
            bot.x = acc[mt][nt][2] + b0; bot.y = acc[mt][nt][3] + b1;
            *(float2*)&outp[(size_t)(base + r0) * HH + col] = top;
            *(float2*)&outp[(size_t)(base + r0 + 8) * HH + col] = bot;
        }
    }
}

// ============================================================
// Kernel 2: fp16 mma edge kernel. Block = (b, 32 j). 512 thr.
// A/mij stored half [row][136]; weights half transposed [n][k].
// ============================================================
#define ELIST 2176

struct EdgeSmem {
    __half As[TE * AH];          // 34816 B
    __half W1[HH * AH];          // We2^T [n][k]
    __half W2[HH * AH];          // Wc1^T [n][k]
    float mi[TJ * HH];
    float phi[TE];
    unsigned short ekey[ELIST];
    float xk[NNODE * 3];
    float be2s[HH], bc1s[HH], wc2s[HH], wds[HH];
    int jstart[33];
    union {
        struct { int wcnt[64]; int wexc[64]; } c;
        float d2t[TE];
    } u;
    float xup[TJ][3];
    int cnt;
};

__global__ __launch_bounds__(NTHREADS, 1) void edge_kernel(
    const float* __restrict__ x,
    const float* __restrict__ We1,
    const float* __restrict__ We2,
    const float* __restrict__ be2,
    const float* __restrict__ Wc1,
    const float* __restrict__ bc1,
    const float* __restrict__ Wc2,
    float* __restrict__ xout)
{
    extern __shared__ char smem_raw[];
    EdgeSmem* S = (EdgeSmem*)smem_raw;
    int tid = threadIdx.x;
    int wid = tid >> 5, lane = tid & 31;
    int jt = blockIdx.x;
    int b  = blockIdx.y;

    // weights transposed: [n][k], sequential smem writes, strided L2 reads
    for (int i = tid; i < HH * HH; i += NTHREADS) {
        int n = i >> 7, k = i & 127;
        S->W1[n * AH + k] = __float2half_rn(__ldg(&We2[k * HH + n]));
        S->W2[n * AH + k] = __float2half_rn(__ldg(&Wc1[k * HH + n]));
    }
    for (int i = tid; i < TJ * HH; i += NTHREADS) S->mi[i] = 0.f;
    if (tid < NNODE * 3) S->xk[tid] = x[b * NNODE * 3 + tid];
    if (tid < HH) {
        S->be2s[tid] = be2[tid];
        S->bc1s[tid] = bc1[tid];
        S->wc2s[tid] = Wc2[tid];
        S->wds [tid] = We1[2 * HH * HH + tid];
    }
    if (tid < TJ * 3) S->xup[tid / 3][tid % 3] = 0.f;
    __syncthreads();

    // ---- compaction (unchanged) ----
#pragma unroll
    for (int p = 0; p < 4; p++) {
        int pid = p * 512 + tid;
        int jl = pid >> 6, k = pid & 63;
        int j = jt * TJ + jl;
        float dx = S->xk[j * 3 + 0] - S->xk[k * 3 + 0];
        float dy = S->xk[j * 3 + 1] - S->xk[k * 3 + 1];
        float dz = S->xk[j * 3 + 2] - S->xk[k * 3 + 2];
        float d2 = dx * dx + dy * dy + dz * dz;
        bool act = (k != j) && (d2 < 25.f);
        unsigned ball = __ballot_sync(0xffffffffu, act);
        if (lane == 0) S->u.c.wcnt[p * 16 + wid] = __popc(ball);
    }
    __syncthreads();
    if (tid == 0) {
        int run = 0;
        for (int i = 0; i < 64; i++) { S->u.c.wexc[i] = run; run += S->u.c.wcnt[i]; }
        S->cnt = run;
    }
    __syncthreads();
#pragma unroll
    for (int p = 0; p < 4; p++) {
        int pid = p * 512 + tid;
        int jl = pid >> 6, k = pid & 63;
        int j = jt * TJ + jl;
        float dx = S->xk[j * 3 + 0] - S->xk[k * 3 + 0];
        float dy = S->xk[j * 3 + 1] - S->xk[k * 3 + 1];
        float dz = S->xk[j * 3 + 2] - S->xk[k * 3 + 2];
        float d2 = dx * dx + dy * dy + dz * dz;
        bool act = (k != j) && (d2 < 25.f);
        unsigned ball = __ballot_sync(0xffffffffu, act);
        if (act) {
            int pos = S->u.c.wexc[p * 16 + wid] + __popc(ball & ((1u << lane) - 1u));
            S->ekey[pos] = (unsigned short)((jl << 6) | k);
        }
    }
    __syncthreads();
    const int cnt = S->cnt;
    if (tid < TE) S->ekey[cnt + tid] = 0;
    if (tid < 33) {
        int target = tid << 6;
        int lo = 0, hi = cnt;
        while (lo < hi) {
            int mid = (lo + hi) >> 1;
            if ((int)S->ekey[mid] < target) lo = mid + 1; else hi = mid;
        }
        S->jstart[tid] = lo;
    }
    __syncthreads();

    const float4* gA4  = (const float4*)g_A  + (size_t)b * NNODE * 32;
    const float4* gBm4 = (const float4*)g_Bm + (size_t)b * NNODE * 32;
    const uint32_t* As32 = (const uint32_t*)S->As;
    const uint32_t* W1u  = (const uint32_t*)S->W1;
    const uint32_t* W2u  = (const uint32_t*)S->W2;

    const int g = lane >> 2, q = lane & 3;
    const int m0 = (wid >> 2) * 32;      // 4 m-groups of 32 rows
    const int n0 = (wid & 3) * 32;       // 4 n-groups of 32 cols
    int ntiles = (cnt + TE - 1) / TE;

    for (int ti = 0; ti < ntiles; ti++) {
        int start = ti * TE;

        if (tid < TE) {
            S->phi[tid] = 0.f;
            int key = S->ekey[start + tid];
            int jl = key >> 6, k = key & 63;
            int j = jt * TJ + jl;
            float dx = S->xk[j * 3 + 0] - S->xk[k * 3 + 0];
            float dy = S->xk[j * 3 + 1] - S->xk[k * 3 + 1];
            float dz = S->xk[j * 3 + 2] - S->xk[k * 3 + 2];
            S->u.d2t[tid] = dx * dx + dy * dy + dz * dz;
        }
        __syncthreads();

        // ---- stage A = half(silu(A_j + Bm_k + d2*wd)) ----
        for (int idx = tid; idx < TE * 32; idx += NTHREADS) {
            int e = idx >> 5, h4 = idx & 31;
            int key = S->ekey[start + e];
            int jl = key >> 6, k = key & 63;
            int j = jt * TJ + jl;
            float d2 = S->u.d2t[e];
            float4 av = __ldg(&gA4[j * 32 + h4]);
            float4 bv = __ldg(&gBm4[k * 32 + h4]);
            float4 wv = ((const float4*)S->wds)[h4];
            float2 st;
            uint32_t p0 = pack_h2(silu(av.x + bv.x + d2 * wv.x),
                                  silu(av.y + bv.y + d2 * wv.y));
            uint32_t p1 = pack_h2(silu(av.z + bv.z + d2 * wv.z),
                                  silu(av.w + bv.w + d2 * wv.w));
            st.x = __uint_as_float(p0);
            st.y = __uint_as_float(p1);
            *(float2*)&S->As[e * AH + h4 * 4] = st;
        }
        __syncthreads();

        // ---- GEMM1: z = A @ We2 (fp16, k16) ----
        float acc[2][4][4];
#pragma unroll
        for (int mt = 0; mt < 2; mt++)
#pragma unroll
            for (int nt = 0; nt < 4; nt++)
#pragma unroll
                for (int c = 0; c < 4; c++) acc[mt][nt][c] = 0.f;

#pragma unroll
        for (int kt = 0; kt < 8; kt++) {
            int k2 = kt * 8;   // half2 units
            uint32_t a[2][4];
#pragma unroll
            for (int mt = 0; mt < 2; mt++) {
                int rb = m0 + mt * 16;
                a[mt][0] = As32[(rb + g)     * AH2 + k2 + q];
                a[mt][1] = As32[(rb + g + 8) * AH2 + k2 + q];
                a[mt][2] = As32[(rb + g)     * AH2 + k2 + 4 + q];
                a[mt][3] = As32[(rb + g + 8) * AH2 + k2 + 4 + q];
            }
#pragma unroll
            for (int nt = 0; nt < 4; nt++) {
                int nrow = n0 + nt * 8 + g;
                uint32_t b0 = W1u[nrow * AH2 + k2 + q];
                uint32_t b1 = W1u[nrow * AH2 + k2 + 4 + q];
                mma_f16(acc[0][nt], a[0][0], a[0][1], a[0][2], a[0][3], b0, b1);
                mma_f16(acc[1][nt], a[1][0], a[1][1], a[1][2], a[1][3], b0, b1);
            }
        }
        __syncthreads();

        // ---- epilogue 1: mij = half(silu(z + be2) * cut) -> As ----
#pragma unroll
        for (int mt = 0; mt < 2; mt++) {
            int r0 = m0 + mt * 16 + g;
            float d2a = S->u.d2t[r0];
            float d2b = S->u.d2t[r0 + 8];
            float cut0 = 1.f - 0.06f * d2a + 0.004f * d2a * sqrtf(d2a);
            float cut1 = 1.f - 0.06f * d2b + 0.004f * d2b * sqrtf(d2b);
#pragma unroll
            for (int nt = 0; nt < 4; nt++) {
                int col = n0 + nt * 8 + q * 2;
                float be0 = S->be2s[col], be1v = S->be2s[col + 1];
                ((uint32_t*)S->As)[r0 * AH2 + (col >> 1)] =
                    pack_h2(silu(acc[mt][nt][0] + be0)  * cut0,
                            silu(acc[mt][nt][1] + be1v) * cut0);
                ((uint32_t*)S->As)[(r0 + 8) * AH2 + (col >> 1)] =
                    pack_h2(silu(acc[mt][nt][2] + be0)  * cut1,
                            silu(acc[mt][nt][3] + be1v) * cut1);
            }
        }
        __syncthreads();

        // ---- mi accumulation (halves -> fp32) ----
        {
            int jl = tid >> 4, cg = tid & 15;
            int lo = max(S->jstart[jl], start);
            int hi = min(S->jstart[jl + 1], start + TE);
            if (lo < hi) {
                float s[8];
#pragma unroll
                for (int c = 0; c < 8; c++) s[c] = 0.f;
                for (int e = lo; e < hi; e++) {
                    float4 raw = *(const float4*)&S->As[(e - start) * AH + cg * 8];
                    float2 f0 = __half22float2(*(__half2*)&raw.x);
                    float2 f1 = __half22float2(*(__half2*)&raw.y);
                    float2 f2 = __half22float2(*(__half2*)&raw.z);
                    float2 f3 = __half22float2(*(__half2*)&raw.w);
                    s[0] += f0.x; s[1] += f0.y; s[2] += f1.x; s[3] += f1.y;
                    s[4] += f2.x; s[5] += f2.y; s[6] += f3.x; s[7] += f3.y;
                }
                float* mip = &S->mi[jl * HH + cg * 8];
#pragma unroll
                for (int c = 0; c < 8; c++) mip[c] += s[c];
            }
        }

        // ---- GEMM2: zc = mij @ Wc1 (fp16) ----
#pragma unroll
        for (int mt = 0; mt < 2; mt++)
#pragma unroll
            for (int nt = 0; nt < 4; nt++)
#pragma unroll
                for (int c = 0; c < 4; c++) acc[mt][nt][c] = 0.f;

#pragma unroll
        for (int kt = 0; kt < 8; kt++) {
            int k2 = kt * 8;
            uint32_t a[2][4];
#pragma unroll
            for (int mt = 0; mt < 2; mt++) {
                int rb = m0 + mt * 16;
                a[mt][0] = As32[(rb + g)     * AH2 + k2 + q];
                a[mt][1] = As32[(rb + g + 8) * AH2 + k2 + q];
                a[mt][2] = As32[(rb + g)     * AH2 + k2 + 4 + q];
                a[mt][3] = As32[(rb + g + 8) * AH2 + k2 + 4 + q];
            }
#pragma unroll
            for (int nt = 0; nt < 4; nt++) {
                int nrow = n0 + nt * 8 + g;
                uint32_t b0 = W2u[nrow * AH2 + k2 + q];
                uint32_t b1 = W2u[nrow * AH2 + k2 + 4 + q];
                mma_f16(acc[0][nt], a[0][0], a[0][1], a[0][2], a[0][3], b0, b1);
                mma_f16(acc[1][nt], a[1][0], a[1][1], a[1][2], a[1][3], b0, b1);
            }
        }

        // ---- epilogue 2: phi ----
#pragma unroll
        for (int mt = 0; mt < 2; mt++) {
            float p0 = 0.f, p1 = 0.f;
#pragma unroll
            for (int nt = 0; nt < 4; nt++) {
                int col = n0 + nt * 8 + q * 2;
                float bc0 = S->bc1s[col], bc1v = S->bc1s[col + 1];
                float wc0 = S->wc2s[col], wc1v = S->wc2s[col + 1];
                p0 += silu(acc[mt][nt][0] + bc0)  * wc0;
                p0 += silu(acc[mt][nt][1] + bc1v) * wc1v;
                p1 += silu(acc[mt][nt][2] + bc0)  * wc0;
                p1 += silu(acc[mt][nt][3] + bc1v) * wc1v;
            }
#pragma unroll
            for (int off = 1; off < 4; off <<= 1) {
                p0 += __shfl_xor_sync(0xffffffffu, p0, off);
                p1 += __shfl_xor_sync(0xffffffffu, p1, off);
            }
            if (q == 0) {
                int r0 = m0 + mt * 16 + g;
                atomicAdd(&S->phi[r0], p0);
                atomicAdd(&S->phi[r0 + 8], p1);
            }
        }
        __syncthreads();

        if (tid < TE && start + tid < cnt) {
            int key = S->ekey[start + tid];
            int jl = key >> 6, k = key & 63;
            int j = jt * TJ + jl;
            float p = S->phi[tid];
            atomicAdd(&S->xup[jl][0], (S->xk[j * 3 + 0] - S->xk[k * 3 + 0]) * p);
            atomicAdd(&S->xup[jl][1], (S->xk[j * 3 + 1] - S->xk[k * 3 + 1]) * p);
            atomicAdd(&S->xup[jl][2], (S->xk[j * 3 + 2] - S->xk[k * 3 + 2]) * p);
        }
        __syncthreads();
    }

    for (int i = tid; i < TJ * HH; i += NTHREADS)
        g_mi[(b * NNODE + jt * TJ) * HH + i] = S->mi[i];
    if (tid < TJ * 3) {
        int jl = tid / 3, c = tid % 3;
        int j = jt * TJ + jl;
        float v = S->xk[j * 3 + c] + (1.f / 63.f) * S->xup[jl][c];
        v = fminf(fmaxf(v, -1000.f), 1000.f);
        xout[(b * NNODE + j) * 3 + c] = v;
    }
}

// ============================================================
// Kernel 3: node MLP via tf32 mma (identical to R13 passing).
// ============================================================
#define NSTR 388
#define USTR 132
#define NWSTR 136

struct NodeSmem {
    float nf[32 * NSTR];
    float wb[128 * NWSTR];
    float u [32 * USTR];
    float bn1s[HH], bn2s[HH];
};

__global__ __launch_bounds__(256, 1) void node_kernel(
    const float* __restrict__ h,
    const float* __restrict__ h0,
    const float* __restrict__ Wn1,
    const float* __restrict__ bn1,
    const float* __restrict__ Wn2,
    const float* __restrict__ bn2,
    float* __restrict__ hout)
{
    extern __shared__ char smem_raw[];
    NodeSmem* S = (NodeSmem*)smem_raw;
    int tid = threadIdx.x;
    int wid = tid >> 5, lane = tid & 31;
    int base = blockIdx.x * 32;

    for (int i = tid; i < 32 * 384; i += 256) {
        int n = i / 384, k = i % 384;
        float v;
        if (k < 128)      v = h   [(base + n) * HH + k];
        else if (k < 256) v = g_mi[(base + n) * HH + k - 128];
        else              v = h0  [(base + n) * HH + k - 256];
        S->nf[n * NSTR + k] = to_tf32(v);
    }
    if (tid < HH) {
        S->bn1s[tid] = bn1[tid];
        S->bn2s[tid] = bn2[tid];
    }

    const int g = lane >> 2, q = lane & 3;
    const int m0 = (wid >> 2) * 16;
    const int n0 = (wid & 3) * 32;

    float acc[4][4];
#pragma unroll
    for (int nt = 0; nt < 4; nt++)
#pragma unroll
        for (int c = 0; c < 4; c++) acc[nt][c] = 0.f;

    for (int ks = 0; ks < 384; ks += 128) {
        __syncthreads();
        for (int i = tid; i < 128 * HH; i += 256) {
            int kk = i >> 7, n = i & 127;
            S->wb[kk * NWSTR + n] = to_tf32(Wn1[(ks + kk) * HH + n]);
        }
        __syncthreads();
#pragma unroll
        for (int kt = 0; kt < 16; kt++) {
            int k0 = kt * 8;
            uint32_t a0 = __float_as_uint(S->nf[(m0 + g)     * NSTR + ks + k0 + q]);
            uint32_t a1 = __float_as_uint(S->nf[(m0 + g + 8) * NSTR + ks + k0 + q]);
            uint32_t a2 = __float_as_uint(S->nf[(m0 + g)     * NSTR + ks + k0 + 4 + q]);
            uint32_t a3 = __float_as_uint(S->nf[(m0 + g + 8) * NSTR + ks + k0 + 4 + q]);
#pragma unroll
            for (int nt = 0; nt < 4; nt++) {
                uint32_t b0 = __float_as_uint(S->wb[(k0 + q)     * NWSTR + n0 + nt * 8 + g]);
                uint32_t b1 = __float_as_uint(S->wb[(k0 + 4 + q) * NWSTR + n0 + nt * 8 + g]);
                mma_tf32(acc[nt], a0, a1, a2, a3, b0, b1);
            }
        }
    }
    {
        int r0 = m0 + g;
#pragma unroll
        for (int nt = 0; nt < 4; nt++) {
            int col = n0 + nt * 8 + q * 2;
            float b0 = S->bn1s[col], b1 = S->bn1s[col + 1];
            float2 top, bot;
            top.x = to_tf32(silu(acc[nt][0] + b0));
            top.y = to_tf32(silu(acc[nt][1] + b1));
            bot.x = to_tf32(silu(acc[nt][2] + b0));
            bot.y = to_tf32(silu(acc[nt][3] + b1));
            *(float2*)&S->u[r0 * USTR + col] = top;
            *(float2*)&S->u[(r0 + 8) * USTR + col] = bot;
        }
    }
    __syncthreads();

    for (int i = tid; i < HH * HH; i += 256) {
        int kk = i >> 7, n = i & 127;
        S->wb[kk * NWSTR + n] = to_tf32(Wn2[kk * HH + n]);
    }
    __syncthreads();

#pragma unroll
    for (int nt = 0; nt < 4; nt++)
#pragma unroll
        for (int c = 0; c < 4; c++) acc[nt][c] = 0.f;

#pragma unroll
    for (int kt = 0; kt < 16; kt++) {
        int k0 = kt * 8;
        uint32_t a0 = __float_as_uint(S->u[(m0 + g)     * USTR + k0 + q]);
        uint32_t a1 = __float_as_uint(S->u[(m0 + g + 8) * USTR + k0 + q]);
        uint32_t a2 = __float_as_uint(S->u[(m0 + g)     * USTR + k0 + 4 + q]);
        uint32_t a3 = __float_as_uint(S->u[(m0 + g + 8) * USTR + k0 + 4 + q]);
#pragma unroll
        for (int nt = 0; nt < 4; nt++) {
            uint32_t b0 = __float_as_uint(S->wb[(k0 + q)     * NWSTR + n0 + nt * 8 + g]);
            uint32_t b1 = __float_as_uint(S->wb[(k0 + 4 + q) * NWSTR + n0 + nt * 8 + g]);
            mma_tf32(acc[nt], a0, a1, a2, a3, b0, b1);
        }
    }

    {
        int r0 = m0 + g;
#pragma unroll
        for (int nt = 0; nt < 4; nt++) {
            int col = n0 + nt * 8 + q * 2;
            float b0 = S->bn2s[col], b1 = S->bn2s[col + 1];
            float2 h_t = *(const float2*)&h[(base + r0) * HH + col];
            float2 h_b = *(const float2*)&h[(base + r0 + 8) * HH + col];
            float2 top, bot;
            top.x = acc[nt][0] + b0 + h_t.x;
            top.y = acc[nt][1] + b1 + h_t.y;
            bot.x = acc[nt][2] + b0 + h_b.x;
            bot.y = acc[nt][3] + b1 + h_b.y;
            *(float2*)&hout[(base + r0) * HH + col] = top;
            *(float2*)&hout[(base + r0 + 8) * HH + col] = bot;
        }
    }
}

// ============================================================
extern "C" void kernel_launch(void* const* d_in, const int* in_sizes, int n_in,
                              void* d_out, int out_size)
{
    (void)in_sizes; (void)n_in; (void)out_size;
    const float* h   = (const float*)d_in[0];
    const float* x   = (const float*)d_in[1];
    const float* h0  = (const float*)d_in[3];
    const float* We1 = (const float*)d_in[4];
    const float* be1 = (const float*)d_in[5];
    const float* We2 = (const float*)d_in[6];
    const float* be2 = (const float*)d_in[7];
    const float* Wn1 = (const float*)d_in[8];
    const float* bn1 = (const float*)d_in[9];
    const float* Wn2 = (const float*)d_in[10];
    const float* bn2 = (const float*)d_in[11];
    const float* Wc1 = (const float*)d_in[12];
    const float* bc1 = (const float*)d_in[13];
    const float* Wc2 = (const float*)d_in[14];

    float* out  = (float*)d_out;
    float* hout = out;
    float* xout = out + BB * NNODE * HH;

    cudaFuncSetAttribute(prep_kernel, cudaFuncAttributeMaxDynamicSharedMemorySize,
                         (int)sizeof(PrepSmem));
    cudaFuncSetAttribute(edge_kernel, cudaFuncAttributeMaxDynamicSharedMemorySize,
                         (int)sizeof(EdgeSmem));
    cudaFuncSetAttribute(node_kernel, cudaFuncAttributeMaxDynamicSharedMemorySize,
                         (int)sizeof(NodeSmem));

    dim3 pgrid(BB * NNODE / 64, 2);
    prep_kernel<<<pgrid, 256, sizeof(PrepSmem)>>>(h, We1, be1);

    dim3 egrid(NNODE / TJ, BB);
    edge_kernel<<<egrid, NTHREADS, sizeof(EdgeSmem)>>>(
        x, We1, We2, be2, Wc1, bc1, Wc2, xout);

    node_kernel<<<BB * NNODE / 32, 256, sizeof(NodeSmem)>>>(
        h, h0, Wn1, bn1, Wn2, bn2, hout);
}

// round 15
// speedup vs baseline: 4.5909x; 1.0476x over previous
#include <cuda_runtime.h>
#include <cuda_fp16.h>
#include <cstdint>

#define BB 64
#define NNODE 64
#define HH 128
#define TJ 32
#define TE 128
#define NTHREADS 512
#define AH 136         // half stride per As row
#define AH2 68         // half2 stride per As row

// ---- device scratch ----
__device__ float g_mi[BB * NNODE * HH];

__device__ __forceinline__ float silu(float z) {
    float t;
    asm("tanh.approx.f32 %0, %1;" : "=f"(t) : "f"(z * 0.5f));
    return 0.5f * z * (1.f + t);
}
__device__ __forceinline__ float to_tf32(float x) {
    uint32_t r;
    asm("cvt.rna.tf32.f32 %0, %1;" : "=r"(r) : "f"(x));
    return __uint_as_float(r);
}
__device__ __forceinline__ uint32_t pack_h2(float a, float b) {
    __half2 p = __floats2half2_rn(a, b);
    return *(uint32_t*)&p;
}
// split (x,y) into hi/lo half2 pairs (3-term split-fp16 GEMM inputs)
__device__ __forceinline__ void split_h2(float x, float y, uint32_t& hi, uint32_t& lo) {
    __half hx = __float2half_rn(x), hy = __float2half_rn(y);
    __half lx = __float2half_rn(x - __half2float(hx));
    __half ly = __float2half_rn(y - __half2float(hy));
    __half2 h2 = __halves2half2(hx, hy), l2 = __halves2half2(lx, ly);
    hi = *(uint32_t*)&h2; lo = *(uint32_t*)&l2;
}

__device__ __forceinline__ void mma_tf32(float* c,
    uint32_t a0, uint32_t a1, uint32_t a2, uint32_t a3,
    uint32_t b0, uint32_t b1)
{
    asm volatile(
        "mma.sync.aligned.m16n8k8.row.col.f32.tf32.tf32.f32 "
        "{%0,%1,%2,%3}, {%4,%5,%6,%7}, {%8,%9}, {%0,%1,%2,%3};"
        : "+f"(c[0]), "+f"(c[1]), "+f"(c[2]), "+f"(c[3])
        : "r"(a0), "r"(a1), "r"(a2), "r"(a3), "r"(b0), "r"(b1));
}
__device__ __forceinline__ void mma_f16(float* c,
    uint32_t a0, uint32_t a1, uint32_t a2, uint32_t a3,
    uint32_t b0, uint32_t b1)
{
    asm volatile(
        "mma.sync.aligned.m16n8k16.row.col.f32.f16.f16.f32 "
        "{%0,%1,%2,%3}, {%4,%5,%6,%7}, {%8,%9}, {%0,%1,%2,%3};"
        : "+f"(c[0]), "+f"(c[1]), "+f"(c[2]), "+f"(c[3])
        : "r"(a0), "r"(a1), "r"(a2), "r"(a3), "r"(b0), "r"(b1));
}

// ============================================================
// Kernel: fused prep + edge. Block = (jt, b). 512 threads.
// ============================================================
#define ELIST 2176

struct EdgeSmem {
    union {
        struct {                       // phase 0: layer-1 prep
            float hs[64 * 132];        // h rows fp32
            float Wtmp[128 * 132];     // We1 half [k][n] fp32
        } p0;
        struct {                       // phase 1: edge GEMMs
            __half As[TE * AH];        // activations / mij
            __half W1[HH * AH];        // We2^T [n][k]
            __half W2[HH * AH];        // Wc1^T [n][k]
        } p1;
    } ov;
    float A_s [TJ * HH];               // silu-layer-1 j rows (+be1)
    float Bm_s[NNODE * HH];            // layer-1 k rows
    float mi[TJ * HH];
    float phi[TE];
    unsigned short ekey[ELIST];
    float xk[NNODE * 3];
    float be2s[HH], bc1s[HH], wc2s[HH], wds[HH], be1s[HH];
    int jstart[33];
    union {
        struct { int wcnt[64]; int wexc[64]; } c;
        float d2t[TE];
    } u;
    float xup[TJ][3];
    int cnt;
};

__global__ __launch_bounds__(NTHREADS, 1) void edge_kernel(
    const float* __restrict__ h,
    const float* __restrict__ x,
    const float* __restrict__ We1,
    const float* __restrict__ be1,
    const float* __restrict__ We2,
    const float* __restrict__ be2,
    const float* __restrict__ Wc1,
    const float* __restrict__ bc1,
    const float* __restrict__ Wc2,
    float* __restrict__ xout)
{
    extern __shared__ char smem_raw[];
    EdgeSmem* S = (EdgeSmem*)smem_raw;
    int tid = threadIdx.x;
    int wid = tid >> 5, lane = tid & 31;
    int jt = blockIdx.x;
    int b  = blockIdx.y;
    const int g = lane >> 2, q = lane & 3;

    // ---- phase 0 loads: h rows + We1 bottom half [k][n] ----
    for (int i = tid; i < 64 * HH; i += NTHREADS)
        S->ov.p0.hs[(i >> 7) * 132 + (i & 127)] = h[(size_t)(b * NNODE) * HH + i];
    for (int i = tid; i < 128 * HH; i += NTHREADS)
        S->ov.p0.Wtmp[(i >> 7) * 132 + (i & 127)] = We1[(size_t)(HH + (i >> 7)) * HH + (i & 127)];
    for (int i = tid; i < TJ * HH; i += NTHREADS) S->mi[i] = 0.f;
    if (tid < NNODE * 3) S->xk[tid] = x[b * NNODE * 3 + tid];
    if (tid < HH) {
        S->be2s[tid] = be2[tid];
        S->bc1s[tid] = bc1[tid];
        S->wc2s[tid] = Wc2[tid];
        S->wds [tid] = We1[2 * HH * HH + tid];
        S->be1s[tid] = be1[tid];
    }
    if (tid < TJ * 3) S->xup[tid / 3][tid % 3] = 0.f;
    __syncthreads();

    // ---- Bm = h @ We1_bot (split-fp16 3-term). 16 warps: 4m x 4n ----
    {
        int mB = (wid >> 2) * 16, nB = (wid & 3) * 32;
        float acc[4][4];
#pragma unroll
        for (int nt = 0; nt < 4; nt++)
#pragma unroll
            for (int c = 0; c < 4; c++) acc[nt][c] = 0.f;
#pragma unroll
        for (int kt = 0; kt < 8; kt++) {
            int k0 = kt * 16;
            float2 v0 = *(const float2*)&S->ov.p0.hs[(mB + g)     * 132 + k0 + 2 * q];
            float2 v1 = *(const float2*)&S->ov.p0.hs[(mB + g + 8) * 132 + k0 + 2 * q];
            float2 v2 = *(const float2*)&S->ov.p0.hs[(mB + g)     * 132 + k0 + 8 + 2 * q];
            float2 v3 = *(const float2*)&S->ov.p0.hs[(mB + g + 8) * 132 + k0 + 8 + 2 * q];
            uint32_t ah[4], al[4];
            split_h2(v0.x, v0.y, ah[0], al[0]);
            split_h2(v1.x, v1.y, ah[1], al[1]);
            split_h2(v2.x, v2.y, ah[2], al[2]);
            split_h2(v3.x, v3.y, ah[3], al[3]);
#pragma unroll
            for (int nt = 0; nt < 4; nt++) {
                int nrow = nB + nt * 8 + g;
                float w0a = S->ov.p0.Wtmp[(k0 + 2 * q)     * 132 + nrow];
                float w0b = S->ov.p0.Wtmp[(k0 + 2 * q + 1) * 132 + nrow];
                float w1a = S->ov.p0.Wtmp[(k0 + 8 + 2 * q)     * 132 + nrow];
                float w1b = S->ov.p0.Wtmp[(k0 + 8 + 2 * q + 1) * 132 + nrow];
                uint32_t bh0, bl0, bh1, bl1;
                split_h2(w0a, w0b, bh0, bl0);
                split_h2(w1a, w1b, bh1, bl1);
                mma_f16(acc[nt], ah[0], ah[1], ah[2], ah[3], bh0, bh1);
                mma_f16(acc[nt], ah[0], ah[1], ah[2], ah[3], bl0, bl1);
                mma_f16(acc[nt], al[0], al[1], al[2], al[3], bh0, bh1);
            }
        }
#pragma unroll
        for (int nt = 0; nt < 4; nt++) {
            int col = nB + nt * 8 + q * 2;
            *(float2*)&S->Bm_s[(mB + g)     * HH + col] = make_float2(acc[nt][0], acc[nt][1]);
            *(float2*)&S->Bm_s[(mB + g + 8) * HH + col] = make_float2(acc[nt][2], acc[nt][3]);
        }
    }
    __syncthreads();

    // ---- reload Wtmp = We1 top half ----
    for (int i = tid; i < 128 * HH; i += NTHREADS)
        S->ov.p0.Wtmp[(i >> 7) * 132 + (i & 127)] = We1[(size_t)(i >> 7) * HH + (i & 127)];
    __syncthreads();

    // ---- A = h_j @ We1_top + be1. 16 warps: 2m x 8n (16x16 tiles) ----
    {
        int mA = (wid >> 3) * 16, nA = (wid & 7) * 16;
        float acc[2][4];
#pragma unroll
        for (int nt = 0; nt < 2; nt++)
#pragma unroll
            for (int c = 0; c < 4; c++) acc[nt][c] = 0.f;
#pragma unroll
        for (int kt = 0; kt < 8; kt++) {
            int k0 = kt * 16;
            int r0 = jt * TJ + mA + g;
            float2 v0 = *(const float2*)&S->ov.p0.hs[r0       * 132 + k0 + 2 * q];
            float2 v1 = *(const float2*)&S->ov.p0.hs[(r0 + 8) * 132 + k0 + 2 * q];
            float2 v2 = *(const float2*)&S->ov.p0.hs[r0       * 132 + k0 + 8 + 2 * q];
            float2 v3 = *(const float2*)&S->ov.p0.hs[(r0 + 8) * 132 + k0 + 8 + 2 * q];
            uint32_t ah[4], al[4];
            split_h2(v0.x, v0.y, ah[0], al[0]);
            split_h2(v1.x, v1.y, ah[1], al[1]);
            split_h2(v2.x, v2.y, ah[2], al[2]);
            split_h2(v3.x, v3.y, ah[3], al[3]);
#pragma unroll
            for (int nt = 0; nt < 2; nt++) {
                int nrow = nA + nt * 8 + g;
                float w0a = S->ov.p0.Wtmp[(k0 + 2 * q)     * 132 + nrow];
                float w0b = S->ov.p0.Wtmp[(k0 + 2 * q + 1) * 132 + nrow];
                float w1a = S->ov.p0.Wtmp[(k0 + 8 + 2 * q)     * 132 + nrow];
                float w1b = S->ov.p0.Wtmp[(k0 + 8 + 2 * q + 1) * 132 + nrow];
                uint32_t bh0, bl0, bh1, bl1;
                split_h2(w0a, w0b, bh0, bl0);
                split_h2(w1a, w1b, bh1, bl1);
                mma_f16(acc[nt], ah[0], ah[1], ah[2], ah[3], bh0, bh1);
                mma_f16(acc[nt], ah[0], ah[1], ah[2], ah[3], bl0, bl1);
                mma_f16(acc[nt], al[0], al[1], al[2], al[3], bh0, bh1);
            }
        }
#pragma unroll
        for (int nt = 0; nt < 2; nt++) {
            int col = nA + nt * 8 + q * 2;
            float b0 = S->be1s[col], b1 = S->be1s[col + 1];
            *(float2*)&S->A_s[(mA + g)     * HH + col] =
                make_float2(acc[nt][0] + b0, acc[nt][1] + b1);
            *(float2*)&S->A_s[(mA + g + 8) * HH + col] =
                make_float2(acc[nt][2] + b0, acc[nt][3] + b1);
        }
    }
    __syncthreads();

    // ---- phase 1: load edge weights (overwrites overlay) ----
    for (int i = tid; i < HH * HH; i += NTHREADS) {
        int n = i >> 7, k = i & 127;
        S->ov.p1.W1[n * AH + k] = __float2half_rn(__ldg(&We2[k * HH + n]));
        S->ov.p1.W2[n * AH + k] = __float2half_rn(__ldg(&Wc1[k * HH + n]));
    }
    __syncthreads();

    // ---- compaction ----
#pragma unroll
    for (int p = 0; p < 4; p++) {
        int pid = p * 512 + tid;
        int jl = pid >> 6, k = pid & 63;
        int j = jt * TJ + jl;
        float dx = S->xk[j * 3 + 0] - S->xk[k * 3 + 0];
        float dy = S->xk[j * 3 + 1] - S->xk[k * 3 + 1];
        float dz = S->xk[j * 3 + 2] - S->xk[k * 3 + 2];
        float d2 = dx * dx + dy * dy + dz * dz;
        bool act = (k != j) && (d2 < 25.f);
        unsigned ball = __ballot_sync(0xffffffffu, act);
        if (lane == 0) S->u.c.wcnt[p * 16 + wid] = __popc(ball);
    }
    __syncthreads();
    if (tid == 0) {
        int run = 0;
        for (int i = 0; i < 64; i++) { S->u.c.wexc[i] = run; run += S->u.c.wcnt[i]; }
        S->cnt = run;
    }
    __syncthreads();
#pragma unroll
    for (int p = 0; p < 4; p++) {
        int pid = p * 512 + tid;
        int jl = pid >> 6, k = pid & 63;
        int j = jt * TJ + jl;
        float dx = S->xk[j * 3 + 0] - S->xk[k * 3 + 0];
        float dy = S->xk[j * 3 + 1] - S->xk[k * 3 + 1];
        float dz = S->xk[j * 3 + 2] - S->xk[k * 3 + 2];
        float d2 = dx * dx + dy * dy + dz * dz;
        bool act = (k != j) && (d2 < 25.f);
        unsigned ball = __ballot_sync(0xffffffffu, act);
        if (act) {
            int pos = S->u.c.wexc[p * 16 + wid] + __popc(ball & ((1u << lane) - 1u));
            S->ekey[pos] = (unsigned short)((jl << 6) | k);
        }
    }
    __syncthreads();
    const int cnt = S->cnt;
    if (tid < TE) S->ekey[cnt + tid] = 0;
    if (tid < 33) {
        int target = tid << 6;
        int lo = 0, hi = cnt;
        while (lo < hi) {
            int mid = (lo + hi) >> 1;
            if ((int)S->ekey[mid] < target) lo = mid + 1; else hi = mid;
        }
        S->jstart[tid] = lo;
    }
    __syncthreads();

    const uint32_t* As32 = (const uint32_t*)S->ov.p1.As;
    const uint32_t* W1u  = (const uint32_t*)S->ov.p1.W1;
    const uint32_t* W2u  = (const uint32_t*)S->ov.p1.W2;
    const int m0 = (wid >> 2) * 32;
    const int n0 = (wid & 3) * 32;
    int ntiles = (cnt + TE - 1) / TE;

    for (int ti = 0; ti < ntiles; ti++) {
        int start = ti * TE;

        if (tid < TE) {
            S->phi[tid] = 0.f;
            int key = S->ekey[start + tid];
            int jl = key >> 6, k = key & 63;
            int j = jt * TJ + jl;
            float dx = S->xk[j * 3 + 0] - S->xk[k * 3 + 0];
            float dy = S->xk[j * 3 + 1] - S->xk[k * 3 + 1];
            float dz = S->xk[j * 3 + 2] - S->xk[k * 3 + 2];
            S->u.d2t[tid] = dx * dx + dy * dy + dz * dz;
        }
        __syncthreads();

        // ---- stage A = half(silu(A_j + Bm_k + d2*wd)) from smem ----
        for (int idx = tid; idx < TE * 32; idx += NTHREADS) {
            int e = idx >> 5, h4 = idx & 31;
            int key = S->ekey[start + e];
            int jl = key >> 6, k = key & 63;
            float d2 = S->u.d2t[e];
            float4 av = ((const float4*)S->A_s)[jl * 32 + h4];
            float4 bv = ((const float4*)S->Bm_s)[k * 32 + h4];
            float4 wv = ((const float4*)S->wds)[h4];
            float2 st;
            st.x = __uint_as_float(pack_h2(silu(av.x + bv.x + d2 * wv.x),
                                           silu(av.y + bv.y + d2 * wv.y)));
            st.y = __uint_as_float(pack_h2(silu(av.z + bv.z + d2 * wv.z),
                                           silu(av.w + bv.w + d2 * wv.w)));
            *(float2*)&S->ov.p1.As[e * AH + h4 * 4] = st;
        }
        __syncthreads();

        // ---- GEMM1: z = A @ We2 (fp16) ----
        float acc[2][4][4];
#pragma unroll
        for (int mt = 0; mt < 2; mt++)
#pragma unroll
            for (int nt = 0; nt < 4; nt++)
#pragma unroll
                for (int c = 0; c < 4; c++) acc[mt][nt][c] = 0.f;

#pragma unroll
        for (int kt = 0; kt < 8; kt++) {
            int k2 = kt * 8;
            uint32_t a[2][4];
#pragma unroll
            for (int mt = 0; mt < 2; mt++) {
                int rb = m0 + mt * 16;
                a[mt][0] = As32[(rb + g)     * AH2 + k2 + q];
                a[mt][1] = As32[(rb + g + 8) * AH2 + k2 + q];
                a[mt][2] = As32[(rb + g)     * AH2 + k2 + 4 + q];
                a[mt][3] = As32[(rb + g + 8) * AH2 + k2 + 4 + q];
            }
#pragma unroll
            for (int nt = 0; nt < 4; nt++) {
                int nrow = n0 + nt * 8 + g;
                uint32_t b0 = W1u[nrow * AH2 + k2 + q];
                uint32_t b1 = W1u[nrow * AH2 + k2 + 4 + q];
                mma_f16(acc[0][nt], a[0][0], a[0][1], a[0][2], a[0][3], b0, b1);
                mma_f16(acc[1][nt], a[1][0], a[1][1], a[1][2], a[1][3], b0, b1);
            }
        }
        __syncthreads();

        // ---- epilogue 1: mij -> As ----
#pragma unroll
        for (int mt = 0; mt < 2; mt++) {
            int r0 = m0 + mt * 16 + g;
            float d2a = S->u.d2t[r0];
            float d2b = S->u.d2t[r0 + 8];
            float cut0 = 1.f - 0.06f * d2a + 0.004f * d2a * sqrtf(d2a);
            float cut1 = 1.f - 0.06f * d2b + 0.004f * d2b * sqrtf(d2b);
#pragma unroll
            for (int nt = 0; nt < 4; nt++) {
                int col = n0 + nt * 8 + q * 2;
                float be0 = S->be2s[col], be1v = S->be2s[col + 1];
                ((uint32_t*)S->ov.p1.As)[r0 * AH2 + (col >> 1)] =
                    pack_h2(silu(acc[mt][nt][0] + be0)  * cut0,
                            silu(acc[mt][nt][1] + be1v) * cut0);
                ((uint32_t*)S->ov.p1.As)[(r0 + 8) * AH2 + (col >> 1)] =
                    pack_h2(silu(acc[mt][nt][2] + be0)  * cut1,
                            silu(acc[mt][nt][3] + be1v) * cut1);
            }
        }
        __syncthreads();

        // ---- mi accumulation ----
        {
            int jl = tid >> 4, cg = tid & 15;
            int lo = max(S->jstart[jl], start);
            int hi = min(S->jstart[jl + 1], start + TE);
            if (lo < hi) {
                float s[8];
#pragma unroll
                for (int c = 0; c < 8; c++) s[c] = 0.f;
                for (int e = lo; e < hi; e++) {
                    float4 raw = *(const float4*)&S->ov.p1.As[(e - start) * AH + cg * 8];
                    float2 f0 = __half22float2(*(__half2*)&raw.x);
                    float2 f1 = __half22float2(*(__half2*)&raw.y);
                    float2 f2 = __half22float2(*(__half2*)&raw.z);
                    float2 f3 = __half22float2(*(__half2*)&raw.w);
                    s[0] += f0.x; s[1] += f0.y; s[2] += f1.x; s[3] += f1.y;
                    s[4] += f2.x; s[5] += f2.y; s[6] += f3.x; s[7] += f3.y;
                }
                float* mip = &S->mi[jl * HH + cg * 8];
#pragma unroll
                for (int c = 0; c < 8; c++) mip[c] += s[c];
            }
        }

        // ---- GEMM2: zc = mij @ Wc1 (fp16) ----
#pragma unroll
        for (int mt = 0; mt < 2; mt++)
#pragma unroll
            for (int nt = 0; nt < 4; nt++)
#pragma unroll
                for (int c = 0; c < 4; c++) acc[mt][nt][c] = 0.f;

#pragma unroll
        for (int kt = 0; kt < 8; kt++) {
            int k2 = kt * 8;
            uint32_t a[2][4];
#pragma unroll
            for (int mt = 0; mt < 2; mt++) {
                int rb = m0 + mt * 16;
                a[mt][0] = As32[(rb + g)     * AH2 + k2 + q];
                a[mt][1] = As32[(rb + g + 8) * AH2 + k2 + q];
                a[mt][2] = As32[(rb + g)     * AH2 + k2 + 4 + q];
                a[mt][3] = As32[(rb + g + 8) * AH2 + k2 + 4 + q];
            }
#pragma unroll
            for (int nt = 0; nt < 4; nt++) {
                int nrow = n0 + nt * 8 + g;
                uint32_t b0 = W2u[nrow * AH2 + k2 + q];
                uint32_t b1 = W2u[nrow * AH2 + k2 + 4 + q];
                mma_f16(acc[0][nt], a[0][0], a[0][1], a[0][2], a[0][3], b0, b1);
                mma_f16(acc[1][nt], a[1][0], a[1][1], a[1][2], a[1][3], b0, b1);
            }
        }

        // ---- epilogue 2: phi ----
#pragma unroll
        for (int mt = 0; mt < 2; mt++) {
            float p0 = 0.f, p1 = 0.f;
#pragma unroll
            for (int nt = 0; nt < 4; nt++) {
                int col = n0 + nt * 8 + q * 2;
                float bc0 = S->bc1s[col], bc1v = S->bc1s[col + 1];
                float wc0 = S->wc2s[col], wc1v = S->wc2s[col + 1];
                p0 += silu(acc[mt][nt][0] + bc0)  * wc0;
                p0 += silu(acc[mt][nt][1] + bc1v) * wc1v;
                p1 += silu(acc[mt][nt][2] + bc0)  * wc0;
                p1 += silu(acc[mt][nt][3] + bc1v) * wc1v;
            }
#pragma unroll
            for (int off = 1; off < 4; off <<= 1) {
                p0 += __shfl_xor_sync(0xffffffffu, p0, off);
                p1 += __shfl_xor_sync(0xffffffffu, p1, off);
            }
            if (q == 0) {
                int r0 = m0 + mt * 16 + g;
                atomicAdd(&S->phi[r0], p0);
                atomicAdd(&S->phi[r0 + 8], p1);
            }
        }
        __syncthreads();

        if (tid < TE && start + tid < cnt) {
            int key = S->ekey[start + tid];
            int jl = key >> 6, k = key & 63;
            int j = jt * TJ + jl;
            float p = S->phi[tid];
            atomicAdd(&S->xup[jl][0], (S->xk[j * 3 + 0] - S->xk[k * 3 + 0]) * p);
            atomicAdd(&S->xup[jl][1], (S->xk[j * 3 + 1] - S->xk[k * 3 + 1]) * p);
            atomicAdd(&S->xup[jl][2], (S->xk[j * 3 + 2] - S->xk[k * 3 + 2]) * p);
        }
        __syncthreads();
    }

    for (int i = tid; i < TJ * HH; i += NTHREADS)
        g_mi[(b * NNODE + jt * TJ) * HH + i] = S->mi[i];
    if (tid < TJ * 3) {
        int jl = tid / 3, c = tid % 3;
        int j = jt * TJ + jl;
        float v = S->xk[j * 3 + c] + (1.f / 63.f) * S->xup[jl][c];
        v = fminf(fmaxf(v, -1000.f), 1000.f);
        xout[(b * NNODE + j) * 3 + c] = v;
    }
}

// ============================================================
// Kernel: node MLP via tf32 mma (identical to R14 passing).
// ============================================================
#define NSTR 388
#define USTR 132
#define NWSTR 136

struct NodeSmem {
    float nf[32 * NSTR];
    float wb[128 * NWSTR];
    float u [32 * USTR];
    float bn1s[HH], bn2s[HH];
};

__global__ __launch_bounds__(256, 1) void node_kernel(
    const float* __restrict__ h,
    const float* __restrict__ h0,
    const float* __restrict__ Wn1,
    const float* __restrict__ bn1,
    const float* __restrict__ Wn2,
    const float* __restrict__ bn2,
    float* __restrict__ hout)
{
    extern __shared__ char smem_raw[];
    NodeSmem* S = (NodeSmem*)smem_raw;
    int tid = threadIdx.x;
    int wid = tid >> 5, lane = tid & 31;
    int base = blockIdx.x * 32;

    for (int i = tid; i < 32 * 384; i += 256) {
        int n = i / 384, k = i % 384;
        float v;
        if (k < 128)      v = h   [(base + n) * HH + k];
        else if (k < 256) v = g_mi[(base + n) * HH + k - 128];
        else              v = h0  [(base + n) * HH + k - 256];
        S->nf[n * NSTR + k] = to_tf32(v);
    }
    if (tid < HH) {
        S->bn1s[tid] = bn1[tid];
        S->bn2s[tid] = bn2[tid];
    }

    const int g = lane >> 2, q = lane & 3;
    const int m0 = (wid >> 2) * 16;
    const int n0 = (wid & 3) * 32;

    float acc[4][4];
#pragma unroll
    for (int nt = 0; nt < 4; nt++)
#pragma unroll
        for (int c = 0; c < 4; c++) acc[nt][c] = 0.f;

    for (int ks = 0; ks < 384; ks += 128) {
        __syncthreads();
        for (int i = tid; i < 128 * HH; i += 256) {
            int kk = i >> 7, n = i & 127;
            S->wb[kk * NWSTR + n] = to_tf32(Wn1[(ks + kk) * HH + n]);
        }
        __syncthreads();
#pragma unroll
        for (int kt = 0; kt < 16; kt++) {
            int k0 = kt * 8;
            uint32_t a0 = __float_as_uint(S->nf[(m0 + g)     * NSTR + ks + k0 + q]);
            uint32_t a1 = __float_as_uint(S->nf[(m0 + g + 8) * NSTR + ks + k0 + q]);
            uint32_t a2 = __float_as_uint(S->nf[(m0 + g)     * NSTR + ks + k0 + 4 + q]);
            uint32_t a3 = __float_as_uint(S->nf[(m0 + g + 8) * NSTR + ks + k0 + 4 + q]);
#pragma unroll
            for (int nt = 0; nt < 4; nt++) {
                uint32_t b0 = __float_as_uint(S->wb[(k0 + q)     * NWSTR + n0 + nt * 8 + g]);
                uint32_t b1 = __float_as_uint(S->wb[(k0 + 4 + q) * NWSTR + n0 + nt * 8 + g]);
                mma_tf32(acc[nt], a0, a1, a2, a3, b0, b1);
            }
        }
    }
    {
        int r0 = m0 + g;
#pragma unroll
        for (int nt = 0; nt < 4; nt++) {
            int col = n0 + nt * 8 + q * 2;
            float b0 = S->bn1s[col], b1 = S->bn1s[col + 1];
            float2 top, bot;
            top.x = to_tf32(silu(acc[nt][0] + b0));
            top.y = to_tf32(silu(acc[nt][1] + b1));
            bot.x = to_tf32(silu(acc[nt][2] + b0));
            bot.y = to_tf32(silu(acc[nt][3] + b1));
            *(float2*)&S->u[r0 * USTR + col] = top;
            *(float2*)&S->u[(r0 + 8) * USTR + col] = bot;
        }
    }
    __syncthreads();

    for (int i = tid; i < HH * HH; i += 256) {
        int kk = i >> 7, n = i & 127;
        S->wb[kk * NWSTR + n] = to_tf32(Wn2[kk * HH + n]);
    }
    __syncthreads();

#pragma unroll
    for (int nt = 0; nt < 4; nt++)
#pragma unroll
        for (int c = 0; c < 4; c++) acc[nt][c] = 0.f;

#pragma unroll
    for (int kt = 0; kt < 16; kt++) {
        int k0 = kt * 8;
        uint32_t a0 = __float_as_uint(S->u[(m0 + g)     * USTR + k0 + q]);
        uint32_t a1 = __float_as_uint(S->u[(m0 + g + 8) * USTR + k0 + q]);
        uint32_t a2 = __float_as_uint(S->u[(m0 + g)     * USTR + k0 + 4 + q]);
        uint32_t a3 = __float_as_uint(S->u[(m0 + g + 8) * USTR + k0 + 4 + q]);
#pragma unroll
        for (int nt = 0; nt < 4; nt++) {
            uint32_t b0 = __float_as_uint(S->wb[(k0 + q)     * NWSTR + n0 + nt * 8 + g]);
            uint32_t b1 = __float_as_uint(S->wb[(k0 + 4 + q) * NWSTR + n0 + nt * 8 + g]);
            mma_tf32(acc[nt], a0, a1, a2, a3, b0, b1);
        }
    }

    {
        int r0 = m0 + g;
#pragma unroll
        for (int nt = 0; nt < 4; nt++) {
            int col = n0 + nt * 8 + q * 2;
            float b0 = S->bn2s[col], b1 = S->bn2s[col + 1];
            float2 h_t = *(const float2*)&h[(base + r0) * HH + col];
            float2 h_b = *(const float2*)&h[(base + r0 + 8) * HH + col];
            float2 top, bot;
            top.x = acc[nt][0] + b0 + h_t.x;
            top.y = acc[nt][1] + b1 + h_t.y;
            bot.x = acc[nt][2] + b0 + h_b.x;
            bot.y = acc[nt][3] + b1 + h_b.y;
            *(float2*)&hout[(base + r0) * HH + col] = top;
            *(float2*)&hout[(base + r0 + 8) * HH + col] = bot;
        }
    }
}

// ============================================================
extern "C" void kernel_launch(void* const* d_in, const int* in_sizes, int n_in,
                              void* d_out, int out_size)
{
    (void)in_sizes; (void)n_in; (void)out_size;
    const float* h   = (const float*)d_in[0];
    const float* x   = (const float*)d_in[1];
    const float* h0  = (const float*)d_in[3];
    const float* We1 = (const float*)d_in[4];
    const float* be1 = (const float*)d_in[5];
    const float* We2 = (const float*)d_in[6];
    const float* be2 = (const float*)d_in[7];
    const float* Wn1 = (const float*)d_in[8];
    const float* bn1 = (const float*)d_in[9];
    const float* Wn2 = (const float*)d_in[10];
    const float* bn2 = (const float*)d_in[11];
    const float* Wc1 = (const float*)d_in[12];
    const float* bc1 = (const float*)d_in[13];
    const float* Wc2 = (const float*)d_in[14];

    float* out  = (float*)d_out;
    float* hout = out;
    float* xout = out + BB * NNODE * HH;

    cudaFuncSetAttribute(edge_kernel, cudaFuncAttributeMaxDynamicSharedMemorySize,
                         (int)sizeof(EdgeSmem));
    cudaFuncSetAttribute(node_kernel, cudaFuncAttributeMaxDynamicSharedMemorySize,
                         (int)sizeof(NodeSmem));

    dim3 egrid(NNODE / TJ, BB);
    edge_kernel<<<egrid, NTHREADS, sizeof(EdgeSmem)>>>(
        h, x, We1, be1, We2, be2, Wc1, bc1, Wc2, xout);

    node_kernel<<<BB * NNODE / 32, 256, sizeof(NodeSmem)>>>(
        h, h0, Wn1, bn1, Wn2, bn2, hout);
}